// round 6
// baseline (speedup 1.0000x reference)
#include <cuda_runtime.h>
#include <cuda_fp16.h>
#include <math.h>

#define CC 32
#define TT 768
#define DD 100
#define HH 5
#define HIDG 60
#define FFND 64
#define NPREDK 10
#define LHID 200
#define NLAYER 3
#define CT (CC*TT)          // 24576
#define DP 128              // padded x-feature dim
#define HD 112              // padded head dim (7x16)
#define QKVP (15*HD)        // 1680
#define ATTP (HH*DP)        // 640 (att keeps 128-stride slots, pads zero)
#define NB (CC*HH)          // 160

// ---------------- device scratch ----------------
__device__ float g_adj[CC*CC];
__device__ float g_h1[CT*DD];
__device__ float g_hid[CT*HIDG];
__device__ float g_hid2[CT*HIDG];
__device__ float g_x[CT*DD];
__device__ float g_y[CT*DD];
__device__ float g_M2[DD*DD];
__device__ float g_cvec[DD];

__device__ __half g_xh[CT*DP];
__device__ __half g_qkvh[(size_t)CT*QKVP];
__device__ __half g_atth[(size_t)CT*ATTP];   // pad cols stay zero (.bss)
__device__ __half g_ffnh[CT*FFND];
__device__ __half g_wqkv[NLAYER*DP*QKVP];
__device__ __half g_wm[NLAYER*ATTP*DP];
__device__ __half g_f1[NLAYER*DP*FFND];
__device__ __half g_f2[NLAYER*FFND*DP];

// ---------------- small helpers ----------------
__device__ __forceinline__ unsigned sptr(const void* p){
    return (unsigned)__cvta_generic_to_shared(p);
}
__device__ __forceinline__ void cpa16(unsigned dst, const void* src, int bytes){
    asm volatile("cp.async.cg.shared.global [%0], [%1], 16, %2;\n"
                 :: "r"(dst), "l"(src), "r"(bytes));
}
__device__ __forceinline__ void cp_commit(){ asm volatile("cp.async.commit_group;\n" ::: "memory"); }
__device__ __forceinline__ void cp_wait0(){ asm volatile("cp.async.wait_group 0;\n" ::: "memory"); }

__device__ __forceinline__ void ldsm4(unsigned& r0,unsigned& r1,unsigned& r2,unsigned& r3, unsigned a){
    asm volatile("ldmatrix.sync.aligned.m8n8.x4.shared.b16 {%0,%1,%2,%3}, [%4];\n"
        : "=r"(r0),"=r"(r1),"=r"(r2),"=r"(r3) : "r"(a));
}
__device__ __forceinline__ void ldsm4t(unsigned& r0,unsigned& r1,unsigned& r2,unsigned& r3, unsigned a){
    asm volatile("ldmatrix.sync.aligned.m8n8.x4.trans.shared.b16 {%0,%1,%2,%3}, [%4];\n"
        : "=r"(r0),"=r"(r1),"=r"(r2),"=r"(r3) : "r"(a));
}
__device__ __forceinline__ void mma16816(float* c, const unsigned* a, const unsigned* b){
    asm volatile("mma.sync.aligned.m16n8k16.row.col.f32.f16.f16.f32 "
        "{%0,%1,%2,%3}, {%4,%5,%6,%7}, {%8,%9}, {%0,%1,%2,%3};\n"
        : "+f"(c[0]),"+f"(c[1]),"+f"(c[2]),"+f"(c[3])
        : "r"(a[0]),"r"(a[1]),"r"(a[2]),"r"(a[3]), "r"(b[0]),"r"(b[1]));
}

// ---------------- fused flash attention (tensor cores, HD=112) ----------------
#define FA_BQ 128
#define FA_BK 64
#define FA_DS 120
#define FA_SMEM ((FA_BQ + 4*FA_BK) * FA_DS * 2)   // 92160 bytes

__global__ void __launch_bounds__(256, 1)
k_fattn(const __half* __restrict__ qkv, __half* __restrict__ att){
    extern __shared__ __align__(16) __half sm[];
    __half* Qs = sm;                       // [128][120]
    __half* Ks = Qs + FA_BQ*FA_DS;         // [2][64][120]
    __half* Vs = Ks + 2*FA_BK*FA_DS;       // [2][64][120]

    int tid = threadIdx.x, lane = tid & 31, w = tid >> 5;
    int qt = blockIdx.x;
    int z = blockIdx.y;
    int c = z / HH, h = z % HH;
    const __half* Qg = qkv + (size_t)c*TT*QKVP + h*HD;
    const __half* Kg = Qg + 5*HD;
    const __half* Vg = Qg + 10*HD;

    // Q tile -> smem (128 x 112 halves = 1792 16B chunks, 7/thread)
    #pragma unroll
    for (int i = 0; i < 7; i++){
        int idx = tid + i*256;
        int r = idx / 14, cc2 = (idx % 14) * 8;
        cpa16(sptr(&Qs[r*FA_DS + cc2]), Qg + (size_t)(qt*FA_BQ + r)*QKVP + cc2, 16);
    }
    cp_commit();

    auto prefKV = [&](int kt, int buf){
        const __half* kb = Kg + (size_t)kt*FA_BK*QKVP;
        const __half* vb = Vg + (size_t)kt*FA_BK*QKVP;
        // K: 64x112 = 896 chunks, V: 896 chunks -> 1792 total, 7/thread
        #pragma unroll
        for (int i = 0; i < 7; i++){
            int idx = tid + i*256;
            if (idx < 896){
                int r = idx / 14, cc2 = (idx % 14) * 8;
                cpa16(sptr(&Ks[(buf*FA_BK + r)*FA_DS + cc2]), kb + (size_t)r*QKVP + cc2, 16);
            } else {
                int j = idx - 896;
                int r = j / 14, cc2 = (j % 14) * 8;
                cpa16(sptr(&Vs[(buf*FA_BK + r)*FA_DS + cc2]), vb + (size_t)r*QKVP + cc2, 16);
            }
        }
    };
    prefKV(0, 0);
    cp_commit();
    cp_wait0();
    __syncthreads();

    // Q fragments: 7 k16 groups
    unsigned qa[7][4];
    #pragma unroll
    for (int kk = 0; kk < 7; kk++){
        unsigned ad = sptr(&Qs[(w*16 + (lane & 15))*FA_DS + kk*16 + (lane >> 4)*8]);
        ldsm4(qa[kk][0], qa[kk][1], qa[kk][2], qa[kk][3], ad);
    }

    float o[14][4];
    #pragma unroll
    for (int i = 0; i < 14; i++){ o[i][0]=0.f; o[i][1]=0.f; o[i][2]=0.f; o[i][3]=0.f; }
    float rs0 = 0.f, rs1 = 0.f;

    for (int kt = 0; kt < TT/FA_BK; kt++){
        int buf = kt & 1;
        if (kt){
            cp_wait0();
            __syncthreads();
        }
        if (kt + 1 < TT/FA_BK) prefKV(kt + 1, buf ^ 1);
        cp_commit();

        // S = Q @ K^T : 64 keys = 8 n8 tiles, 7 k-groups
        float s[8][4];
        #pragma unroll
        for (int i = 0; i < 8; i++){ s[i][0]=0.f; s[i][1]=0.f; s[i][2]=0.f; s[i][3]=0.f; }
        #pragma unroll
        for (int ks = 0; ks < 7; ks++){
            unsigned kbf[8][2];
            #pragma unroll
            for (int np = 0; np < 4; np++){
                unsigned ad = sptr(&Ks[(buf*FA_BK + np*16 + (lane & 7) + ((lane >> 4) << 3))*FA_DS
                                        + ks*16 + ((lane >> 3) & 1)*8]);
                ldsm4(kbf[np*2][0], kbf[np*2][1], kbf[np*2+1][0], kbf[np*2+1][1], ad);
            }
            #pragma unroll
            for (int nt = 0; nt < 8; nt++)
                mma16816(s[nt], qa[ks], kbf[nt]);
        }

        // p = exp(0.1*s) fp16; rowsum of rounded values; pack A-frags
        unsigned pa[4][4];
        #pragma unroll
        for (int nt = 0; nt < 8; nt++){
            __half2 h01 = __floats2half2_rn(__expf(s[nt][0]*0.1f), __expf(s[nt][1]*0.1f));
            __half2 h23 = __floats2half2_rn(__expf(s[nt][2]*0.1f), __expf(s[nt][3]*0.1f));
            int g = nt >> 1, odd = (nt & 1) << 1;
            pa[g][odd]     = *(unsigned*)&h01;
            pa[g][odd + 1] = *(unsigned*)&h23;
            float2 f01 = __half22float2(h01); rs0 += f01.x + f01.y;
            float2 f23 = __half22float2(h23); rs1 += f23.x + f23.y;
        }

        // O += P @ V : 4 k16 steps, 7 n16 tiles (112 d)
        #pragma unroll
        for (int ks = 0; ks < 4; ks++){
            #pragma unroll
            for (int nt16 = 0; nt16 < 7; nt16++){
                unsigned b0[2], b1[2];
                unsigned ad = sptr(&Vs[(buf*FA_BK + ks*16 + (lane & 15))*FA_DS
                                        + nt16*16 + (lane >> 4)*8]);
                ldsm4t(b0[0], b0[1], b1[0], b1[1], ad);
                mma16816(o[nt16*2],     pa[ks], b0);
                mma16816(o[nt16*2 + 1], pa[ks], b1);
            }
        }
        __syncthreads();
    }

    rs0 += __shfl_xor_sync(0xffffffffu, rs0, 1);
    rs0 += __shfl_xor_sync(0xffffffffu, rs0, 2);
    rs1 += __shfl_xor_sync(0xffffffffu, rs1, 1);
    rs1 += __shfl_xor_sync(0xffffffffu, rs1, 2);
    float inv0 = 1.f / rs0, inv1 = 1.f / rs1;

    int row0 = qt*FA_BQ + w*16 + (lane >> 2);
    __half* o0 = att + ((size_t)c*TT + row0)*ATTP + h*DP;
    __half* o1 = o0 + 8*ATTP;
    #pragma unroll
    for (int nt = 0; nt < 14; nt++){
        int col = nt*8 + (lane & 3)*2;
        if (col <= 98){
            *(__half2*)(o0 + col) = __floats2half2_rn(o[nt][0]*inv0, o[nt][1]*inv0);
            *(__half2*)(o1 + col) = __floats2half2_rn(o[nt][2]*inv1, o[nt][3]*inv1);
        }
    }
}

// ---------------- fp16 tensor-core GEMM (templated BN) ----------------
// EPI: 0 half(acc); 3 f32 acc+res; 4 half(relu(acc+bias)); 5 f32 acc+bias+res
#define BM 128
#define BKK 32

template<int EPI, int BNT = 64>
__global__ void __launch_bounds__(256)
hgemm(const __half* __restrict__ A, const __half* __restrict__ B,
      float* __restrict__ outF, __half* __restrict__ outH,
      const float* __restrict__ bias, const float* __restrict__ res, int ldr,
      int M, int N, int K, int lda, int ldb, int ldc)
{
    constexpr int CPR = BNT/8;        // 16B chunks per B row
    constexpr int NWT = BNT/16;       // n8-tile pairs per warp... (n-tiles of 8)
    __shared__ __align__(16) __half As[2][BM][BKK+8];
    __shared__ __align__(16) __half Bs[2][BKK][BNT+8];

    int tid = threadIdx.x;
    int m0 = blockIdx.y * BM, n0 = blockIdx.x * BNT;
    int warp = tid >> 5, lane = tid & 31;
    int wm0 = (warp >> 1) * 32, wn0 = (warp & 1) * (BNT/2);

    float c[2][NWT][4];
    #pragma unroll
    for (int a=0;a<2;a++) for (int b=0;b<NWT;b++) for (int d=0;d<4;d++) c[a][b][d]=0.f;

    auto prefA = [&](int kt, int buf){
        int k0 = kt*BKK;
        #pragma unroll
        for (int i=0;i<2;i++){
            int q = tid + i*256;
            int r = q >> 2, cc = (q & 3) * 8;
            cpa16(sptr(&As[buf][r][cc]), A + (size_t)(m0+r)*lda + k0 + cc, 16);
        }
    };
    auto prefB = [&](int kt, int buf){
        int k0 = kt*BKK;
        #pragma unroll
        for (int i = 0; i < BNT/64; i++){
            int q = tid + i*256;
            int r = q / CPR, cc = (q % CPR) * 8;
            int nrem = N - (n0 + cc);
            int bytes = nrem >= 8 ? 16 : (nrem > 0 ? nrem*2 : 0);
            const __half* src = bytes ? (B + (size_t)(k0+r)*ldb + n0 + cc) : B;
            cpa16(sptr(&Bs[buf][r][cc]), src, bytes);
        }
    };

    int nk = K / BKK;
    prefA(0,0); prefB(0,0); cp_commit();

    for (int kt = 0; kt < nk; kt++){
        int buf = kt & 1;
        cp_wait0();
        __syncthreads();
        if (kt+1 < nk){ prefA(kt+1, buf^1); prefB(kt+1, buf^1); }
        cp_commit();

        #pragma unroll
        for (int ks = 0; ks < 2; ks++){
            unsigned a[2][4], b[NWT][2];
            #pragma unroll
            for (int mt = 0; mt < 2; mt++){
                unsigned ad = sptr(&As[buf][wm0 + mt*16 + (lane & 15)][ks*16 + (lane >> 4)*8]);
                ldsm4(a[mt][0], a[mt][1], a[mt][2], a[mt][3], ad);
            }
            #pragma unroll
            for (int np = 0; np < NWT/2; np++){
                unsigned ad = sptr(&Bs[buf][ks*16 + (lane & 15)][wn0 + np*16 + (lane >> 4)*8]);
                ldsm4t(b[np*2][0], b[np*2][1], b[np*2+1][0], b[np*2+1][1], ad);
            }
            #pragma unroll
            for (int mt = 0; mt < 2; mt++)
                #pragma unroll
                for (int nt = 0; nt < NWT; nt++)
                    mma16816(c[mt][nt], a[mt], b[nt]);
        }
        __syncthreads();
    }

    #pragma unroll
    for (int mt = 0; mt < 2; mt++){
        #pragma unroll
        for (int i = 0; i < 2; i++){
            int row = m0 + wm0 + mt*16 + (lane >> 2) + i*8;
            #pragma unroll
            for (int nt = 0; nt < NWT; nt++){
                int col = n0 + wn0 + nt*8 + (lane & 3)*2;
                if (col >= N) continue;
                float v0 = c[mt][nt][i*2+0];
                float v1 = c[mt][nt][i*2+1];
                size_t off = (size_t)row*ldc + col;
                if (EPI == 0){
                    *(__half2*)(outH + off) = __floats2half2_rn(v0, v1);
                } else if (EPI == 3){
                    outF[off]   = v0 + res[(size_t)row*ldr + col];
                    outF[off+1] = v1 + res[(size_t)row*ldr + col + 1];
                } else if (EPI == 4){
                    *(__half2*)(outH + off) = __floats2half2_rn(fmaxf(v0 + bias[col], 0.f),
                                                                fmaxf(v1 + bias[col+1], 0.f));
                } else if (EPI == 5){
                    outF[off]   = v0 + bias[col]   + res[(size_t)row*ldr + col];
                    outF[off+1] = v1 + bias[col+1] + res[(size_t)row*ldr + col + 1];
                }
            }
        }
    }
}

// ---------------- weight packing ----------------
__global__ void k_pack_qkv(const float* __restrict__ wq, const float* __restrict__ wk,
                           const float* __restrict__ wv){
    int idx = blockIdx.x*256 + threadIdx.x;
    if (idx >= NLAYER*DP*QKVP) return;
    int l = idx / (DP*QKVP);
    int r = idx % (DP*QKVP);
    int k = r / QKVP, n = r % QKVP;
    int slot = n / HD, d = n % HD;
    int type = slot / HH, h = slot % HH;
    float v = 0.f;
    if (k < DD && d < DD){
        const float* w = type == 0 ? wq : (type == 1 ? wk : wv);
        v = w[(((size_t)l*HH + h)*DD + k)*DD + d];
    }
    g_wqkv[idx] = __float2half(v);
}

__global__ void k_pack_wm(const float* __restrict__ wm){
    int idx = blockIdx.x*256 + threadIdx.x;
    if (idx >= NLAYER*ATTP*DP) return;
    int l = idx / (ATTP*DP);
    int r = idx % (ATTP*DP);
    int k = r / DP, n = r % DP;
    int h = k / DP, dk = k % DP;
    float v = 0.f;
    if (dk < DD && n < DD)
        v = wm[((size_t)l*(HH*DD) + h*DD + dk)*DD + n];
    g_wm[idx] = __float2half(v);
}

__global__ void k_pack_f1(const float* __restrict__ f1){
    int idx = blockIdx.x*256 + threadIdx.x;
    if (idx >= NLAYER*DP*FFND) return;
    int l = idx / (DP*FFND);
    int r = idx % (DP*FFND);
    int k = r / FFND, n = r % FFND;
    g_f1[idx] = __float2half(k < DD ? f1[((size_t)l*DD + k)*FFND + n] : 0.f);
}

__global__ void k_pack_f2(const float* __restrict__ f2){
    int idx = blockIdx.x*256 + threadIdx.x;
    if (idx >= NLAYER*FFND*DP) return;
    int l = idx / (FFND*DP);
    int r = idx % (FFND*DP);
    int k = r / DP, n = r % DP;
    g_f2[idx] = __float2half(n < DD ? f2[((size_t)l*FFND + k)*DD + n] : 0.f);
}

// ---------------- layernorm (fp32 in-place) + fp16 padded output ----------------
__global__ void k_lnh(float* __restrict__ x, const float* __restrict__ g,
                      const float* __restrict__ b, __half* __restrict__ xh){
    int warp = threadIdx.x >> 5;
    int lane = threadIdx.x & 31;
    int row = blockIdx.x*8 + warp;
    if (row >= CT) return;
    float* xr = x + (size_t)row*DD;
    float v0 = xr[lane], v1 = xr[lane+32], v2 = xr[lane+64];
    float v3 = (lane + 96 < DD) ? xr[lane+96] : 0.f;
    float s = v0 + v1 + v2 + v3;
    #pragma unroll
    for (int o = 16; o; o >>= 1) s += __shfl_xor_sync(0xffffffffu, s, o);
    float mean = s * (1.f/DD);
    float d0 = v0-mean, d1 = v1-mean, d2 = v2-mean;
    float d3 = (lane + 96 < DD) ? (v3 - mean) : 0.f;
    float vs = d0*d0 + d1*d1 + d2*d2 + d3*d3;
    #pragma unroll
    for (int o = 16; o; o >>= 1) vs += __shfl_xor_sync(0xffffffffu, vs, o);
    float inv = rsqrtf(vs * (1.f/DD) + 1e-5f);
    __half* hr = xh + (size_t)row*DP;
    float w;
    w = d0*inv*g[lane]    + b[lane];    xr[lane]    = w; hr[lane]    = __float2half(w);
    w = d1*inv*g[lane+32] + b[lane+32]; xr[lane+32] = w; hr[lane+32] = __float2half(w);
    w = d2*inv*g[lane+64] + b[lane+64]; xr[lane+64] = w; hr[lane+64] = __float2half(w);
    if (lane + 96 < DD){
        w = d3*inv*g[lane+96] + b[lane+96]; xr[lane+96] = w; hr[lane+96] = __float2half(w);
    } else {
        hr[96 + lane] = __half(0.f);
    }
}

// ---------------- GCN ----------------
__global__ void k_adj(const float* __restrict__ A){
    int i = threadIdx.x;
    if (i >= CC) return;
    float s = 0.f;
    for (int j = 0; j < CC; j++) s += A[i*CC + j] + (i == j ? 1.f : 0.f);
    float inv = 1.f / s;
    for (int j = 0; j < CC; j++)
        g_adj[i*CC + j] = (A[i*CC + j] + (i == j ? 1.f : 0.f)) * inv;
}

// out[i, n] = sum_j adj[i,j] in[j, n]; one thread computes all 32 i's for its n
__global__ void k_agg(const float* __restrict__ in, float* __restrict__ out, int TD){
    __shared__ float sadj[CC*CC];
    int tid = threadIdx.x;
    for (int q = tid; q < CC*CC; q += 256) sadj[q] = g_adj[q];
    __syncthreads();
    int n = blockIdx.x*256 + tid;
    if (n >= TD) return;
    float v[CC];
    #pragma unroll
    for (int j = 0; j < CC; j++) v[j] = in[(size_t)j*TD + n];
    #pragma unroll
    for (int i = 0; i < CC; i++){
        float acc = 0.f;
        #pragma unroll
        for (int j = 0; j < CC; j++) acc += sadj[i*CC + j] * v[j];
        out[(size_t)i*TD + n] = acc;
    }
}

// fp32 GEMM for GCN; TOH also writes half to g_xh (padded 128-stride)
template<int RELU, int HASB, int TOH>
__global__ void __launch_bounds__(256)
k_gemm(const float* __restrict__ A, const float* __restrict__ B,
       const float* __restrict__ bias, float* __restrict__ C, int M, int N, int K){
    __shared__ __align__(16) float As[16][64];
    __shared__ __align__(16) float Bs[16][64];
    int tid = threadIdx.x;
    int tx = tid & 15, ty = tid >> 4;
    int m0 = blockIdx.y * 64, n0 = blockIdx.x * 64;
    float acc[4][4] = {};
    int nk = (K + 15) >> 4;
    for (int kt = 0; kt < nk; kt++){
        int k0 = kt * 16;
        {
            int r = tid >> 2; int kc = (tid & 3) * 4;
            int grow = m0 + r;
            #pragma unroll
            for (int i = 0; i < 4; i++){
                int kk = k0 + kc + i;
                As[kc + i][r] = (grow < M && kk < K) ? A[(size_t)grow*K + kk] : 0.f;
            }
        }
        {
            int kr = tid >> 4; int nc = (tid & 15) * 4;
            int gk = k0 + kr;
            #pragma unroll
            for (int i = 0; i < 4; i++){
                int gn = n0 + nc + i;
                Bs[kr][nc + i] = (gk < K && gn < N) ? B[(size_t)gk*N + gn] : 0.f;
            }
        }
        __syncthreads();
        #pragma unroll
        for (int kc = 0; kc < 16; kc++){
            float4 a4 = *(const float4*)&As[kc][ty*4];
            float4 b4 = *(const float4*)&Bs[kc][tx*4];
            float av[4] = {a4.x, a4.y, a4.z, a4.w};
            float bv[4] = {b4.x, b4.y, b4.z, b4.w};
            #pragma unroll
            for (int j = 0; j < 4; j++)
                #pragma unroll
                for (int i = 0; i < 4; i++)
                    acc[j][i] += av[j] * bv[i];
        }
        __syncthreads();
    }
    #pragma unroll
    for (int j = 0; j < 4; j++){
        int row = m0 + ty*4 + j;
        if (row >= M) continue;
        #pragma unroll
        for (int i = 0; i < 4; i++){
            int col = n0 + tx*4 + i;
            if (col >= N) continue;
            float v = acc[j][i];
            if (HASB) v += bias[col];
            if (RELU) v = fmaxf(v, 0.f);
            C[(size_t)row*N + col] = v;
            if (TOH) g_xh[(size_t)row*DP + col] = __float2half(v);
        }
    }
}

// ---------------- prediction head ----------------
__global__ void k_stepM(const float* __restrict__ l1, const float* __restrict__ l1b,
                        const float* __restrict__ l2, const float* __restrict__ l2b){
    int idx = blockIdx.x * blockDim.x + threadIdx.x;
    if (idx < DD*DD){
        int e = idx / DD, d = idx % DD;
        float acc = 0.f;
        for (int r = 0; r < LHID; r++)
            acc += l1[e*LHID + r] * l2[r*DD + d];
        g_M2[idx] = acc;
    } else if (idx < DD*DD + DD){
        int d = idx - DD*DD;
        float acc = l2b[d];
        for (int r = 0; r < LHID; r++)
            acc += l1b[r] * l2[r*DD + d];
        g_cvec[d] = acc;
    }
}

// all 10 steps in one CTA: carry/M2/cvec in smem
#define HEAD_SMEM ((DD*DD + DD + CC*DD) * (int)sizeof(float))
__global__ void __launch_bounds__(1024)
k_head(const float* __restrict__ x, float* __restrict__ out){
    extern __shared__ float hs[];
    float* sM2 = hs;                 // [100][100]
    float* scv = sM2 + DD*DD;        // [100]
    float* scr = scv + DD;           // [32][100]
    int tid = threadIdx.x;
    for (int q = tid; q < DD*DD; q += 1024) sM2[q] = g_M2[q];
    if (tid < DD) scv[tid] = g_cvec[tid];
    for (int q = tid; q < CC*DD; q += 1024){
        int c = q / DD, d = q % DD;
        scr[q] = x[((size_t)c*TT + TT - 1)*DD + d];
    }
    __syncthreads();
    for (int k = 0; k < NPREDK; k++){
        float rv[4];
        int cnt = 0;
        for (int q = tid; q < CC*DD; q += 1024){
            int c = q / DD, d = q % DD;
            float acc = scv[d];
            const float* cr = scr + c*DD;
            #pragma unroll 4
            for (int e = 0; e < DD; e++)
                acc += cr[e] * sM2[e*DD + d];
            rv[cnt++] = acc;
        }
        __syncthreads();
        cnt = 0;
        for (int q = tid; q < CC*DD; q += 1024){
            int c = q / DD, d = q % DD;
            scr[q] = rv[cnt];
            out[((size_t)c*NPREDK + k)*DD + d] = rv[cnt];
            cnt++;
        }
        __syncthreads();
    }
}

// ---------------- host orchestration ----------------
static float* symF(const void* s){ void* p = nullptr; cudaGetSymbolAddress(&p, s); return (float*)p; }
static __half* symH(const void* s){ void* p = nullptr; cudaGetSymbolAddress(&p, s); return (__half*)p; }

extern "C" void kernel_launch(void* const* d_in, const int* in_sizes, int n_in,
                              void* d_out, int out_size){
    const float* X      = (const float*)d_in[0];
    const float* A      = (const float*)d_in[1];
    const float* gcn_w1 = (const float*)d_in[2];
    const float* gcn_b1 = (const float*)d_in[3];
    const float* gcn_w2 = (const float*)d_in[4];
    const float* gcn_b2 = (const float*)d_in[5];
    const float* enc_wq = (const float*)d_in[6];
    const float* enc_wk = (const float*)d_in[7];
    const float* enc_wv = (const float*)d_in[8];
    const float* enc_wm = (const float*)d_in[9];
    const float* enc_f1w= (const float*)d_in[10];
    const float* enc_f1b= (const float*)d_in[11];
    const float* enc_f2w= (const float*)d_in[12];
    const float* enc_f2b= (const float*)d_in[13];
    const float* ln1g   = (const float*)d_in[14];
    const float* ln1b   = (const float*)d_in[15];
    const float* ln2g   = (const float*)d_in[16];
    const float* ln2b   = (const float*)d_in[17];
    const float* lin1_w = (const float*)d_in[18];
    const float* lin1_b = (const float*)d_in[19];
    const float* lin2_w = (const float*)d_in[20];
    const float* lin2_b = (const float*)d_in[21];
    float* out = (float*)d_out;

    float*  p_h1   = symF(g_h1);
    float*  p_hid  = symF(g_hid);
    float*  p_hid2 = symF(g_hid2);
    float*  p_x    = symF(g_x);
    float*  p_y    = symF(g_y);
    __half* p_xh   = symH(g_xh);
    __half* p_qkv  = symH(g_qkvh);
    __half* p_att  = symH(g_atth);
    __half* p_ffn  = symH(g_ffnh);
    __half* p_wqkv = symH(g_wqkv);
    __half* p_wm   = symH(g_wm);
    __half* p_f1   = symH(g_f1);
    __half* p_f2   = symH(g_f2);

    cudaFuncSetAttribute(k_fattn, cudaFuncAttributeMaxDynamicSharedMemorySize, FA_SMEM);
    cudaFuncSetAttribute(k_head,  cudaFuncAttributeMaxDynamicSharedMemorySize, HEAD_SMEM);

    // GCN (fp32); final gemm also emits fp16 padded xh
    k_adj<<<1, 32>>>(A);
    k_agg<<<(TT*DD + 255)/256, 256>>>(X, p_h1, TT*DD);
    k_gemm<1,1,0><<<dim3(1, CT/64), 256>>>(p_h1, gcn_w1, gcn_b1, p_hid, CT, HIDG, DD);
    k_agg<<<(TT*HIDG + 255)/256, 256>>>(p_hid, p_hid2, TT*HIDG);
    k_gemm<0,1,1><<<dim3(2, CT/64), 256>>>(p_hid2, gcn_w2, gcn_b2, p_x, CT, DD, HIDG);

    // pack weights fp16 (all layers)
    k_pack_qkv<<<(NLAYER*DP*QKVP + 255)/256, 256>>>(enc_wq, enc_wk, enc_wv);
    k_pack_wm <<<(NLAYER*ATTP*DP + 255)/256, 256>>>(enc_wm);
    k_pack_f1 <<<(NLAYER*DP*FFND + 255)/256, 256>>>(enc_f1w);
    k_pack_f2 <<<(NLAYER*FFND*DP + 255)/256, 256>>>(enc_f2w);

    for (int l = 0; l < NLAYER; l++){
        // QKV: [CT,128] @ [128,1680] -> fp16
        hgemm<0,128><<<dim3((QKVP + 127)/128, CT/BM), 256>>>(
            p_xh, p_wqkv + (size_t)l*DP*QKVP, nullptr, p_qkv, nullptr, nullptr, 0,
            CT, QKVP, DP, DP, QKVP, QKVP);

        // fused attention
        k_fattn<<<dim3(TT/FA_BQ, NB), 256, FA_SMEM>>>(p_qkv, p_att);

        // proj: y = x + att @ wm  (fp32 out)
        hgemm<3><<<dim3(2, CT/BM), 256>>>(
            p_att, p_wm + (size_t)l*ATTP*DP, p_y, nullptr, nullptr, p_x, DD,
            CT, DD, ATTP, ATTP, DP, DD);

        k_lnh<<<CT/8, 256>>>(p_y, ln1g + l*DD, ln1b + l*DD, p_xh);

        // ffn1: relu(xh @ f1 + b1) -> fp16
        hgemm<4><<<dim3(1, CT/BM), 256>>>(
            p_xh, p_f1 + (size_t)l*DP*FFND, nullptr, p_ffn, enc_f1b + l*FFND, nullptr, 0,
            CT, FFND, DP, DP, FFND, FFND);

        // ffn2: x = y + ffn @ f2 + b2 (fp32 out)
        hgemm<5><<<dim3(2, CT/BM), 256>>>(
            p_ffn, p_f2 + (size_t)l*FFND*DP, p_x, nullptr, enc_f2b + l*DD, p_y, DD,
            CT, DD, FFND, FFND, DP, DD);

        k_lnh<<<CT/8, 256>>>(p_x, ln2g + l*DD, ln2b + l*DD, p_xh);
    }

    // head: fold affine chain, then all 10 steps in one kernel
    k_stepM<<<(DD*DD + DD + 255)/256, 256>>>(lin1_w, lin1_b, lin2_w, lin2_b);
    k_head<<<1, 1024, HEAD_SMEM>>>(p_x, out);
}

// round 7
// speedup vs baseline: 1.3951x; 1.3951x over previous
#include <cuda_runtime.h>
#include <cuda_fp16.h>
#include <math.h>

#define CC 32
#define TT 768
#define DD 100
#define HH 5
#define HIDG 60
#define FFND 64
#define NPREDK 10
#define LHID 200
#define NLAYER 3
#define CT (CC*TT)          // 24576
#define DP 128              // padded feature/head dim
#define QKVP (15*DP)        // 1920
#define ATTP (HH*DP)        // 640
#define NB (CC*HH)          // 160

// ---------------- device scratch ----------------
__device__ float g_adj[CC*CC];
__device__ float g_h1[CT*DD];
__device__ float g_hid[CT*HIDG];
__device__ float g_hid2[CT*HIDG];
__device__ float g_x[CT*DD];
__device__ float g_y[CT*DD];

__device__ __half g_xh[CT*DP];
__device__ __half g_qkvh[(size_t)CT*QKVP];
__device__ __half g_atth[(size_t)CT*ATTP];   // pad cols stay zero (.bss)
__device__ __half g_ffnh[CT*FFND];
__device__ __half g_wqkv[NLAYER*DP*QKVP];
__device__ __half g_wm[NLAYER*ATTP*DP];
__device__ __half g_f1[NLAYER*DP*FFND];
__device__ __half g_f2[NLAYER*FFND*DP];

// ---------------- small helpers ----------------
__device__ __forceinline__ unsigned sptr(const void* p){
    return (unsigned)__cvta_generic_to_shared(p);
}
__device__ __forceinline__ void cpa16(unsigned dst, const void* src, int bytes){
    asm volatile("cp.async.cg.shared.global [%0], [%1], 16, %2;\n"
                 :: "r"(dst), "l"(src), "r"(bytes));
}
__device__ __forceinline__ void cp_commit(){ asm volatile("cp.async.commit_group;\n" ::: "memory"); }
__device__ __forceinline__ void cp_wait0(){ asm volatile("cp.async.wait_group 0;\n" ::: "memory"); }

__device__ __forceinline__ void ldsm4(unsigned& r0,unsigned& r1,unsigned& r2,unsigned& r3, unsigned a){
    asm volatile("ldmatrix.sync.aligned.m8n8.x4.shared.b16 {%0,%1,%2,%3}, [%4];\n"
        : "=r"(r0),"=r"(r1),"=r"(r2),"=r"(r3) : "r"(a));
}
__device__ __forceinline__ void ldsm4t(unsigned& r0,unsigned& r1,unsigned& r2,unsigned& r3, unsigned a){
    asm volatile("ldmatrix.sync.aligned.m8n8.x4.trans.shared.b16 {%0,%1,%2,%3}, [%4];\n"
        : "=r"(r0),"=r"(r1),"=r"(r2),"=r"(r3) : "r"(a));
}
__device__ __forceinline__ void mma16816(float* c, const unsigned* a, const unsigned* b){
    asm volatile("mma.sync.aligned.m16n8k16.row.col.f32.f16.f16.f32 "
        "{%0,%1,%2,%3}, {%4,%5,%6,%7}, {%8,%9}, {%0,%1,%2,%3};\n"
        : "+f"(c[0]),"+f"(c[1]),"+f"(c[2]),"+f"(c[3])
        : "r"(a[0]),"r"(a[1]),"r"(a[2]),"r"(a[3]), "r"(b[0]),"r"(b[1]));
}

// ---------------- fused flash attention (R5-proven config) ----------------
#define FA_BQ 128
#define FA_BK 64
#define FA_DS 136
#define FA_SMEM ((FA_BQ + 4*FA_BK) * FA_DS * 2)

__global__ void __launch_bounds__(256, 1)
k_fattn(const __half* __restrict__ qkv, __half* __restrict__ att){
    extern __shared__ __align__(16) __half sm[];
    __half* Qs = sm;                       // [128][136]
    __half* Ks = Qs + FA_BQ*FA_DS;         // [2][64][136]
    __half* Vs = Ks + 2*FA_BK*FA_DS;       // [2][64][136]

    int tid = threadIdx.x, lane = tid & 31, w = tid >> 5;
    int qt = blockIdx.x;
    int z = blockIdx.y;
    int c = z / HH, h = z % HH;
    const __half* Qg = qkv + (size_t)c*TT*QKVP + h*DP;
    const __half* Kg = Qg + HH*DP;
    const __half* Vg = Qg + 2*HH*DP;

    #pragma unroll
    for (int i = 0; i < 8; i++){
        int idx = tid + i*256;
        int r = idx >> 4, cc2 = (idx & 15) * 8;
        cpa16(sptr(&Qs[r*FA_DS + cc2]), Qg + (size_t)(qt*FA_BQ + r)*QKVP + cc2, 16);
    }
    cp_commit();

    auto prefKV = [&](int kt, int buf){
        const __half* kb = Kg + (size_t)kt*FA_BK*QKVP;
        const __half* vb = Vg + (size_t)kt*FA_BK*QKVP;
        #pragma unroll
        for (int i = 0; i < 4; i++){
            int idx = tid + i*256;
            int r = idx >> 4, cc2 = (idx & 15) * 8;
            cpa16(sptr(&Ks[(buf*FA_BK + r)*FA_DS + cc2]), kb + (size_t)r*QKVP + cc2, 16);
        }
        #pragma unroll
        for (int i = 0; i < 4; i++){
            int idx = tid + i*256;
            int r = idx >> 4, cc2 = (idx & 15) * 8;
            cpa16(sptr(&Vs[(buf*FA_BK + r)*FA_DS + cc2]), vb + (size_t)r*QKVP + cc2, 16);
        }
    };
    prefKV(0, 0);
    cp_commit();
    cp_wait0();
    __syncthreads();

    unsigned qa[8][4];
    #pragma unroll
    for (int kk = 0; kk < 8; kk++){
        unsigned ad = sptr(&Qs[(w*16 + (lane & 15))*FA_DS + kk*16 + (lane >> 4)*8]);
        ldsm4(qa[kk][0], qa[kk][1], qa[kk][2], qa[kk][3], ad);
    }

    float o[16][4];
    #pragma unroll
    for (int i = 0; i < 16; i++){ o[i][0]=0.f; o[i][1]=0.f; o[i][2]=0.f; o[i][3]=0.f; }
    float rs0 = 0.f, rs1 = 0.f;

    for (int kt = 0; kt < TT/FA_BK; kt++){
        int buf = kt & 1;
        if (kt){
            cp_wait0();
            __syncthreads();
        }
        if (kt + 1 < TT/FA_BK) prefKV(kt + 1, buf ^ 1);
        cp_commit();

        float s[8][4];
        #pragma unroll
        for (int i = 0; i < 8; i++){ s[i][0]=0.f; s[i][1]=0.f; s[i][2]=0.f; s[i][3]=0.f; }
        #pragma unroll
        for (int ks = 0; ks < 8; ks++){
            unsigned kbf[8][2];
            #pragma unroll
            for (int np = 0; np < 4; np++){
                unsigned ad = sptr(&Ks[(buf*FA_BK + np*16 + (lane & 7) + ((lane >> 4) << 3))*FA_DS
                                        + ks*16 + ((lane >> 3) & 1)*8]);
                ldsm4(kbf[np*2][0], kbf[np*2][1], kbf[np*2+1][0], kbf[np*2+1][1], ad);
            }
            #pragma unroll
            for (int nt = 0; nt < 8; nt++)
                mma16816(s[nt], qa[ks], kbf[nt]);
        }

        unsigned pa[4][4];
        #pragma unroll
        for (int nt = 0; nt < 8; nt++){
            __half2 h01 = __floats2half2_rn(__expf(s[nt][0]*0.1f), __expf(s[nt][1]*0.1f));
            __half2 h23 = __floats2half2_rn(__expf(s[nt][2]*0.1f), __expf(s[nt][3]*0.1f));
            int g = nt >> 1, odd = (nt & 1) << 1;
            pa[g][odd]     = *(unsigned*)&h01;
            pa[g][odd + 1] = *(unsigned*)&h23;
            float2 f01 = __half22float2(h01); rs0 += f01.x + f01.y;
            float2 f23 = __half22float2(h23); rs1 += f23.x + f23.y;
        }

        #pragma unroll
        for (int ks = 0; ks < 4; ks++){
            #pragma unroll
            for (int nt16 = 0; nt16 < 8; nt16++){
                unsigned b0[2], b1[2];
                unsigned ad = sptr(&Vs[(buf*FA_BK + ks*16 + (lane & 15))*FA_DS
                                        + nt16*16 + (lane >> 4)*8]);
                ldsm4t(b0[0], b0[1], b1[0], b1[1], ad);
                mma16816(o[nt16*2],     pa[ks], b0);
                mma16816(o[nt16*2 + 1], pa[ks], b1);
            }
        }
        __syncthreads();
    }

    rs0 += __shfl_xor_sync(0xffffffffu, rs0, 1);
    rs0 += __shfl_xor_sync(0xffffffffu, rs0, 2);
    rs1 += __shfl_xor_sync(0xffffffffu, rs1, 1);
    rs1 += __shfl_xor_sync(0xffffffffu, rs1, 2);
    float inv0 = 1.f / rs0, inv1 = 1.f / rs1;

    int row0 = qt*FA_BQ + w*16 + (lane >> 2);
    __half* o0 = att + ((size_t)c*TT + row0)*ATTP + h*DP;
    __half* o1 = o0 + 8*ATTP;
    #pragma unroll
    for (int nt = 0; nt < 16; nt++){
        int col = nt*8 + (lane & 3)*2;
        if (col <= 98){
            *(__half2*)(o0 + col) = __floats2half2_rn(o[nt][0]*inv0, o[nt][1]*inv0);
            *(__half2*)(o1 + col) = __floats2half2_rn(o[nt][2]*inv1, o[nt][3]*inv1);
        }
    }
}

// ---------------- fp16 tensor-core GEMM (R5-proven BN=64) ----------------
// EPI: 0 half(acc); 3 f32 acc+res; 4 half(relu(acc+bias)); 5 f32 acc+bias+res
#define BM 128
#define BN 64
#define BKK 32

template<int EPI>
__global__ void __launch_bounds__(256)
hgemm(const __half* __restrict__ A, const __half* __restrict__ B,
      float* __restrict__ outF, __half* __restrict__ outH,
      const float* __restrict__ bias, const float* __restrict__ res, int ldr,
      int M, int N, int K, int lda, int ldb, int ldc)
{
    __shared__ __align__(16) __half As[2][BM][BKK+8];
    __shared__ __align__(16) __half Bs[2][BKK][BN+8];

    int tid = threadIdx.x;
    int m0 = blockIdx.y * BM, n0 = blockIdx.x * BN;
    int warp = tid >> 5, lane = tid & 31;
    int wm0 = (warp >> 1) * 32, wn0 = (warp & 1) * 32;

    float c[2][4][4];
    #pragma unroll
    for (int a=0;a<2;a++) for (int b=0;b<4;b++) for (int d=0;d<4;d++) c[a][b][d]=0.f;

    auto prefA = [&](int kt, int buf){
        int k0 = kt*BKK;
        #pragma unroll
        for (int i=0;i<2;i++){
            int q = tid + i*256;
            int r = q >> 2, cc = (q & 3) * 8;
            cpa16(sptr(&As[buf][r][cc]), A + (size_t)(m0+r)*lda + k0 + cc, 16);
        }
    };
    auto prefB = [&](int kt, int buf){
        int k0 = kt*BKK;
        int r = tid >> 3, cc = (tid & 7) * 8;
        int nrem = N - (n0 + cc);
        int bytes = nrem >= 8 ? 16 : (nrem > 0 ? nrem*2 : 0);
        const __half* src = bytes ? (B + (size_t)(k0+r)*ldb + n0 + cc) : B;
        cpa16(sptr(&Bs[buf][r][cc]), src, bytes);
    };

    int nk = K / BKK;
    prefA(0,0); prefB(0,0); cp_commit();

    for (int kt = 0; kt < nk; kt++){
        int buf = kt & 1;
        cp_wait0();
        __syncthreads();
        if (kt+1 < nk){ prefA(kt+1, buf^1); prefB(kt+1, buf^1); }
        cp_commit();

        #pragma unroll
        for (int ks = 0; ks < 2; ks++){
            unsigned a[2][4], b[4][2];
            #pragma unroll
            for (int mt = 0; mt < 2; mt++){
                unsigned ad = sptr(&As[buf][wm0 + mt*16 + (lane & 15)][ks*16 + (lane >> 4)*8]);
                ldsm4(a[mt][0], a[mt][1], a[mt][2], a[mt][3], ad);
            }
            #pragma unroll
            for (int np = 0; np < 2; np++){
                unsigned ad = sptr(&Bs[buf][ks*16 + (lane & 15)][wn0 + np*16 + (lane >> 4)*8]);
                ldsm4t(b[np*2][0], b[np*2][1], b[np*2+1][0], b[np*2+1][1], ad);
            }
            #pragma unroll
            for (int mt = 0; mt < 2; mt++)
                #pragma unroll
                for (int nt = 0; nt < 4; nt++)
                    mma16816(c[mt][nt], a[mt], b[nt]);
        }
        __syncthreads();
    }

    #pragma unroll
    for (int mt = 0; mt < 2; mt++){
        #pragma unroll
        for (int i = 0; i < 2; i++){
            int row = m0 + wm0 + mt*16 + (lane >> 2) + i*8;
            #pragma unroll
            for (int nt = 0; nt < 4; nt++){
                int col = n0 + wn0 + nt*8 + (lane & 3)*2;
                if (col >= N) continue;
                float v0 = c[mt][nt][i*2+0];
                float v1 = c[mt][nt][i*2+1];
                size_t off = (size_t)row*ldc + col;
                if (EPI == 0){
                    *(__half2*)(outH + off) = __floats2half2_rn(v0, v1);
                } else if (EPI == 3){
                    outF[off]   = v0 + res[(size_t)row*ldr + col];
                    outF[off+1] = v1 + res[(size_t)row*ldr + col + 1];
                } else if (EPI == 4){
                    *(__half2*)(outH + off) = __floats2half2_rn(fmaxf(v0 + bias[col], 0.f),
                                                                fmaxf(v1 + bias[col+1], 0.f));
                } else if (EPI == 5){
                    outF[off]   = v0 + bias[col]   + res[(size_t)row*ldr + col];
                    outF[off+1] = v1 + bias[col+1] + res[(size_t)row*ldr + col + 1];
                }
            }
        }
    }
}

// ---------------- weight packing ----------------
__global__ void k_pack_qkv(const float* __restrict__ wq, const float* __restrict__ wk,
                           const float* __restrict__ wv){
    int idx = blockIdx.x*256 + threadIdx.x;
    if (idx >= NLAYER*DP*QKVP) return;
    int l = idx / (DP*QKVP);
    int r = idx % (DP*QKVP);
    int k = r / QKVP, n = r % QKVP;
    int slot = n / DP, d = n % DP;
    int type = slot / HH, h = slot % HH;
    float v = 0.f;
    if (k < DD && d < DD){
        const float* w = type == 0 ? wq : (type == 1 ? wk : wv);
        v = w[(((size_t)l*HH + h)*DD + k)*DD + d];
    }
    g_wqkv[idx] = __float2half(v);
}

__global__ void k_pack_wm(const float* __restrict__ wm){
    int idx = blockIdx.x*256 + threadIdx.x;
    if (idx >= NLAYER*ATTP*DP) return;
    int l = idx / (ATTP*DP);
    int r = idx % (ATTP*DP);
    int k = r / DP, n = r % DP;
    int h = k / DP, dk = k % DP;
    float v = 0.f;
    if (dk < DD && n < DD)
        v = wm[((size_t)l*(HH*DD) + h*DD + dk)*DD + n];
    g_wm[idx] = __float2half(v);
}

__global__ void k_pack_f1(const float* __restrict__ f1){
    int idx = blockIdx.x*256 + threadIdx.x;
    if (idx >= NLAYER*DP*FFND) return;
    int l = idx / (DP*FFND);
    int r = idx % (DP*FFND);
    int k = r / FFND, n = r % FFND;
    g_f1[idx] = __float2half(k < DD ? f1[((size_t)l*DD + k)*FFND + n] : 0.f);
}

__global__ void k_pack_f2(const float* __restrict__ f2){
    int idx = blockIdx.x*256 + threadIdx.x;
    if (idx >= NLAYER*FFND*DP) return;
    int l = idx / (FFND*DP);
    int r = idx % (FFND*DP);
    int k = r / DP, n = r % DP;
    g_f2[idx] = __float2half(n < DD ? f2[((size_t)l*FFND + k)*DD + n] : 0.f);
}

// ---------------- layernorm (fp32 in-place) + fp16 padded output ----------------
__global__ void k_lnh(float* __restrict__ x, const float* __restrict__ g,
                      const float* __restrict__ b, __half* __restrict__ xh){
    int warp = threadIdx.x >> 5;
    int lane = threadIdx.x & 31;
    int row = blockIdx.x*8 + warp;
    if (row >= CT) return;
    float* xr = x + (size_t)row*DD;
    float v0 = xr[lane], v1 = xr[lane+32], v2 = xr[lane+64];
    float v3 = (lane + 96 < DD) ? xr[lane+96] : 0.f;
    float s = v0 + v1 + v2 + v3;
    #pragma unroll
    for (int o = 16; o; o >>= 1) s += __shfl_xor_sync(0xffffffffu, s, o);
    float mean = s * (1.f/DD);
    float d0 = v0-mean, d1 = v1-mean, d2 = v2-mean;
    float d3 = (lane + 96 < DD) ? (v3 - mean) : 0.f;
    float vs = d0*d0 + d1*d1 + d2*d2 + d3*d3;
    #pragma unroll
    for (int o = 16; o; o >>= 1) vs += __shfl_xor_sync(0xffffffffu, vs, o);
    float inv = rsqrtf(vs * (1.f/DD) + 1e-5f);
    __half* hr = xh + (size_t)row*DP;
    float w;
    w = d0*inv*g[lane]    + b[lane];    xr[lane]    = w; hr[lane]    = __float2half(w);
    w = d1*inv*g[lane+32] + b[lane+32]; xr[lane+32] = w; hr[lane+32] = __float2half(w);
    w = d2*inv*g[lane+64] + b[lane+64]; xr[lane+64] = w; hr[lane+64] = __float2half(w);
    if (lane + 96 < DD){
        w = d3*inv*g[lane+96] + b[lane+96]; xr[lane+96] = w; hr[lane+96] = __float2half(w);
    } else {
        hr[96 + lane] = __half(0.f);
    }
}

// ---------------- GCN ----------------
__global__ void k_adj(const float* __restrict__ A){
    int i = threadIdx.x;
    if (i >= CC) return;
    float s = 0.f;
    for (int j = 0; j < CC; j++) s += A[i*CC + j] + (i == j ? 1.f : 0.f);
    float inv = 1.f / s;
    for (int j = 0; j < CC; j++)
        g_adj[i*CC + j] = (A[i*CC + j] + (i == j ? 1.f : 0.f)) * inv;
}

// out[i, n] = sum_j adj[i,j] in[j, n]; one thread computes all 32 i's for its n
__global__ void k_agg(const float* __restrict__ in, float* __restrict__ out, int TD){
    __shared__ float sadj[CC*CC];
    int tid = threadIdx.x;
    for (int q = tid; q < CC*CC; q += 256) sadj[q] = g_adj[q];
    __syncthreads();
    int n = blockIdx.x*256 + tid;
    if (n >= TD) return;
    float v[CC];
    #pragma unroll
    for (int j = 0; j < CC; j++) v[j] = in[(size_t)j*TD + n];
    #pragma unroll
    for (int i = 0; i < CC; i++){
        float acc = 0.f;
        #pragma unroll
        for (int j = 0; j < CC; j++) acc += sadj[i*CC + j] * v[j];
        out[(size_t)i*TD + n] = acc;
    }
}

// fp32 GEMM for GCN; TOH also writes half to g_xh (padded 128-stride)
template<int RELU, int HASB, int TOH>
__global__ void __launch_bounds__(256)
k_gemm(const float* __restrict__ A, const float* __restrict__ B,
       const float* __restrict__ bias, float* __restrict__ C, int M, int N, int K){
    __shared__ __align__(16) float As[16][64];
    __shared__ __align__(16) float Bs[16][64];
    int tid = threadIdx.x;
    int tx = tid & 15, ty = tid >> 4;
    int m0 = blockIdx.y * 64, n0 = blockIdx.x * 64;
    float acc[4][4] = {};
    int nk = (K + 15) >> 4;
    for (int kt = 0; kt < nk; kt++){
        int k0 = kt * 16;
        {
            int r = tid >> 2; int kc = (tid & 3) * 4;
            int grow = m0 + r;
            #pragma unroll
            for (int i = 0; i < 4; i++){
                int kk = k0 + kc + i;
                As[kc + i][r] = (grow < M && kk < K) ? A[(size_t)grow*K + kk] : 0.f;
            }
        }
        {
            int kr = tid >> 4; int nc = (tid & 15) * 4;
            int gk = k0 + kr;
            #pragma unroll
            for (int i = 0; i < 4; i++){
                int gn = n0 + nc + i;
                Bs[kr][nc + i] = (gk < K && gn < N) ? B[(size_t)gk*N + gn] : 0.f;
            }
        }
        __syncthreads();
        #pragma unroll
        for (int kc = 0; kc < 16; kc++){
            float4 a4 = *(const float4*)&As[kc][ty*4];
            float4 b4 = *(const float4*)&Bs[kc][tx*4];
            float av[4] = {a4.x, a4.y, a4.z, a4.w};
            float bv[4] = {b4.x, b4.y, b4.z, b4.w};
            #pragma unroll
            for (int j = 0; j < 4; j++)
                #pragma unroll
                for (int i = 0; i < 4; i++)
                    acc[j][i] += av[j] * bv[i];
        }
        __syncthreads();
    }
    #pragma unroll
    for (int j = 0; j < 4; j++){
        int row = m0 + ty*4 + j;
        if (row >= M) continue;
        #pragma unroll
        for (int i = 0; i < 4; i++){
            int col = n0 + tx*4 + i;
            if (col >= N) continue;
            float v = acc[j][i];
            if (HASB) v += bias[col];
            if (RELU) v = fmaxf(v, 0.f);
            C[(size_t)row*N + col] = v;
            if (TOH) g_xh[(size_t)row*DP + col] = __float2half(v);
        }
    }
}

// ---------------- prediction head: fold affine, then 10 steps, one CTA ----------------
#define HEAD_SMEM ((DD*DD + DD + CC*DD) * (int)sizeof(float))
__global__ void __launch_bounds__(1024)
k_head(const float* __restrict__ x,
       const float* __restrict__ l1, const float* __restrict__ l1b,
       const float* __restrict__ l2, const float* __restrict__ l2b,
       float* __restrict__ out){
    extern __shared__ float hs[];
    float* sM2 = hs;                 // [100][100]  M2 = l1 @ l2
    float* scv = sM2 + DD*DD;        // [100]
    float* scr = scv + DD;           // [32][100]
    int tid = threadIdx.x;
    // fold: M2[e][d] = sum_r l1[e][r] l2[r][d]; cvec[d] = l2b[d] + sum_r l1b[r] l2[r][d]
    for (int q = tid; q < DD*DD; q += 1024){
        int e = q / DD, d = q % DD;
        float acc = 0.f;
        for (int r = 0; r < LHID; r++)
            acc += l1[e*LHID + r] * l2[r*DD + d];
        sM2[q] = acc;
    }
    if (tid < DD){
        float acc = l2b[tid];
        for (int r = 0; r < LHID; r++)
            acc += l1b[r] * l2[r*DD + tid];
        scv[tid] = acc;
    }
    for (int q = tid; q < CC*DD; q += 1024){
        int c = q / DD, d = q % DD;
        scr[q] = x[((size_t)c*TT + TT - 1)*DD + d];
    }
    __syncthreads();
    for (int k = 0; k < NPREDK; k++){
        float rv[4];
        int cnt = 0;
        for (int q = tid; q < CC*DD; q += 1024){
            int c = q / DD, d = q % DD;
            float acc = scv[d];
            const float* cr = scr + c*DD;
            #pragma unroll 4
            for (int e = 0; e < DD; e++)
                acc += cr[e] * sM2[e*DD + d];
            rv[cnt++] = acc;
        }
        __syncthreads();
        cnt = 0;
        for (int q = tid; q < CC*DD; q += 1024){
            int c = q / DD, d = q % DD;
            scr[q] = rv[cnt];
            out[((size_t)c*NPREDK + k)*DD + d] = rv[cnt];
            cnt++;
        }
        __syncthreads();
    }
}

// ---------------- host orchestration ----------------
static float* symF(const void* s){ void* p = nullptr; cudaGetSymbolAddress(&p, s); return (float*)p; }
static __half* symH(const void* s){ void* p = nullptr; cudaGetSymbolAddress(&p, s); return (__half*)p; }

extern "C" void kernel_launch(void* const* d_in, const int* in_sizes, int n_in,
                              void* d_out, int out_size){
    const float* X      = (const float*)d_in[0];
    const float* A      = (const float*)d_in[1];
    const float* gcn_w1 = (const float*)d_in[2];
    const float* gcn_b1 = (const float*)d_in[3];
    const float* gcn_w2 = (const float*)d_in[4];
    const float* gcn_b2 = (const float*)d_in[5];
    const float* enc_wq = (const float*)d_in[6];
    const float* enc_wk = (const float*)d_in[7];
    const float* enc_wv = (const float*)d_in[8];
    const float* enc_wm = (const float*)d_in[9];
    const float* enc_f1w= (const float*)d_in[10];
    const float* enc_f1b= (const float*)d_in[11];
    const float* enc_f2w= (const float*)d_in[12];
    const float* enc_f2b= (const float*)d_in[13];
    const float* ln1g   = (const float*)d_in[14];
    const float* ln1b   = (const float*)d_in[15];
    const float* ln2g   = (const float*)d_in[16];
    const float* ln2b   = (const float*)d_in[17];
    const float* lin1_w = (const float*)d_in[18];
    const float* lin1_b = (const float*)d_in[19];
    const float* lin2_w = (const float*)d_in[20];
    const float* lin2_b = (const float*)d_in[21];
    float* out = (float*)d_out;

    float*  p_h1   = symF(g_h1);
    float*  p_hid  = symF(g_hid);
    float*  p_hid2 = symF(g_hid2);
    float*  p_x    = symF(g_x);
    float*  p_y    = symF(g_y);
    __half* p_xh   = symH(g_xh);
    __half* p_qkv  = symH(g_qkvh);
    __half* p_att  = symH(g_atth);
    __half* p_ffn  = symH(g_ffnh);
    __half* p_wqkv = symH(g_wqkv);
    __half* p_wm   = symH(g_wm);
    __half* p_f1   = symH(g_f1);
    __half* p_f2   = symH(g_f2);

    cudaFuncSetAttribute(k_fattn, cudaFuncAttributeMaxDynamicSharedMemorySize, FA_SMEM);
    cudaFuncSetAttribute(k_head,  cudaFuncAttributeMaxDynamicSharedMemorySize, HEAD_SMEM);

    // GCN (fp32); final gemm also emits fp16 padded xh
    k_adj<<<1, 32>>>(A);
    k_agg<<<(TT*DD + 255)/256, 256>>>(X, p_h1, TT*DD);
    k_gemm<1,1,0><<<dim3(1, CT/64), 256>>>(p_h1, gcn_w1, gcn_b1, p_hid, CT, HIDG, DD);
    k_agg<<<(TT*HIDG + 255)/256, 256>>>(p_hid, p_hid2, TT*HIDG);
    k_gemm<0,1,1><<<dim3(2, CT/64), 256>>>(p_hid2, gcn_w2, gcn_b2, p_x, CT, DD, HIDG);

    // pack weights fp16 (all layers)
    k_pack_qkv<<<(NLAYER*DP*QKVP + 255)/256, 256>>>(enc_wq, enc_wk, enc_wv);
    k_pack_wm <<<(NLAYER*ATTP*DP + 255)/256, 256>>>(enc_wm);
    k_pack_f1 <<<(NLAYER*DP*FFND + 255)/256, 256>>>(enc_f1w);
    k_pack_f2 <<<(NLAYER*FFND*DP + 255)/256, 256>>>(enc_f2w);

    for (int l = 0; l < NLAYER; l++){
        // QKV: [CT,128] @ [128,1920] -> fp16
        hgemm<0><<<dim3(QKVP/BN, CT/BM), 256>>>(
            p_xh, p_wqkv + (size_t)l*DP*QKVP, nullptr, p_qkv, nullptr, nullptr, 0,
            CT, QKVP, DP, DP, QKVP, QKVP);

        // fused attention
        k_fattn<<<dim3(TT/FA_BQ, NB), 256, FA_SMEM>>>(p_qkv, p_att);

        // proj: y = x + att @ wm  (fp32 out)
        hgemm<3><<<dim3(2, CT/BM), 256>>>(
            p_att, p_wm + (size_t)l*ATTP*DP, p_y, nullptr, nullptr, p_x, DD,
            CT, DD, ATTP, ATTP, DP, DD);

        k_lnh<<<CT/8, 256>>>(p_y, ln1g + l*DD, ln1b + l*DD, p_xh);

        // ffn1: relu(xh @ f1 + b1) -> fp16
        hgemm<4><<<dim3(1, CT/BM), 256>>>(
            p_xh, p_f1 + (size_t)l*DP*FFND, nullptr, p_ffn, enc_f1b + l*FFND, nullptr, 0,
            CT, FFND, DP, DP, FFND, FFND);

        // ffn2: x = y + ffn @ f2 + b2 (fp32 out)
        hgemm<5><<<dim3(2, CT/BM), 256>>>(
            p_ffn, p_f2 + (size_t)l*FFND*DP, p_x, nullptr, enc_f2b + l*DD, p_y, DD,
            CT, DD, FFND, FFND, DP, DD);

        k_lnh<<<CT/8, 256>>>(p_x, ln2g + l*DD, ln2b + l*DD, p_xh);
    }

    // head: fold + 10 steps in one kernel
    k_head<<<1, 1024, HEAD_SMEM>>>(p_x, lin1_w, lin1_b, lin2_w, lin2_b, out);
}

// round 8
// speedup vs baseline: 1.4157x; 1.0148x over previous
#include <cuda_runtime.h>
#include <cuda_fp16.h>
#include <math.h>

#define CC 32
#define TT 768
#define DD 100
#define HH 5
#define HIDG 60
#define FFND 64
#define NPREDK 10
#define LHID 200
#define NLAYER 3
#define CT (CC*TT)          // 24576
#define DP 128              // padded feature/head dim
#define QKVP (15*DP)        // 1920
#define ATTP (HH*DP)        // 640
#define NB (CC*HH)          // 160

// ---------------- device scratch ----------------
__device__ float g_adj[CC*CC];
__device__ float g_h1[CT*DD];
__device__ float g_hid[CT*HIDG];
__device__ float g_hid2[CT*HIDG];
__device__ float g_x[CT*DD];
__device__ float g_y[CT*DD];

__device__ __half g_xh[CT*DP];
__device__ __half g_qkvh[(size_t)CT*QKVP];
__device__ __half g_atth[(size_t)CT*ATTP];   // pad cols stay zero (.bss)
__device__ __half g_ffnh[CT*FFND];
__device__ __half g_wqkv[NLAYER*DP*QKVP];
__device__ __half g_wm[NLAYER*ATTP*DP];
__device__ __half g_f1[NLAYER*DP*FFND];
__device__ __half g_f2[NLAYER*FFND*DP];

// ---------------- small helpers ----------------
__device__ __forceinline__ unsigned sptr(const void* p){
    return (unsigned)__cvta_generic_to_shared(p);
}
__device__ __forceinline__ void cpa16(unsigned dst, const void* src, int bytes){
    asm volatile("cp.async.cg.shared.global [%0], [%1], 16, %2;\n"
                 :: "r"(dst), "l"(src), "r"(bytes));
}
__device__ __forceinline__ void cp_commit(){ asm volatile("cp.async.commit_group;\n" ::: "memory"); }
__device__ __forceinline__ void cp_wait0(){ asm volatile("cp.async.wait_group 0;\n" ::: "memory"); }

__device__ __forceinline__ void ldsm4(unsigned& r0,unsigned& r1,unsigned& r2,unsigned& r3, unsigned a){
    asm volatile("ldmatrix.sync.aligned.m8n8.x4.shared.b16 {%0,%1,%2,%3}, [%4];\n"
        : "=r"(r0),"=r"(r1),"=r"(r2),"=r"(r3) : "r"(a));
}
__device__ __forceinline__ void ldsm4t(unsigned& r0,unsigned& r1,unsigned& r2,unsigned& r3, unsigned a){
    asm volatile("ldmatrix.sync.aligned.m8n8.x4.trans.shared.b16 {%0,%1,%2,%3}, [%4];\n"
        : "=r"(r0),"=r"(r1),"=r"(r2),"=r"(r3) : "r"(a));
}
__device__ __forceinline__ void mma16816(float* c, const unsigned* a, const unsigned* b){
    asm volatile("mma.sync.aligned.m16n8k16.row.col.f32.f16.f16.f32 "
        "{%0,%1,%2,%3}, {%4,%5,%6,%7}, {%8,%9}, {%0,%1,%2,%3};\n"
        : "+f"(c[0]),"+f"(c[1]),"+f"(c[2]),"+f"(c[3])
        : "r"(a[0]),"r"(a[1]),"r"(a[2]),"r"(a[3]), "r"(b[0]),"r"(b[1]));
}

// ---------------- fused flash attention ----------------
// R5-identical layout/copies; only zero-padded MMA tiles skipped:
//   S-phase k-groups 0..6 (cols 0..111; 112..127 are zero in Q and K)
//   PV-phase d-tiles 0..6 (output cols 0..111; only <100 stored)
#define FA_BQ 128
#define FA_BK 64
#define FA_DS 136
#define FA_SMEM ((FA_BQ + 4*FA_BK) * FA_DS * 2)

__global__ void __launch_bounds__(256, 1)
k_fattn(const __half* __restrict__ qkv, __half* __restrict__ att){
    extern __shared__ __align__(16) __half sm[];
    __half* Qs = sm;                       // [128][136]
    __half* Ks = Qs + FA_BQ*FA_DS;         // [2][64][136]
    __half* Vs = Ks + 2*FA_BK*FA_DS;       // [2][64][136]

    int tid = threadIdx.x, lane = tid & 31, w = tid >> 5;
    int qt = blockIdx.x;
    int z = blockIdx.y;
    int c = z / HH, h = z % HH;
    const __half* Qg = qkv + (size_t)c*TT*QKVP + h*DP;
    const __half* Kg = Qg + HH*DP;
    const __half* Vg = Qg + 2*HH*DP;

    #pragma unroll
    for (int i = 0; i < 8; i++){
        int idx = tid + i*256;
        int r = idx >> 4, cc2 = (idx & 15) * 8;
        cpa16(sptr(&Qs[r*FA_DS + cc2]), Qg + (size_t)(qt*FA_BQ + r)*QKVP + cc2, 16);
    }
    cp_commit();

    auto prefKV = [&](int kt, int buf){
        const __half* kb = Kg + (size_t)kt*FA_BK*QKVP;
        const __half* vb = Vg + (size_t)kt*FA_BK*QKVP;
        #pragma unroll
        for (int i = 0; i < 4; i++){
            int idx = tid + i*256;
            int r = idx >> 4, cc2 = (idx & 15) * 8;
            cpa16(sptr(&Ks[(buf*FA_BK + r)*FA_DS + cc2]), kb + (size_t)r*QKVP + cc2, 16);
        }
        #pragma unroll
        for (int i = 0; i < 4; i++){
            int idx = tid + i*256;
            int r = idx >> 4, cc2 = (idx & 15) * 8;
            cpa16(sptr(&Vs[(buf*FA_BK + r)*FA_DS + cc2]), vb + (size_t)r*QKVP + cc2, 16);
        }
    };
    prefKV(0, 0);
    cp_commit();
    cp_wait0();
    __syncthreads();

    // Q fragments: only k-groups 0..6 carry data (7 is all-zero pad)
    unsigned qa[7][4];
    #pragma unroll
    for (int kk = 0; kk < 7; kk++){
        unsigned ad = sptr(&Qs[(w*16 + (lane & 15))*FA_DS + kk*16 + (lane >> 4)*8]);
        ldsm4(qa[kk][0], qa[kk][1], qa[kk][2], qa[kk][3], ad);
    }

    float o[14][4];
    #pragma unroll
    for (int i = 0; i < 14; i++){ o[i][0]=0.f; o[i][1]=0.f; o[i][2]=0.f; o[i][3]=0.f; }
    float rs0 = 0.f, rs1 = 0.f;

    for (int kt = 0; kt < TT/FA_BK; kt++){
        int buf = kt & 1;
        if (kt){
            cp_wait0();
            __syncthreads();
        }
        if (kt + 1 < TT/FA_BK) prefKV(kt + 1, buf ^ 1);
        cp_commit();

        float s[8][4];
        #pragma unroll
        for (int i = 0; i < 8; i++){ s[i][0]=0.f; s[i][1]=0.f; s[i][2]=0.f; s[i][3]=0.f; }
        #pragma unroll
        for (int ks = 0; ks < 7; ks++){
            unsigned kbf[8][2];
            #pragma unroll
            for (int np = 0; np < 4; np++){
                unsigned ad = sptr(&Ks[(buf*FA_BK + np*16 + (lane & 7) + ((lane >> 4) << 3))*FA_DS
                                        + ks*16 + ((lane >> 3) & 1)*8]);
                ldsm4(kbf[np*2][0], kbf[np*2][1], kbf[np*2+1][0], kbf[np*2+1][1], ad);
            }
            #pragma unroll
            for (int nt = 0; nt < 8; nt++)
                mma16816(s[nt], qa[ks], kbf[nt]);
        }

        unsigned pa[4][4];
        #pragma unroll
        for (int nt = 0; nt < 8; nt++){
            __half2 h01 = __floats2half2_rn(__expf(s[nt][0]*0.1f), __expf(s[nt][1]*0.1f));
            __half2 h23 = __floats2half2_rn(__expf(s[nt][2]*0.1f), __expf(s[nt][3]*0.1f));
            int g = nt >> 1, odd = (nt & 1) << 1;
            pa[g][odd]     = *(unsigned*)&h01;
            pa[g][odd + 1] = *(unsigned*)&h23;
            float2 f01 = __half22float2(h01); rs0 += f01.x + f01.y;
            float2 f23 = __half22float2(h23); rs1 += f23.x + f23.y;
        }

        #pragma unroll
        for (int ks = 0; ks < 4; ks++){
            #pragma unroll
            for (int nt16 = 0; nt16 < 7; nt16++){
                unsigned b0[2], b1[2];
                unsigned ad = sptr(&Vs[(buf*FA_BK + ks*16 + (lane & 15))*FA_DS
                                        + nt16*16 + (lane >> 4)*8]);
                ldsm4t(b0[0], b0[1], b1[0], b1[1], ad);
                mma16816(o[nt16*2],     pa[ks], b0);
                mma16816(o[nt16*2 + 1], pa[ks], b1);
            }
        }
        __syncthreads();
    }

    rs0 += __shfl_xor_sync(0xffffffffu, rs0, 1);
    rs0 += __shfl_xor_sync(0xffffffffu, rs0, 2);
    rs1 += __shfl_xor_sync(0xffffffffu, rs1, 1);
    rs1 += __shfl_xor_sync(0xffffffffu, rs1, 2);
    float inv0 = 1.f / rs0, inv1 = 1.f / rs1;

    int row0 = qt*FA_BQ + w*16 + (lane >> 2);
    __half* o0 = att + ((size_t)c*TT + row0)*ATTP + h*DP;
    __half* o1 = o0 + 8*ATTP;
    #pragma unroll
    for (int nt = 0; nt < 13; nt++){
        int col = nt*8 + (lane & 3)*2;
        if (col <= 98){
            *(__half2*)(o0 + col) = __floats2half2_rn(o[nt][0]*inv0, o[nt][1]*inv0);
            *(__half2*)(o1 + col) = __floats2half2_rn(o[nt][2]*inv1, o[nt][3]*inv1);
        }
    }
}

// ---------------- fp16 tensor-core GEMM ----------------
// EPI: 0 half(acc); 3 f32 acc+res; 4 half(relu(acc+bias)); 5 f32 acc+bias+res
#define BM 128
#define BN 64
#define BKK 32

template<int EPI>
__global__ void __launch_bounds__(256)
hgemm(const __half* __restrict__ A, const __half* __restrict__ B,
      float* __restrict__ outF, __half* __restrict__ outH,
      const float* __restrict__ bias, const float* __restrict__ res, int ldr,
      int M, int N, int K, int lda, int ldb, int ldc)
{
    __shared__ __align__(16) __half As[2][BM][BKK+8];
    __shared__ __align__(16) __half Bs[2][BKK][BN+8];

    int tid = threadIdx.x;
    int m0 = blockIdx.y * BM, n0 = blockIdx.x * BN;
    int warp = tid >> 5, lane = tid & 31;
    int wm0 = (warp >> 1) * 32, wn0 = (warp & 1) * 32;

    float c[2][4][4];
    #pragma unroll
    for (int a=0;a<2;a++) for (int b=0;b<4;b++) for (int d=0;d<4;d++) c[a][b][d]=0.f;

    auto prefA = [&](int kt, int buf){
        int k0 = kt*BKK;
        #pragma unroll
        for (int i=0;i<2;i++){
            int q = tid + i*256;
            int r = q >> 2, cc = (q & 3) * 8;
            cpa16(sptr(&As[buf][r][cc]), A + (size_t)(m0+r)*lda + k0 + cc, 16);
        }
    };
    auto prefB = [&](int kt, int buf){
        int k0 = kt*BKK;
        int r = tid >> 3, cc = (tid & 7) * 8;
        int nrem = N - (n0 + cc);
        int bytes = nrem >= 8 ? 16 : (nrem > 0 ? nrem*2 : 0);
        const __half* src = bytes ? (B + (size_t)(k0+r)*ldb + n0 + cc) : B;
        cpa16(sptr(&Bs[buf][r][cc]), src, bytes);
    };

    int nk = K / BKK;
    prefA(0,0); prefB(0,0); cp_commit();

    for (int kt = 0; kt < nk; kt++){
        int buf = kt & 1;
        cp_wait0();
        __syncthreads();
        if (kt+1 < nk){ prefA(kt+1, buf^1); prefB(kt+1, buf^1); }
        cp_commit();

        #pragma unroll
        for (int ks = 0; ks < 2; ks++){
            unsigned a[2][4], b[4][2];
            #pragma unroll
            for (int mt = 0; mt < 2; mt++){
                unsigned ad = sptr(&As[buf][wm0 + mt*16 + (lane & 15)][ks*16 + (lane >> 4)*8]);
                ldsm4(a[mt][0], a[mt][1], a[mt][2], a[mt][3], ad);
            }
            #pragma unroll
            for (int np = 0; np < 2; np++){
                unsigned ad = sptr(&Bs[buf][ks*16 + (lane & 15)][wn0 + np*16 + (lane >> 4)*8]);
                ldsm4t(b[np*2][0], b[np*2][1], b[np*2+1][0], b[np*2+1][1], ad);
            }
            #pragma unroll
            for (int mt = 0; mt < 2; mt++)
                #pragma unroll
                for (int nt = 0; nt < 4; nt++)
                    mma16816(c[mt][nt], a[mt], b[nt]);
        }
        __syncthreads();
    }

    #pragma unroll
    for (int mt = 0; mt < 2; mt++){
        #pragma unroll
        for (int i = 0; i < 2; i++){
            int row = m0 + wm0 + mt*16 + (lane >> 2) + i*8;
            #pragma unroll
            for (int nt = 0; nt < 4; nt++){
                int col = n0 + wn0 + nt*8 + (lane & 3)*2;
                if (col >= N) continue;
                float v0 = c[mt][nt][i*2+0];
                float v1 = c[mt][nt][i*2+1];
                size_t off = (size_t)row*ldc + col;
                if (EPI == 0){
                    *(__half2*)(outH + off) = __floats2half2_rn(v0, v1);
                } else if (EPI == 3){
                    outF[off]   = v0 + res[(size_t)row*ldr + col];
                    outF[off+1] = v1 + res[(size_t)row*ldr + col + 1];
                } else if (EPI == 4){
                    *(__half2*)(outH + off) = __floats2half2_rn(fmaxf(v0 + bias[col], 0.f),
                                                                fmaxf(v1 + bias[col+1], 0.f));
                } else if (EPI == 5){
                    outF[off]   = v0 + bias[col]   + res[(size_t)row*ldr + col];
                    outF[off+1] = v1 + bias[col+1] + res[(size_t)row*ldr + col + 1];
                }
            }
        }
    }
}

// ---------------- weight packing ----------------
__global__ void k_pack_qkv(const float* __restrict__ wq, const float* __restrict__ wk,
                           const float* __restrict__ wv){
    int idx = blockIdx.x*256 + threadIdx.x;
    if (idx >= NLAYER*DP*QKVP) return;
    int l = idx / (DP*QKVP);
    int r = idx % (DP*QKVP);
    int k = r / QKVP, n = r % QKVP;
    int slot = n / DP, d = n % DP;
    int type = slot / HH, h = slot % HH;
    float v = 0.f;
    if (k < DD && d < DD){
        const float* w = type == 0 ? wq : (type == 1 ? wk : wv);
        v = w[(((size_t)l*HH + h)*DD + k)*DD + d];
    }
    g_wqkv[idx] = __float2half(v);
}

__global__ void k_pack_wm(const float* __restrict__ wm){
    int idx = blockIdx.x*256 + threadIdx.x;
    if (idx >= NLAYER*ATTP*DP) return;
    int l = idx / (ATTP*DP);
    int r = idx % (ATTP*DP);
    int k = r / DP, n = r % DP;
    int h = k / DP, dk = k % DP;
    float v = 0.f;
    if (dk < DD && n < DD)
        v = wm[((size_t)l*(HH*DD) + h*DD + dk)*DD + n];
    g_wm[idx] = __float2half(v);
}

__global__ void k_pack_f1(const float* __restrict__ f1){
    int idx = blockIdx.x*256 + threadIdx.x;
    if (idx >= NLAYER*DP*FFND) return;
    int l = idx / (DP*FFND);
    int r = idx % (DP*FFND);
    int k = r / FFND, n = r % FFND;
    g_f1[idx] = __float2half(k < DD ? f1[((size_t)l*DD + k)*FFND + n] : 0.f);
}

__global__ void k_pack_f2(const float* __restrict__ f2){
    int idx = blockIdx.x*256 + threadIdx.x;
    if (idx >= NLAYER*FFND*DP) return;
    int l = idx / (FFND*DP);
    int r = idx % (FFND*DP);
    int k = r / DP, n = r % DP;
    g_f2[idx] = __float2half(n < DD ? f2[((size_t)l*FFND + k)*DD + n] : 0.f);
}

// ---------------- layernorm (fp32 in-place) + fp16 padded output ----------------
__global__ void k_lnh(float* __restrict__ x, const float* __restrict__ g,
                      const float* __restrict__ b, __half* __restrict__ xh){
    int warp = threadIdx.x >> 5;
    int lane = threadIdx.x & 31;
    int row = blockIdx.x*8 + warp;
    if (row >= CT) return;
    float* xr = x + (size_t)row*DD;
    float v0 = xr[lane], v1 = xr[lane+32], v2 = xr[lane+64];
    float v3 = (lane + 96 < DD) ? xr[lane+96] : 0.f;
    float s = v0 + v1 + v2 + v3;
    #pragma unroll
    for (int o = 16; o; o >>= 1) s += __shfl_xor_sync(0xffffffffu, s, o);
    float mean = s * (1.f/DD);
    float d0 = v0-mean, d1 = v1-mean, d2 = v2-mean;
    float d3 = (lane + 96 < DD) ? (v3 - mean) : 0.f;
    float vs = d0*d0 + d1*d1 + d2*d2 + d3*d3;
    #pragma unroll
    for (int o = 16; o; o >>= 1) vs += __shfl_xor_sync(0xffffffffu, vs, o);
    float inv = rsqrtf(vs * (1.f/DD) + 1e-5f);
    __half* hr = xh + (size_t)row*DP;
    float w;
    w = d0*inv*g[lane]    + b[lane];    xr[lane]    = w; hr[lane]    = __float2half(w);
    w = d1*inv*g[lane+32] + b[lane+32]; xr[lane+32] = w; hr[lane+32] = __float2half(w);
    w = d2*inv*g[lane+64] + b[lane+64]; xr[lane+64] = w; hr[lane+64] = __float2half(w);
    if (lane + 96 < DD){
        w = d3*inv*g[lane+96] + b[lane+96]; xr[lane+96] = w; hr[lane+96] = __float2half(w);
    } else {
        hr[96 + lane] = __half(0.f);
    }
}

// ---------------- GCN ----------------
__global__ void k_adj(const float* __restrict__ A){
    int i = threadIdx.x;
    if (i >= CC) return;
    float s = 0.f;
    for (int j = 0; j < CC; j++) s += A[i*CC + j] + (i == j ? 1.f : 0.f);
    float inv = 1.f / s;
    for (int j = 0; j < CC; j++)
        g_adj[i*CC + j] = (A[i*CC + j] + (i == j ? 1.f : 0.f)) * inv;
}

__global__ void k_agg(const float* __restrict__ in, float* __restrict__ out, int TD){
    __shared__ float sadj[CC*CC];
    int tid = threadIdx.x;
    for (int q = tid; q < CC*CC; q += 256) sadj[q] = g_adj[q];
    __syncthreads();
    int n = blockIdx.x*256 + tid;
    if (n >= TD) return;
    float v[CC];
    #pragma unroll
    for (int j = 0; j < CC; j++) v[j] = in[(size_t)j*TD + n];
    #pragma unroll
    for (int i = 0; i < CC; i++){
        float acc = 0.f;
        #pragma unroll
        for (int j = 0; j < CC; j++) acc += sadj[i*CC + j] * v[j];
        out[(size_t)i*TD + n] = acc;
    }
}

// fp32 GEMM for GCN; TOH also writes half to g_xh (padded 128-stride)
template<int RELU, int HASB, int TOH>
__global__ void __launch_bounds__(256)
k_gemm(const float* __restrict__ A, const float* __restrict__ B,
       const float* __restrict__ bias, float* __restrict__ C, int M, int N, int K){
    __shared__ __align__(16) float As[16][64];
    __shared__ __align__(16) float Bs[16][64];
    int tid = threadIdx.x;
    int tx = tid & 15, ty = tid >> 4;
    int m0 = blockIdx.y * 64, n0 = blockIdx.x * 64;
    float acc[4][4] = {};
    int nk = (K + 15) >> 4;
    for (int kt = 0; kt < nk; kt++){
        int k0 = kt * 16;
        {
            int r = tid >> 2; int kc = (tid & 3) * 4;
            int grow = m0 + r;
            #pragma unroll
            for (int i = 0; i < 4; i++){
                int kk = k0 + kc + i;
                As[kc + i][r] = (grow < M && kk < K) ? A[(size_t)grow*K + kk] : 0.f;
            }
        }
        {
            int kr = tid >> 4; int nc = (tid & 15) * 4;
            int gk = k0 + kr;
            #pragma unroll
            for (int i = 0; i < 4; i++){
                int gn = n0 + nc + i;
                Bs[kr][nc + i] = (gk < K && gn < N) ? B[(size_t)gk*N + gn] : 0.f;
            }
        }
        __syncthreads();
        #pragma unroll
        for (int kc = 0; kc < 16; kc++){
            float4 a4 = *(const float4*)&As[kc][ty*4];
            float4 b4 = *(const float4*)&Bs[kc][tx*4];
            float av[4] = {a4.x, a4.y, a4.z, a4.w};
            float bv[4] = {b4.x, b4.y, b4.z, b4.w};
            #pragma unroll
            for (int j = 0; j < 4; j++)
                #pragma unroll
                for (int i = 0; i < 4; i++)
                    acc[j][i] += av[j] * bv[i];
        }
        __syncthreads();
    }
    #pragma unroll
    for (int j = 0; j < 4; j++){
        int row = m0 + ty*4 + j;
        if (row >= M) continue;
        #pragma unroll
        for (int i = 0; i < 4; i++){
            int col = n0 + tx*4 + i;
            if (col >= N) continue;
            float v = acc[j][i];
            if (HASB) v += bias[col];
            if (RELU) v = fmaxf(v, 0.f);
            C[(size_t)row*N + col] = v;
            if (TOH) g_xh[(size_t)row*DP + col] = __float2half(v);
        }
    }
}

// ---------------- prediction head: fold affine, then 10 steps, one CTA ----------------
#define HEAD_SMEM ((DD*DD + DD + CC*DD) * (int)sizeof(float))
__global__ void __launch_bounds__(1024)
k_head(const float* __restrict__ x,
       const float* __restrict__ l1, const float* __restrict__ l1b,
       const float* __restrict__ l2, const float* __restrict__ l2b,
       float* __restrict__ out){
    extern __shared__ float hs[];
    float* sM2 = hs;                 // [100][100]  M2 = l1 @ l2
    float* scv = sM2 + DD*DD;        // [100]
    float* scr = scv + DD;           // [32][100]
    int tid = threadIdx.x;
    for (int q = tid; q < DD*DD; q += 1024){
        int e = q / DD, d = q % DD;
        float acc = 0.f;
        for (int r = 0; r < LHID; r++)
            acc += l1[e*LHID + r] * l2[r*DD + d];
        sM2[q] = acc;
    }
    if (tid < DD){
        float acc = l2b[tid];
        for (int r = 0; r < LHID; r++)
            acc += l1b[r] * l2[r*DD + tid];
        scv[tid] = acc;
    }
    for (int q = tid; q < CC*DD; q += 1024){
        int c = q / DD, d = q % DD;
        scr[q] = x[((size_t)c*TT + TT - 1)*DD + d];
    }
    __syncthreads();
    for (int k = 0; k < NPREDK; k++){
        float rv[4];
        int cnt = 0;
        for (int q = tid; q < CC*DD; q += 1024){
            int c = q / DD, d = q % DD;
            float acc = scv[d];
            const float* cr = scr + c*DD;
            #pragma unroll 4
            for (int e = 0; e < DD; e++)
                acc += cr[e] * sM2[e*DD + d];
            rv[cnt++] = acc;
        }
        __syncthreads();
        cnt = 0;
        for (int q = tid; q < CC*DD; q += 1024){
            int c = q / DD, d = q % DD;
            scr[q] = rv[cnt];
            out[((size_t)c*NPREDK + k)*DD + d] = rv[cnt];
            cnt++;
        }
        __syncthreads();
    }
}

// ---------------- host orchestration ----------------
static float* symF(const void* s){ void* p = nullptr; cudaGetSymbolAddress(&p, s); return (float*)p; }
static __half* symH(const void* s){ void* p = nullptr; cudaGetSymbolAddress(&p, s); return (__half*)p; }

extern "C" void kernel_launch(void* const* d_in, const int* in_sizes, int n_in,
                              void* d_out, int out_size){
    const float* X      = (const float*)d_in[0];
    const float* A      = (const float*)d_in[1];
    const float* gcn_w1 = (const float*)d_in[2];
    const float* gcn_b1 = (const float*)d_in[3];
    const float* gcn_w2 = (const float*)d_in[4];
    const float* gcn_b2 = (const float*)d_in[5];
    const float* enc_wq = (const float*)d_in[6];
    const float* enc_wk = (const float*)d_in[7];
    const float* enc_wv = (const float*)d_in[8];
    const float* enc_wm = (const float*)d_in[9];
    const float* enc_f1w= (const float*)d_in[10];
    const float* enc_f1b= (const float*)d_in[11];
    const float* enc_f2w= (const float*)d_in[12];
    const float* enc_f2b= (const float*)d_in[13];
    const float* ln1g   = (const float*)d_in[14];
    const float* ln1b   = (const float*)d_in[15];
    const float* ln2g   = (const float*)d_in[16];
    const float* ln2b   = (const float*)d_in[17];
    const float* lin1_w = (const float*)d_in[18];
    const float* lin1_b = (const float*)d_in[19];
    const float* lin2_w = (const float*)d_in[20];
    const float* lin2_b = (const float*)d_in[21];
    float* out = (float*)d_out;

    float*  p_h1   = symF(g_h1);
    float*  p_hid  = symF(g_hid);
    float*  p_hid2 = symF(g_hid2);
    float*  p_x    = symF(g_x);
    float*  p_y    = symF(g_y);
    __half* p_xh   = symH(g_xh);
    __half* p_qkv  = symH(g_qkvh);
    __half* p_att  = symH(g_atth);
    __half* p_ffn  = symH(g_ffnh);
    __half* p_wqkv = symH(g_wqkv);
    __half* p_wm   = symH(g_wm);
    __half* p_f1   = symH(g_f1);
    __half* p_f2   = symH(g_f2);

    cudaFuncSetAttribute(k_fattn, cudaFuncAttributeMaxDynamicSharedMemorySize, FA_SMEM);
    cudaFuncSetAttribute(k_head,  cudaFuncAttributeMaxDynamicSharedMemorySize, HEAD_SMEM);

    // GCN (fp32); final gemm also emits fp16 padded xh
    k_adj<<<1, 32>>>(A);
    k_agg<<<(TT*DD + 255)/256, 256>>>(X, p_h1, TT*DD);
    k_gemm<1,1,0><<<dim3(1, CT/64), 256>>>(p_h1, gcn_w1, gcn_b1, p_hid, CT, HIDG, DD);
    k_agg<<<(TT*HIDG + 255)/256, 256>>>(p_hid, p_hid2, TT*HIDG);
    k_gemm<0,1,1><<<dim3(2, CT/64), 256>>>(p_hid2, gcn_w2, gcn_b2, p_x, CT, DD, HIDG);

    // pack weights fp16 (all layers)
    k_pack_qkv<<<(NLAYER*DP*QKVP + 255)/256, 256>>>(enc_wq, enc_wk, enc_wv);
    k_pack_wm <<<(NLAYER*ATTP*DP + 255)/256, 256>>>(enc_wm);
    k_pack_f1 <<<(NLAYER*DP*FFND + 255)/256, 256>>>(enc_f1w);
    k_pack_f2 <<<(NLAYER*FFND*DP + 255)/256, 256>>>(enc_f2w);

    for (int l = 0; l < NLAYER; l++){
        // QKV: [CT,128] @ [128,1920] -> fp16
        hgemm<0><<<dim3(QKVP/BN, CT/BM), 256>>>(
            p_xh, p_wqkv + (size_t)l*DP*QKVP, nullptr, p_qkv, nullptr, nullptr, 0,
            CT, QKVP, DP, DP, QKVP, QKVP);

        // fused attention
        k_fattn<<<dim3(TT/FA_BQ, NB), 256, FA_SMEM>>>(p_qkv, p_att);

        // proj: y = x + att @ wm  (fp32 out)
        hgemm<3><<<dim3(2, CT/BM), 256>>>(
            p_att, p_wm + (size_t)l*ATTP*DP, p_y, nullptr, nullptr, p_x, DD,
            CT, DD, ATTP, ATTP, DP, DD);

        k_lnh<<<CT/8, 256>>>(p_y, ln1g + l*DD, ln1b + l*DD, p_xh);

        // ffn1: relu(xh @ f1 + b1) -> fp16
        hgemm<4><<<dim3(1, CT/BM), 256>>>(
            p_xh, p_f1 + (size_t)l*DP*FFND, nullptr, p_ffn, enc_f1b + l*FFND, nullptr, 0,
            CT, FFND, DP, DP, FFND, FFND);

        // ffn2: x = y + ffn @ f2 + b2 (fp32 out)
        hgemm<5><<<dim3(2, CT/BM), 256>>>(
            p_ffn, p_f2 + (size_t)l*FFND*DP, p_x, nullptr, enc_f2b + l*DD, p_y, DD,
            CT, DD, FFND, FFND, DP, DD);

        k_lnh<<<CT/8, 256>>>(p_x, ln2g + l*DD, ln2b + l*DD, p_xh);
    }

    // head: fold + 10 steps in one kernel
    k_head<<<1, 1024, HEAD_SMEM>>>(p_x, lin1_w, lin1_b, lin2_w, lin2_b, out);
}

// round 9
// speedup vs baseline: 1.5023x; 1.0612x over previous
#include <cuda_runtime.h>
#include <cuda_fp16.h>
#include <math.h>

#define CC 32
#define TT 768
#define DD 100
#define HH 5
#define HIDG 60
#define FFND 64
#define NPREDK 10
#define LHID 200
#define NLAYER 3
#define CT (CC*TT)          // 24576
#define DP 128              // padded feature/head dim
#define QKVP (15*DP)        // 1920
#define ATTP (HH*DP)        // 640
#define NB (CC*HH)          // 160

// ---------------- device scratch ----------------
__device__ float g_adj[CC*CC];
__device__ float g_h1[CT*DD];
__device__ float g_hid[CT*HIDG];
__device__ float g_hid2[CT*HIDG];
__device__ float g_x[CT*DD];
__device__ float g_y[CT*DD];
__device__ float g_M2[DD*DD];
__device__ float g_cvec[DD];

__device__ __half g_xh[CT*DP];
__device__ __half g_qkvh[(size_t)CT*QKVP];
__device__ __half g_atth[(size_t)CT*ATTP];   // pad cols stay zero (.bss)
__device__ __half g_ffnh[CT*FFND];
__device__ __half g_wqkv[NLAYER*DP*QKVP];
__device__ __half g_wm[NLAYER*ATTP*DP];
__device__ __half g_f1[NLAYER*DP*FFND];
__device__ __half g_f2[NLAYER*FFND*DP];

// ---------------- small helpers ----------------
__device__ __forceinline__ unsigned sptr(const void* p){
    return (unsigned)__cvta_generic_to_shared(p);
}
__device__ __forceinline__ void cpa16(unsigned dst, const void* src, int bytes){
    asm volatile("cp.async.cg.shared.global [%0], [%1], 16, %2;\n"
                 :: "r"(dst), "l"(src), "r"(bytes));
}
__device__ __forceinline__ void cp_commit(){ asm volatile("cp.async.commit_group;\n" ::: "memory"); }
__device__ __forceinline__ void cp_wait0(){ asm volatile("cp.async.wait_group 0;\n" ::: "memory"); }

__device__ __forceinline__ void ldsm4(unsigned& r0,unsigned& r1,unsigned& r2,unsigned& r3, unsigned a){
    asm volatile("ldmatrix.sync.aligned.m8n8.x4.shared.b16 {%0,%1,%2,%3}, [%4];\n"
        : "=r"(r0),"=r"(r1),"=r"(r2),"=r"(r3) : "r"(a));
}
__device__ __forceinline__ void ldsm4t(unsigned& r0,unsigned& r1,unsigned& r2,unsigned& r3, unsigned a){
    asm volatile("ldmatrix.sync.aligned.m8n8.x4.trans.shared.b16 {%0,%1,%2,%3}, [%4];\n"
        : "=r"(r0),"=r"(r1),"=r"(r2),"=r"(r3) : "r"(a));
}
__device__ __forceinline__ void mma16816(float* c, const unsigned* a, const unsigned* b){
    asm volatile("mma.sync.aligned.m16n8k16.row.col.f32.f16.f16.f32 "
        "{%0,%1,%2,%3}, {%4,%5,%6,%7}, {%8,%9}, {%0,%1,%2,%3};\n"
        : "+f"(c[0]),"+f"(c[1]),"+f"(c[2]),"+f"(c[3])
        : "r"(a[0]),"r"(a[1]),"r"(a[2]),"r"(a[3]), "r"(b[0]),"r"(b[1]));
}

// ---------------- fused flash attention ----------------
// R5 layout/copies; zero-padded MMA tiles skipped (k-groups 0..6, d-tiles 0..6)
#define FA_BQ 128
#define FA_BK 64
#define FA_DS 136
#define FA_SMEM ((FA_BQ + 4*FA_BK) * FA_DS * 2)

__global__ void __launch_bounds__(256, 1)
k_fattn(const __half* __restrict__ qkv, __half* __restrict__ att){
    extern __shared__ __align__(16) __half sm[];
    __half* Qs = sm;                       // [128][136]
    __half* Ks = Qs + FA_BQ*FA_DS;         // [2][64][136]
    __half* Vs = Ks + 2*FA_BK*FA_DS;       // [2][64][136]

    int tid = threadIdx.x, lane = tid & 31, w = tid >> 5;
    int qt = blockIdx.x;
    int z = blockIdx.y;
    int c = z / HH, h = z % HH;
    const __half* Qg = qkv + (size_t)c*TT*QKVP + h*DP;
    const __half* Kg = Qg + HH*DP;
    const __half* Vg = Qg + 2*HH*DP;

    #pragma unroll
    for (int i = 0; i < 8; i++){
        int idx = tid + i*256;
        int r = idx >> 4, cc2 = (idx & 15) * 8;
        cpa16(sptr(&Qs[r*FA_DS + cc2]), Qg + (size_t)(qt*FA_BQ + r)*QKVP + cc2, 16);
    }
    cp_commit();

    auto prefKV = [&](int kt, int buf){
        const __half* kb = Kg + (size_t)kt*FA_BK*QKVP;
        const __half* vb = Vg + (size_t)kt*FA_BK*QKVP;
        #pragma unroll
        for (int i = 0; i < 4; i++){
            int idx = tid + i*256;
            int r = idx >> 4, cc2 = (idx & 15) * 8;
            cpa16(sptr(&Ks[(buf*FA_BK + r)*FA_DS + cc2]), kb + (size_t)r*QKVP + cc2, 16);
        }
        #pragma unroll
        for (int i = 0; i < 4; i++){
            int idx = tid + i*256;
            int r = idx >> 4, cc2 = (idx & 15) * 8;
            cpa16(sptr(&Vs[(buf*FA_BK + r)*FA_DS + cc2]), vb + (size_t)r*QKVP + cc2, 16);
        }
    };
    prefKV(0, 0);
    cp_commit();
    cp_wait0();
    __syncthreads();

    unsigned qa[7][4];
    #pragma unroll
    for (int kk = 0; kk < 7; kk++){
        unsigned ad = sptr(&Qs[(w*16 + (lane & 15))*FA_DS + kk*16 + (lane >> 4)*8]);
        ldsm4(qa[kk][0], qa[kk][1], qa[kk][2], qa[kk][3], ad);
    }

    float o[14][4];
    #pragma unroll
    for (int i = 0; i < 14; i++){ o[i][0]=0.f; o[i][1]=0.f; o[i][2]=0.f; o[i][3]=0.f; }
    float rs0 = 0.f, rs1 = 0.f;

    for (int kt = 0; kt < TT/FA_BK; kt++){
        int buf = kt & 1;
        if (kt){
            cp_wait0();
            __syncthreads();
        }
        if (kt + 1 < TT/FA_BK) prefKV(kt + 1, buf ^ 1);
        cp_commit();

        float s[8][4];
        #pragma unroll
        for (int i = 0; i < 8; i++){ s[i][0]=0.f; s[i][1]=0.f; s[i][2]=0.f; s[i][3]=0.f; }
        #pragma unroll
        for (int ks = 0; ks < 7; ks++){
            unsigned kbf[8][2];
            #pragma unroll
            for (int np = 0; np < 4; np++){
                unsigned ad = sptr(&Ks[(buf*FA_BK + np*16 + (lane & 7) + ((lane >> 4) << 3))*FA_DS
                                        + ks*16 + ((lane >> 3) & 1)*8]);
                ldsm4(kbf[np*2][0], kbf[np*2][1], kbf[np*2+1][0], kbf[np*2+1][1], ad);
            }
            #pragma unroll
            for (int nt = 0; nt < 8; nt++)
                mma16816(s[nt], qa[ks], kbf[nt]);
        }

        unsigned pa[4][4];
        #pragma unroll
        for (int nt = 0; nt < 8; nt++){
            __half2 h01 = __floats2half2_rn(__expf(s[nt][0]*0.1f), __expf(s[nt][1]*0.1f));
            __half2 h23 = __floats2half2_rn(__expf(s[nt][2]*0.1f), __expf(s[nt][3]*0.1f));
            int g = nt >> 1, odd = (nt & 1) << 1;
            pa[g][odd]     = *(unsigned*)&h01;
            pa[g][odd + 1] = *(unsigned*)&h23;
            float2 f01 = __half22float2(h01); rs0 += f01.x + f01.y;
            float2 f23 = __half22float2(h23); rs1 += f23.x + f23.y;
        }

        #pragma unroll
        for (int ks = 0; ks < 4; ks++){
            #pragma unroll
            for (int nt16 = 0; nt16 < 7; nt16++){
                unsigned b0[2], b1[2];
                unsigned ad = sptr(&Vs[(buf*FA_BK + ks*16 + (lane & 15))*FA_DS
                                        + nt16*16 + (lane >> 4)*8]);
                ldsm4t(b0[0], b0[1], b1[0], b1[1], ad);
                mma16816(o[nt16*2],     pa[ks], b0);
                mma16816(o[nt16*2 + 1], pa[ks], b1);
            }
        }
        __syncthreads();
    }

    rs0 += __shfl_xor_sync(0xffffffffu, rs0, 1);
    rs0 += __shfl_xor_sync(0xffffffffu, rs0, 2);
    rs1 += __shfl_xor_sync(0xffffffffu, rs1, 1);
    rs1 += __shfl_xor_sync(0xffffffffu, rs1, 2);
    float inv0 = 1.f / rs0, inv1 = 1.f / rs1;

    int row0 = qt*FA_BQ + w*16 + (lane >> 2);
    __half* o0 = att + ((size_t)c*TT + row0)*ATTP + h*DP;
    __half* o1 = o0 + 8*ATTP;
    #pragma unroll
    for (int nt = 0; nt < 13; nt++){
        int col = nt*8 + (lane & 3)*2;
        if (col <= 98){
            *(__half2*)(o0 + col) = __floats2half2_rn(o[nt][0]*inv0, o[nt][1]*inv0);
            *(__half2*)(o1 + col) = __floats2half2_rn(o[nt][2]*inv1, o[nt][3]*inv1);
        }
    }
}

// ---------------- fp16 tensor-core GEMM ----------------
// EPI: 0 half(acc); 3 f32 acc+res; 4 half(relu(acc+bias)); 5 f32 acc+bias+res
#define BM 128
#define BN 64
#define BKK 32

template<int EPI>
__global__ void __launch_bounds__(256)
hgemm(const __half* __restrict__ A, const __half* __restrict__ B,
      float* __restrict__ outF, __half* __restrict__ outH,
      const float* __restrict__ bias, const float* __restrict__ res, int ldr,
      int M, int N, int K, int lda, int ldb, int ldc)
{
    __shared__ __align__(16) __half As[2][BM][BKK+8];
    __shared__ __align__(16) __half Bs[2][BKK][BN+8];

    int tid = threadIdx.x;
    int m0 = blockIdx.y * BM, n0 = blockIdx.x * BN;
    int warp = tid >> 5, lane = tid & 31;
    int wm0 = (warp >> 1) * 32, wn0 = (warp & 1) * 32;

    float c[2][4][4];
    #pragma unroll
    for (int a=0;a<2;a++) for (int b=0;b<4;b++) for (int d=0;d<4;d++) c[a][b][d]=0.f;

    auto prefA = [&](int kt, int buf){
        int k0 = kt*BKK;
        #pragma unroll
        for (int i=0;i<2;i++){
            int q = tid + i*256;
            int r = q >> 2, cc = (q & 3) * 8;
            cpa16(sptr(&As[buf][r][cc]), A + (size_t)(m0+r)*lda + k0 + cc, 16);
        }
    };
    auto prefB = [&](int kt, int buf){
        int k0 = kt*BKK;
        int r = tid >> 3, cc = (tid & 7) * 8;
        int nrem = N - (n0 + cc);
        int bytes = nrem >= 8 ? 16 : (nrem > 0 ? nrem*2 : 0);
        const __half* src = bytes ? (B + (size_t)(k0+r)*ldb + n0 + cc) : B;
        cpa16(sptr(&Bs[buf][r][cc]), src, bytes);
    };

    int nk = K / BKK;
    prefA(0,0); prefB(0,0); cp_commit();

    for (int kt = 0; kt < nk; kt++){
        int buf = kt & 1;
        cp_wait0();
        __syncthreads();
        if (kt+1 < nk){ prefA(kt+1, buf^1); prefB(kt+1, buf^1); }
        cp_commit();

        #pragma unroll
        for (int ks = 0; ks < 2; ks++){
            unsigned a[2][4], b[4][2];
            #pragma unroll
            for (int mt = 0; mt < 2; mt++){
                unsigned ad = sptr(&As[buf][wm0 + mt*16 + (lane & 15)][ks*16 + (lane >> 4)*8]);
                ldsm4(a[mt][0], a[mt][1], a[mt][2], a[mt][3], ad);
            }
            #pragma unroll
            for (int np = 0; np < 2; np++){
                unsigned ad = sptr(&Bs[buf][ks*16 + (lane & 15)][wn0 + np*16 + (lane >> 4)*8]);
                ldsm4t(b[np*2][0], b[np*2][1], b[np*2+1][0], b[np*2+1][1], ad);
            }
            #pragma unroll
            for (int mt = 0; mt < 2; mt++)
                #pragma unroll
                for (int nt = 0; nt < 4; nt++)
                    mma16816(c[mt][nt], a[mt], b[nt]);
        }
        __syncthreads();
    }

    #pragma unroll
    for (int mt = 0; mt < 2; mt++){
        #pragma unroll
        for (int i = 0; i < 2; i++){
            int row = m0 + wm0 + mt*16 + (lane >> 2) + i*8;
            #pragma unroll
            for (int nt = 0; nt < 4; nt++){
                int col = n0 + wn0 + nt*8 + (lane & 3)*2;
                if (col >= N) continue;
                float v0 = c[mt][nt][i*2+0];
                float v1 = c[mt][nt][i*2+1];
                size_t off = (size_t)row*ldc + col;
                if (EPI == 0){
                    *(__half2*)(outH + off) = __floats2half2_rn(v0, v1);
                } else if (EPI == 3){
                    outF[off]   = v0 + res[(size_t)row*ldr + col];
                    outF[off+1] = v1 + res[(size_t)row*ldr + col + 1];
                } else if (EPI == 4){
                    *(__half2*)(outH + off) = __floats2half2_rn(fmaxf(v0 + bias[col], 0.f),
                                                                fmaxf(v1 + bias[col+1], 0.f));
                } else if (EPI == 5){
                    outF[off]   = v0 + bias[col]   + res[(size_t)row*ldr + col];
                    outF[off+1] = v1 + bias[col+1] + res[(size_t)row*ldr + col + 1];
                }
            }
        }
    }
}

// ---------------- weight packing ----------------
__global__ void k_pack_qkv(const float* __restrict__ wq, const float* __restrict__ wk,
                           const float* __restrict__ wv){
    int idx = blockIdx.x*256 + threadIdx.x;
    if (idx >= NLAYER*DP*QKVP) return;
    int l = idx / (DP*QKVP);
    int r = idx % (DP*QKVP);
    int k = r / QKVP, n = r % QKVP;
    int slot = n / DP, d = n % DP;
    int type = slot / HH, h = slot % HH;
    float v = 0.f;
    if (k < DD && d < DD){
        const float* w = type == 0 ? wq : (type == 1 ? wk : wv);
        v = w[(((size_t)l*HH + h)*DD + k)*DD + d];
    }
    g_wqkv[idx] = __float2half(v);
}

__global__ void k_pack_wm(const float* __restrict__ wm){
    int idx = blockIdx.x*256 + threadIdx.x;
    if (idx >= NLAYER*ATTP*DP) return;
    int l = idx / (ATTP*DP);
    int r = idx % (ATTP*DP);
    int k = r / DP, n = r % DP;
    int h = k / DP, dk = k % DP;
    float v = 0.f;
    if (dk < DD && n < DD)
        v = wm[((size_t)l*(HH*DD) + h*DD + dk)*DD + n];
    g_wm[idx] = __float2half(v);
}

__global__ void k_pack_f1(const float* __restrict__ f1){
    int idx = blockIdx.x*256 + threadIdx.x;
    if (idx >= NLAYER*DP*FFND) return;
    int l = idx / (DP*FFND);
    int r = idx % (DP*FFND);
    int k = r / FFND, n = r % FFND;
    g_f1[idx] = __float2half(k < DD ? f1[((size_t)l*DD + k)*FFND + n] : 0.f);
}

__global__ void k_pack_f2(const float* __restrict__ f2){
    int idx = blockIdx.x*256 + threadIdx.x;
    if (idx >= NLAYER*FFND*DP) return;
    int l = idx / (FFND*DP);
    int r = idx % (FFND*DP);
    int k = r / DP, n = r % DP;
    g_f2[idx] = __float2half(n < DD ? f2[((size_t)l*FFND + k)*DD + n] : 0.f);
}

// ---------------- layernorm (fp32 in-place) + fp16 padded output ----------------
__global__ void k_lnh(float* __restrict__ x, const float* __restrict__ g,
                      const float* __restrict__ b, __half* __restrict__ xh){
    int warp = threadIdx.x >> 5;
    int lane = threadIdx.x & 31;
    int row = blockIdx.x*8 + warp;
    if (row >= CT) return;
    float* xr = x + (size_t)row*DD;
    float v0 = xr[lane], v1 = xr[lane+32], v2 = xr[lane+64];
    float v3 = (lane + 96 < DD) ? xr[lane+96] : 0.f;
    float s = v0 + v1 + v2 + v3;
    #pragma unroll
    for (int o = 16; o; o >>= 1) s += __shfl_xor_sync(0xffffffffu, s, o);
    float mean = s * (1.f/DD);
    float d0 = v0-mean, d1 = v1-mean, d2 = v2-mean;
    float d3 = (lane + 96 < DD) ? (v3 - mean) : 0.f;
    float vs = d0*d0 + d1*d1 + d2*d2 + d3*d3;
    #pragma unroll
    for (int o = 16; o; o >>= 1) vs += __shfl_xor_sync(0xffffffffu, vs, o);
    float inv = rsqrtf(vs * (1.f/DD) + 1e-5f);
    __half* hr = xh + (size_t)row*DP;
    float w;
    w = d0*inv*g[lane]    + b[lane];    xr[lane]    = w; hr[lane]    = __float2half(w);
    w = d1*inv*g[lane+32] + b[lane+32]; xr[lane+32] = w; hr[lane+32] = __float2half(w);
    w = d2*inv*g[lane+64] + b[lane+64]; xr[lane+64] = w; hr[lane+64] = __float2half(w);
    if (lane + 96 < DD){
        w = d3*inv*g[lane+96] + b[lane+96]; xr[lane+96] = w; hr[lane+96] = __float2half(w);
    } else {
        hr[96 + lane] = __half(0.f);
    }
}

// ---------------- GCN ----------------
__global__ void k_adj(const float* __restrict__ A){
    int i = threadIdx.x;
    if (i >= CC) return;
    float s = 0.f;
    for (int j = 0; j < CC; j++) s += A[i*CC + j] + (i == j ? 1.f : 0.f);
    float inv = 1.f / s;
    for (int j = 0; j < CC; j++)
        g_adj[i*CC + j] = (A[i*CC + j] + (i == j ? 1.f : 0.f)) * inv;
}

__global__ void k_agg(const float* __restrict__ in, float* __restrict__ out, int TD){
    __shared__ float sadj[CC*CC];
    int tid = threadIdx.x;
    for (int q = tid; q < CC*CC; q += 256) sadj[q] = g_adj[q];
    __syncthreads();
    int n = blockIdx.x*256 + tid;
    if (n >= TD) return;
    float v[CC];
    #pragma unroll
    for (int j = 0; j < CC; j++) v[j] = in[(size_t)j*TD + n];
    #pragma unroll
    for (int i = 0; i < CC; i++){
        float acc = 0.f;
        #pragma unroll
        for (int j = 0; j < CC; j++) acc += sadj[i*CC + j] * v[j];
        out[(size_t)i*TD + n] = acc;
    }
}

// fp32 GEMM for GCN; TOH also writes half to g_xh (padded 128-stride)
template<int RELU, int HASB, int TOH>
__global__ void __launch_bounds__(256)
k_gemm(const float* __restrict__ A, const float* __restrict__ B,
       const float* __restrict__ bias, float* __restrict__ C, int M, int N, int K){
    __shared__ __align__(16) float As[16][64];
    __shared__ __align__(16) float Bs[16][64];
    int tid = threadIdx.x;
    int tx = tid & 15, ty = tid >> 4;
    int m0 = blockIdx.y * 64, n0 = blockIdx.x * 64;
    float acc[4][4] = {};
    int nk = (K + 15) >> 4;
    for (int kt = 0; kt < nk; kt++){
        int k0 = kt * 16;
        {
            int r = tid >> 2; int kc = (tid & 3) * 4;
            int grow = m0 + r;
            #pragma unroll
            for (int i = 0; i < 4; i++){
                int kk = k0 + kc + i;
                As[kc + i][r] = (grow < M && kk < K) ? A[(size_t)grow*K + kk] : 0.f;
            }
        }
        {
            int kr = tid >> 4; int nc = (tid & 15) * 4;
            int gk = k0 + kr;
            #pragma unroll
            for (int i = 0; i < 4; i++){
                int gn = n0 + nc + i;
                Bs[kr][nc + i] = (gk < K && gn < N) ? B[(size_t)gk*N + gn] : 0.f;
            }
        }
        __syncthreads();
        #pragma unroll
        for (int kc = 0; kc < 16; kc++){
            float4 a4 = *(const float4*)&As[kc][ty*4];
            float4 b4 = *(const float4*)&Bs[kc][tx*4];
            float av[4] = {a4.x, a4.y, a4.z, a4.w};
            float bv[4] = {b4.x, b4.y, b4.z, b4.w};
            #pragma unroll
            for (int j = 0; j < 4; j++)
                #pragma unroll
                for (int i = 0; i < 4; i++)
                    acc[j][i] += av[j] * bv[i];
        }
        __syncthreads();
    }
    #pragma unroll
    for (int j = 0; j < 4; j++){
        int row = m0 + ty*4 + j;
        if (row >= M) continue;
        #pragma unroll
        for (int i = 0; i < 4; i++){
            int col = n0 + tx*4 + i;
            if (col >= N) continue;
            float v = acc[j][i];
            if (HASB) v += bias[col];
            if (RELU) v = fmaxf(v, 0.f);
            C[(size_t)row*N + col] = v;
            if (TOH) g_xh[(size_t)row*DP + col] = __float2half(v);
        }
    }
}

// ---------------- prediction head ----------------
// multi-CTA fold (fast): M2 = l1@l2, cvec = l1b@l2 + l2b
__global__ void k_stepM(const float* __restrict__ l1, const float* __restrict__ l1b,
                        const float* __restrict__ l2, const float* __restrict__ l2b){
    int idx = blockIdx.x * blockDim.x + threadIdx.x;
    if (idx < DD*DD){
        int e = idx / DD, d = idx % DD;
        float acc = 0.f;
        for (int r = 0; r < LHID; r++)
            acc += l1[e*LHID + r] * l2[r*DD + d];
        g_M2[idx] = acc;
    } else if (idx < DD*DD + DD){
        int d = idx - DD*DD;
        float acc = l2b[d];
        for (int r = 0; r < LHID; r++)
            acc += l1b[r] * l2[r*DD + d];
        g_cvec[d] = acc;
    }
}

// iterate-only head: one CTA, M2/carry in smem, 10 steps
#define HEAD_SMEM ((DD*DD + DD + CC*DD) * (int)sizeof(float))
__global__ void __launch_bounds__(1024)
k_head(const float* __restrict__ x, float* __restrict__ out){
    extern __shared__ float hs[];
    float* sM2 = hs;                 // [100][100]
    float* scv = sM2 + DD*DD;        // [100]
    float* scr = scv + DD;           // [32][100]
    int tid = threadIdx.x;
    for (int q = tid; q < DD*DD; q += 1024) sM2[q] = g_M2[q];
    if (tid < DD) scv[tid] = g_cvec[tid];
    for (int q = tid; q < CC*DD; q += 1024){
        int c = q / DD, d = q % DD;
        scr[q] = x[((size_t)c*TT + TT - 1)*DD + d];
    }
    __syncthreads();
    for (int k = 0; k < NPREDK; k++){
        float rv[4];
        int cnt = 0;
        for (int q = tid; q < CC*DD; q += 1024){
            int c = q / DD, d = q % DD;
            float acc = scv[d];
            const float* cr = scr + c*DD;
            #pragma unroll 4
            for (int e = 0; e < DD; e++)
                acc += cr[e] * sM2[e*DD + d];
            rv[cnt++] = acc;
        }
        __syncthreads();
        cnt = 0;
        for (int q = tid; q < CC*DD; q += 1024){
            int c = q / DD, d = q % DD;
            scr[q] = rv[cnt];
            out[((size_t)c*NPREDK + k)*DD + d] = rv[cnt];
            cnt++;
        }
        __syncthreads();
    }
}

// ---------------- host orchestration ----------------
static float* symF(const void* s){ void* p = nullptr; cudaGetSymbolAddress(&p, s); return (float*)p; }
static __half* symH(const void* s){ void* p = nullptr; cudaGetSymbolAddress(&p, s); return (__half*)p; }

extern "C" void kernel_launch(void* const* d_in, const int* in_sizes, int n_in,
                              void* d_out, int out_size){
    const float* X      = (const float*)d_in[0];
    const float* A      = (const float*)d_in[1];
    const float* gcn_w1 = (const float*)d_in[2];
    const float* gcn_b1 = (const float*)d_in[3];
    const float* gcn_w2 = (const float*)d_in[4];
    const float* gcn_b2 = (const float*)d_in[5];
    const float* enc_wq = (const float*)d_in[6];
    const float* enc_wk = (const float*)d_in[7];
    const float* enc_wv = (const float*)d_in[8];
    const float* enc_wm = (const float*)d_in[9];
    const float* enc_f1w= (const float*)d_in[10];
    const float* enc_f1b= (const float*)d_in[11];
    const float* enc_f2w= (const float*)d_in[12];
    const float* enc_f2b= (const float*)d_in[13];
    const float* ln1g   = (const float*)d_in[14];
    const float* ln1b   = (const float*)d_in[15];
    const float* ln2g   = (const float*)d_in[16];
    const float* ln2b   = (const float*)d_in[17];
    const float* lin1_w = (const float*)d_in[18];
    const float* lin1_b = (const float*)d_in[19];
    const float* lin2_w = (const float*)d_in[20];
    const float* lin2_b = (const float*)d_in[21];
    float* out = (float*)d_out;

    float*  p_h1   = symF(g_h1);
    float*  p_hid  = symF(g_hid);
    float*  p_hid2 = symF(g_hid2);
    float*  p_x    = symF(g_x);
    float*  p_y    = symF(g_y);
    __half* p_xh   = symH(g_xh);
    __half* p_qkv  = symH(g_qkvh);
    __half* p_att  = symH(g_atth);
    __half* p_ffn  = symH(g_ffnh);
    __half* p_wqkv = symH(g_wqkv);
    __half* p_wm   = symH(g_wm);
    __half* p_f1   = symH(g_f1);
    __half* p_f2   = symH(g_f2);

    cudaFuncSetAttribute(k_fattn, cudaFuncAttributeMaxDynamicSharedMemorySize, FA_SMEM);
    cudaFuncSetAttribute(k_head,  cudaFuncAttributeMaxDynamicSharedMemorySize, HEAD_SMEM);

    // GCN (fp32); final gemm also emits fp16 padded xh
    k_adj<<<1, 32>>>(A);
    k_agg<<<(TT*DD + 255)/256, 256>>>(X, p_h1, TT*DD);
    k_gemm<1,1,0><<<dim3(1, CT/64), 256>>>(p_h1, gcn_w1, gcn_b1, p_hid, CT, HIDG, DD);
    k_agg<<<(TT*HIDG + 255)/256, 256>>>(p_hid, p_hid2, TT*HIDG);
    k_gemm<0,1,1><<<dim3(2, CT/64), 256>>>(p_hid2, gcn_w2, gcn_b2, p_x, CT, DD, HIDG);

    // pack weights fp16 (all layers); fold head affine (multi-CTA, overlaps)
    k_pack_qkv<<<(NLAYER*DP*QKVP + 255)/256, 256>>>(enc_wq, enc_wk, enc_wv);
    k_pack_wm <<<(NLAYER*ATTP*DP + 255)/256, 256>>>(enc_wm);
    k_pack_f1 <<<(NLAYER*DP*FFND + 255)/256, 256>>>(enc_f1w);
    k_pack_f2 <<<(NLAYER*FFND*DP + 255)/256, 256>>>(enc_f2w);
    k_stepM<<<(DD*DD + DD + 255)/256, 256>>>(lin1_w, lin1_b, lin2_w, lin2_b);

    for (int l = 0; l < NLAYER; l++){
        // QKV: [CT,128] @ [128,1920] -> fp16
        hgemm<0><<<dim3(QKVP/BN, CT/BM), 256>>>(
            p_xh, p_wqkv + (size_t)l*DP*QKVP, nullptr, p_qkv, nullptr, nullptr, 0,
            CT, QKVP, DP, DP, QKVP, QKVP);

        // fused attention
        k_fattn<<<dim3(TT/FA_BQ, NB), 256, FA_SMEM>>>(p_qkv, p_att);

        // proj: y = x + att @ wm  (fp32 out)
        hgemm<3><<<dim3(2, CT/BM), 256>>>(
            p_att, p_wm + (size_t)l*ATTP*DP, p_y, nullptr, nullptr, p_x, DD,
            CT, DD, ATTP, ATTP, DP, DD);

        k_lnh<<<CT/8, 256>>>(p_y, ln1g + l*DD, ln1b + l*DD, p_xh);

        // ffn1: relu(xh @ f1 + b1) -> fp16
        hgemm<4><<<dim3(1, CT/BM), 256>>>(
            p_xh, p_f1 + (size_t)l*DP*FFND, nullptr, p_ffn, enc_f1b + l*FFND, nullptr, 0,
            CT, FFND, DP, DP, FFND, FFND);

        // ffn2: x = y + ffn @ f2 + b2 (fp32 out)
        hgemm<5><<<dim3(2, CT/BM), 256>>>(
            p_ffn, p_f2 + (size_t)l*FFND*DP, p_x, nullptr, enc_f2b + l*DD, p_y, DD,
            CT, DD, FFND, FFND, DP, DD);

        k_lnh<<<CT/8, 256>>>(p_x, ln2g + l*DD, ln2b + l*DD, p_xh);
    }

    // head: iterate 10 steps (fold already done in k_stepM)
    k_head<<<1, 1024, HEAD_SMEM>>>(p_x, out);
}

// round 10
// speedup vs baseline: 1.5461x; 1.0292x over previous
#include <cuda_runtime.h>
#include <cuda_fp16.h>
#include <math.h>

#define CC 32
#define TT 768
#define DD 100
#define HH 5
#define HIDG 60
#define FFND 64
#define NPREDK 10
#define LHID 200
#define NLAYER 3
#define CT (CC*TT)          // 24576
#define DP 128              // padded feature/head dim
#define QKVP (15*DP)        // 1920
#define ATTP (HH*DP)        // 640
#define NB (CC*HH)          // 160

// ---------------- device scratch ----------------
__device__ float g_adj[CC*CC];
__device__ float g_h1[CT*DD];
__device__ float g_hid[CT*HIDG];
__device__ float g_hid2[CT*HIDG];
__device__ float g_x[CT*DD];
__device__ float g_y[CT*DD];
__device__ float g_M2[DD*DD];
__device__ float g_cvec[DD];

__device__ __half g_xh[CT*DP];
__device__ __half g_qkvh[(size_t)CT*QKVP];
__device__ __half g_atth[(size_t)CT*ATTP];   // pad cols stay zero (.bss)
__device__ __half g_ffnh[CT*FFND];
__device__ __half g_wqkv[NLAYER*DP*QKVP];
__device__ __half g_wm[NLAYER*ATTP*DP];
__device__ __half g_f1[NLAYER*DP*FFND];
__device__ __half g_f2[NLAYER*FFND*DP];

// ---------------- small helpers ----------------
__device__ __forceinline__ unsigned sptr(const void* p){
    return (unsigned)__cvta_generic_to_shared(p);
}
__device__ __forceinline__ void cpa16(unsigned dst, const void* src, int bytes){
    asm volatile("cp.async.cg.shared.global [%0], [%1], 16, %2;\n"
                 :: "r"(dst), "l"(src), "r"(bytes));
}
__device__ __forceinline__ void cp_commit(){ asm volatile("cp.async.commit_group;\n" ::: "memory"); }
__device__ __forceinline__ void cp_wait0(){ asm volatile("cp.async.wait_group 0;\n" ::: "memory"); }

__device__ __forceinline__ void ldsm4(unsigned& r0,unsigned& r1,unsigned& r2,unsigned& r3, unsigned a){
    asm volatile("ldmatrix.sync.aligned.m8n8.x4.shared.b16 {%0,%1,%2,%3}, [%4];\n"
        : "=r"(r0),"=r"(r1),"=r"(r2),"=r"(r3) : "r"(a));
}
__device__ __forceinline__ void ldsm4t(unsigned& r0,unsigned& r1,unsigned& r2,unsigned& r3, unsigned a){
    asm volatile("ldmatrix.sync.aligned.m8n8.x4.trans.shared.b16 {%0,%1,%2,%3}, [%4];\n"
        : "=r"(r0),"=r"(r1),"=r"(r2),"=r"(r3) : "r"(a));
}
__device__ __forceinline__ void mma16816(float* c, const unsigned* a, const unsigned* b){
    asm volatile("mma.sync.aligned.m16n8k16.row.col.f32.f16.f16.f32 "
        "{%0,%1,%2,%3}, {%4,%5,%6,%7}, {%8,%9}, {%0,%1,%2,%3};\n"
        : "+f"(c[0]),"+f"(c[1]),"+f"(c[2]),"+f"(c[3])
        : "r"(a[0]),"r"(a[1]),"r"(a[2]),"r"(a[3]), "r"(b[0]),"r"(b[1]));
}

// ---------------- fused flash attention ----------------
// R5 layout/copies; zero-pad MMA tiles skipped; exp interleaved with PV per-ks
#define FA_BQ 128
#define FA_BK 64
#define FA_DS 136
#define FA_SMEM ((FA_BQ + 4*FA_BK) * FA_DS * 2)

__global__ void __launch_bounds__(256, 1)
k_fattn(const __half* __restrict__ qkv, __half* __restrict__ att){
    extern __shared__ __align__(16) __half sm[];
    __half* Qs = sm;                       // [128][136]
    __half* Ks = Qs + FA_BQ*FA_DS;         // [2][64][136]
    __half* Vs = Ks + 2*FA_BK*FA_DS;       // [2][64][136]

    int tid = threadIdx.x, lane = tid & 31, w = tid >> 5;
    int qt = blockIdx.x;
    int z = blockIdx.y;
    int c = z / HH, h = z % HH;
    const __half* Qg = qkv + (size_t)c*TT*QKVP + h*DP;
    const __half* Kg = Qg + HH*DP;
    const __half* Vg = Qg + 2*HH*DP;

    #pragma unroll
    for (int i = 0; i < 8; i++){
        int idx = tid + i*256;
        int r = idx >> 4, cc2 = (idx & 15) * 8;
        cpa16(sptr(&Qs[r*FA_DS + cc2]), Qg + (size_t)(qt*FA_BQ + r)*QKVP + cc2, 16);
    }
    cp_commit();

    auto prefKV = [&](int kt, int buf){
        const __half* kb = Kg + (size_t)kt*FA_BK*QKVP;
        const __half* vb = Vg + (size_t)kt*FA_BK*QKVP;
        #pragma unroll
        for (int i = 0; i < 4; i++){
            int idx = tid + i*256;
            int r = idx >> 4, cc2 = (idx & 15) * 8;
            cpa16(sptr(&Ks[(buf*FA_BK + r)*FA_DS + cc2]), kb + (size_t)r*QKVP + cc2, 16);
        }
        #pragma unroll
        for (int i = 0; i < 4; i++){
            int idx = tid + i*256;
            int r = idx >> 4, cc2 = (idx & 15) * 8;
            cpa16(sptr(&Vs[(buf*FA_BK + r)*FA_DS + cc2]), vb + (size_t)r*QKVP + cc2, 16);
        }
    };
    prefKV(0, 0);
    cp_commit();
    cp_wait0();
    __syncthreads();

    unsigned qa[7][4];
    #pragma unroll
    for (int kk = 0; kk < 7; kk++){
        unsigned ad = sptr(&Qs[(w*16 + (lane & 15))*FA_DS + kk*16 + (lane >> 4)*8]);
        ldsm4(qa[kk][0], qa[kk][1], qa[kk][2], qa[kk][3], ad);
    }

    float o[14][4];
    #pragma unroll
    for (int i = 0; i < 14; i++){ o[i][0]=0.f; o[i][1]=0.f; o[i][2]=0.f; o[i][3]=0.f; }
    float rs0 = 0.f, rs1 = 0.f;

    for (int kt = 0; kt < TT/FA_BK; kt++){
        int buf = kt & 1;
        if (kt){
            cp_wait0();
            __syncthreads();
        }
        if (kt + 1 < TT/FA_BK) prefKV(kt + 1, buf ^ 1);
        cp_commit();

        float s[8][4];
        #pragma unroll
        for (int i = 0; i < 8; i++){ s[i][0]=0.f; s[i][1]=0.f; s[i][2]=0.f; s[i][3]=0.f; }
        #pragma unroll
        for (int ks = 0; ks < 7; ks++){
            unsigned kbf[8][2];
            #pragma unroll
            for (int np = 0; np < 4; np++){
                unsigned ad = sptr(&Ks[(buf*FA_BK + np*16 + (lane & 7) + ((lane >> 4) << 3))*FA_DS
                                        + ks*16 + ((lane >> 3) & 1)*8]);
                ldsm4(kbf[np*2][0], kbf[np*2][1], kbf[np*2+1][0], kbf[np*2+1][1], ad);
            }
            #pragma unroll
            for (int nt = 0; nt < 8; nt++)
                mma16816(s[nt], qa[ks], kbf[nt]);
        }

        // interleaved: per PV k-step, convert exactly the two s-tiles it needs
        // (rowsum add order nt=0,1,...,7 preserved -> bit-identical numerics)
        #pragma unroll
        for (int ks = 0; ks < 4; ks++){
            unsigned paks[4];
            #pragma unroll
            for (int j = 0; j < 2; j++){
                int nt = 2*ks + j;
                __half2 h01 = __floats2half2_rn(__expf(s[nt][0]*0.1f), __expf(s[nt][1]*0.1f));
                __half2 h23 = __floats2half2_rn(__expf(s[nt][2]*0.1f), __expf(s[nt][3]*0.1f));
                paks[2*j]     = *(unsigned*)&h01;
                paks[2*j + 1] = *(unsigned*)&h23;
                float2 f01 = __half22float2(h01); rs0 += f01.x + f01.y;
                float2 f23 = __half22float2(h23); rs1 += f23.x + f23.y;
            }
            #pragma unroll
            for (int nt16 = 0; nt16 < 7; nt16++){
                unsigned b0[2], b1[2];
                unsigned ad = sptr(&Vs[(buf*FA_BK + ks*16 + (lane & 15))*FA_DS
                                        + nt16*16 + (lane >> 4)*8]);
                ldsm4t(b0[0], b0[1], b1[0], b1[1], ad);
                mma16816(o[nt16*2],     paks, b0);
                mma16816(o[nt16*2 + 1], paks, b1);
            }
        }
        __syncthreads();
    }

    rs0 += __shfl_xor_sync(0xffffffffu, rs0, 1);
    rs0 += __shfl_xor_sync(0xffffffffu, rs0, 2);
    rs1 += __shfl_xor_sync(0xffffffffu, rs1, 1);
    rs1 += __shfl_xor_sync(0xffffffffu, rs1, 2);
    float inv0 = 1.f / rs0, inv1 = 1.f / rs1;

    int row0 = qt*FA_BQ + w*16 + (lane >> 2);
    __half* o0 = att + ((size_t)c*TT + row0)*ATTP + h*DP;
    __half* o1 = o0 + 8*ATTP;
    #pragma unroll
    for (int nt = 0; nt < 13; nt++){
        int col = nt*8 + (lane & 3)*2;
        if (col <= 98){
            *(__half2*)(o0 + col) = __floats2half2_rn(o[nt][0]*inv0, o[nt][1]*inv0);
            *(__half2*)(o1 + col) = __floats2half2_rn(o[nt][2]*inv1, o[nt][3]*inv1);
        }
    }
}

// ---------------- QKV special GEMM: K=128 fully smem-resident, no pipeline ----------------
#define QBM 128
#define QBN 64
__global__ void __launch_bounds__(256)
k_qkv(const __half* __restrict__ A, const __half* __restrict__ B, __half* __restrict__ C){
    __shared__ __align__(16) __half As[QBM][DP+8];   // 128 x 136
    __shared__ __align__(16) __half Bs[DP][QBN+8];   // 128 x 72
    int tid = threadIdx.x;
    int m0 = blockIdx.y * QBM, n0 = blockIdx.x * QBN;
    int warp = tid >> 5, lane = tid & 31;
    int wm0 = (warp >> 1) * 32, wn0 = (warp & 1) * 32;

    #pragma unroll
    for (int i = 0; i < 8; i++){
        int idx = tid + i*256;
        int r = idx >> 4, cc = (idx & 15) * 8;
        cpa16(sptr(&As[r][cc]), A + (size_t)(m0 + r)*DP + cc, 16);
    }
    #pragma unroll
    for (int i = 0; i < 4; i++){
        int idx = tid + i*256;
        int r = idx >> 3, cc = (idx & 7) * 8;
        cpa16(sptr(&Bs[r][cc]), B + (size_t)r*QKVP + n0 + cc, 16);
    }
    cp_commit(); cp_wait0(); __syncthreads();

    float c[2][4][4];
    #pragma unroll
    for (int a=0;a<2;a++) for (int b=0;b<4;b++) for (int d=0;d<4;d++) c[a][b][d]=0.f;

    #pragma unroll
    for (int ks = 0; ks < 8; ks++){
        unsigned a[2][4], b[4][2];
        #pragma unroll
        for (int mt = 0; mt < 2; mt++){
            unsigned ad = sptr(&As[wm0 + mt*16 + (lane & 15)][ks*16 + (lane >> 4)*8]);
            ldsm4(a[mt][0], a[mt][1], a[mt][2], a[mt][3], ad);
        }
        #pragma unroll
        for (int np = 0; np < 2; np++){
            unsigned ad = sptr(&Bs[ks*16 + (lane & 15)][wn0 + np*16 + (lane >> 4)*8]);
            ldsm4t(b[np*2][0], b[np*2][1], b[np*2+1][0], b[np*2+1][1], ad);
        }
        #pragma unroll
        for (int mt = 0; mt < 2; mt++)
            #pragma unroll
            for (int nt = 0; nt < 4; nt++)
                mma16816(c[mt][nt], a[mt], b[nt]);
    }

    #pragma unroll
    for (int mt = 0; mt < 2; mt++){
        #pragma unroll
        for (int i = 0; i < 2; i++){
            int row = m0 + wm0 + mt*16 + (lane >> 2) + i*8;
            #pragma unroll
            for (int nt = 0; nt < 4; nt++){
                int col = n0 + wn0 + nt*8 + (lane & 3)*2;
                *(__half2*)(C + (size_t)row*QKVP + col) =
                    __floats2half2_rn(c[mt][nt][i*2+0], c[mt][nt][i*2+1]);
            }
        }
    }
}

// ---------------- fp16 tensor-core GEMM (generic, R5-proven) ----------------
// EPI: 0 half(acc); 3 f32 acc+res; 4 half(relu(acc+bias)); 5 f32 acc+bias+res
#define BM 128
#define BN 64
#define BKK 32

template<int EPI>
__global__ void __launch_bounds__(256)
hgemm(const __half* __restrict__ A, const __half* __restrict__ B,
      float* __restrict__ outF, __half* __restrict__ outH,
      const float* __restrict__ bias, const float* __restrict__ res, int ldr,
      int M, int N, int K, int lda, int ldb, int ldc)
{
    __shared__ __align__(16) __half As[2][BM][BKK+8];
    __shared__ __align__(16) __half Bs[2][BKK][BN+8];

    int tid = threadIdx.x;
    int m0 = blockIdx.y * BM, n0 = blockIdx.x * BN;
    int warp = tid >> 5, lane = tid & 31;
    int wm0 = (warp >> 1) * 32, wn0 = (warp & 1) * 32;

    float c[2][4][4];
    #pragma unroll
    for (int a=0;a<2;a++) for (int b=0;b<4;b++) for (int d=0;d<4;d++) c[a][b][d]=0.f;

    auto prefA = [&](int kt, int buf){
        int k0 = kt*BKK;
        #pragma unroll
        for (int i=0;i<2;i++){
            int q = tid + i*256;
            int r = q >> 2, cc = (q & 3) * 8;
            cpa16(sptr(&As[buf][r][cc]), A + (size_t)(m0+r)*lda + k0 + cc, 16);
        }
    };
    auto prefB = [&](int kt, int buf){
        int k0 = kt*BKK;
        int r = tid >> 3, cc = (tid & 7) * 8;
        int nrem = N - (n0 + cc);
        int bytes = nrem >= 8 ? 16 : (nrem > 0 ? nrem*2 : 0);
        const __half* src = bytes ? (B + (size_t)(k0+r)*ldb + n0 + cc) : B;
        cpa16(sptr(&Bs[buf][r][cc]), src, bytes);
    };

    int nk = K / BKK;
    prefA(0,0); prefB(0,0); cp_commit();

    for (int kt = 0; kt < nk; kt++){
        int buf = kt & 1;
        cp_wait0();
        __syncthreads();
        if (kt+1 < nk){ prefA(kt+1, buf^1); prefB(kt+1, buf^1); }
        cp_commit();

        #pragma unroll
        for (int ks = 0; ks < 2; ks++){
            unsigned a[2][4], b[4][2];
            #pragma unroll
            for (int mt = 0; mt < 2; mt++){
                unsigned ad = sptr(&As[buf][wm0 + mt*16 + (lane & 15)][ks*16 + (lane >> 4)*8]);
                ldsm4(a[mt][0], a[mt][1], a[mt][2], a[mt][3], ad);
            }
            #pragma unroll
            for (int np = 0; np < 2; np++){
                unsigned ad = sptr(&Bs[buf][ks*16 + (lane & 15)][wn0 + np*16 + (lane >> 4)*8]);
                ldsm4t(b[np*2][0], b[np*2][1], b[np*2+1][0], b[np*2+1][1], ad);
            }
            #pragma unroll
            for (int mt = 0; mt < 2; mt++)
                #pragma unroll
                for (int nt = 0; nt < 4; nt++)
                    mma16816(c[mt][nt], a[mt], b[nt]);
        }
        __syncthreads();
    }

    #pragma unroll
    for (int mt = 0; mt < 2; mt++){
        #pragma unroll
        for (int i = 0; i < 2; i++){
            int row = m0 + wm0 + mt*16 + (lane >> 2) + i*8;
            #pragma unroll
            for (int nt = 0; nt < 4; nt++){
                int col = n0 + wn0 + nt*8 + (lane & 3)*2;
                if (col >= N) continue;
                float v0 = c[mt][nt][i*2+0];
                float v1 = c[mt][nt][i*2+1];
                size_t off = (size_t)row*ldc + col;
                if (EPI == 0){
                    *(__half2*)(outH + off) = __floats2half2_rn(v0, v1);
                } else if (EPI == 3){
                    outF[off]   = v0 + res[(size_t)row*ldr + col];
                    outF[off+1] = v1 + res[(size_t)row*ldr + col + 1];
                } else if (EPI == 4){
                    *(__half2*)(outH + off) = __floats2half2_rn(fmaxf(v0 + bias[col], 0.f),
                                                                fmaxf(v1 + bias[col+1], 0.f));
                } else if (EPI == 5){
                    outF[off]   = v0 + bias[col]   + res[(size_t)row*ldr + col];
                    outF[off+1] = v1 + bias[col+1] + res[(size_t)row*ldr + col + 1];
                }
            }
        }
    }
}

// ---------------- weight packing ----------------
__global__ void k_pack_qkv(const float* __restrict__ wq, const float* __restrict__ wk,
                           const float* __restrict__ wv){
    int idx = blockIdx.x*256 + threadIdx.x;
    if (idx >= NLAYER*DP*QKVP) return;
    int l = idx / (DP*QKVP);
    int r = idx % (DP*QKVP);
    int k = r / QKVP, n = r % QKVP;
    int slot = n / DP, d = n % DP;
    int type = slot / HH, h = slot % HH;
    float v = 0.f;
    if (k < DD && d < DD){
        const float* w = type == 0 ? wq : (type == 1 ? wk : wv);
        v = w[(((size_t)l*HH + h)*DD + k)*DD + d];
    }
    g_wqkv[idx] = __float2half(v);
}

__global__ void k_pack_wm(const float* __restrict__ wm){
    int idx = blockIdx.x*256 + threadIdx.x;
    if (idx >= NLAYER*ATTP*DP) return;
    int l = idx / (ATTP*DP);
    int r = idx % (ATTP*DP);
    int k = r / DP, n = r % DP;
    int h = k / DP, dk = k % DP;
    float v = 0.f;
    if (dk < DD && n < DD)
        v = wm[((size_t)l*(HH*DD) + h*DD + dk)*DD + n];
    g_wm[idx] = __float2half(v);
}

__global__ void k_pack_f1(const float* __restrict__ f1){
    int idx = blockIdx.x*256 + threadIdx.x;
    if (idx >= NLAYER*DP*FFND) return;
    int l = idx / (DP*FFND);
    int r = idx % (DP*FFND);
    int k = r / FFND, n = r % FFND;
    g_f1[idx] = __float2half(k < DD ? f1[((size_t)l*DD + k)*FFND + n] : 0.f);
}

__global__ void k_pack_f2(const float* __restrict__ f2){
    int idx = blockIdx.x*256 + threadIdx.x;
    if (idx >= NLAYER*FFND*DP) return;
    int l = idx / (FFND*DP);
    int r = idx % (FFND*DP);
    int k = r / DP, n = r % DP;
    g_f2[idx] = __float2half(n < DD ? f2[((size_t)l*FFND + k)*DD + n] : 0.f);
}

// ---------------- layernorm (fp32 in-place) + fp16 padded output ----------------
__global__ void k_lnh(float* __restrict__ x, const float* __restrict__ g,
                      const float* __restrict__ b, __half* __restrict__ xh){
    int warp = threadIdx.x >> 5;
    int lane = threadIdx.x & 31;
    int row = blockIdx.x*8 + warp;
    if (row >= CT) return;
    float* xr = x + (size_t)row*DD;
    float v0 = xr[lane], v1 = xr[lane+32], v2 = xr[lane+64];
    float v3 = (lane + 96 < DD) ? xr[lane+96] : 0.f;
    float s = v0 + v1 + v2 + v3;
    #pragma unroll
    for (int o = 16; o; o >>= 1) s += __shfl_xor_sync(0xffffffffu, s, o);
    float mean = s * (1.f/DD);
    float d0 = v0-mean, d1 = v1-mean, d2 = v2-mean;
    float d3 = (lane + 96 < DD) ? (v3 - mean) : 0.f;
    float vs = d0*d0 + d1*d1 + d2*d2 + d3*d3;
    #pragma unroll
    for (int o = 16; o; o >>= 1) vs += __shfl_xor_sync(0xffffffffu, vs, o);
    float inv = rsqrtf(vs * (1.f/DD) + 1e-5f);
    __half* hr = xh + (size_t)row*DP;
    float w;
    w = d0*inv*g[lane]    + b[lane];    xr[lane]    = w; hr[lane]    = __float2half(w);
    w = d1*inv*g[lane+32] + b[lane+32]; xr[lane+32] = w; hr[lane+32] = __float2half(w);
    w = d2*inv*g[lane+64] + b[lane+64]; xr[lane+64] = w; hr[lane+64] = __float2half(w);
    if (lane + 96 < DD){
        w = d3*inv*g[lane+96] + b[lane+96]; xr[lane+96] = w; hr[lane+96] = __float2half(w);
    } else {
        hr[96 + lane] = __half(0.f);
    }
}

// ---------------- GCN ----------------
__global__ void k_adj(const float* __restrict__ A){
    int i = threadIdx.x;
    if (i >= CC) return;
    float s = 0.f;
    for (int j = 0; j < CC; j++) s += A[i*CC + j] + (i == j ? 1.f : 0.f);
    float inv = 1.f / s;
    for (int j = 0; j < CC; j++)
        g_adj[i*CC + j] = (A[i*CC + j] + (i == j ? 1.f : 0.f)) * inv;
}

__global__ void k_agg(const float* __restrict__ in, float* __restrict__ out, int TD){
    __shared__ float sadj[CC*CC];
    int tid = threadIdx.x;
    for (int q = tid; q < CC*CC; q += 256) sadj[q] = g_adj[q];
    __syncthreads();
    int n = blockIdx.x*256 + tid;
    if (n >= TD) return;
    float v[CC];
    #pragma unroll
    for (int j = 0; j < CC; j++) v[j] = in[(size_t)j*TD + n];
    #pragma unroll
    for (int i = 0; i < CC; i++){
        float acc = 0.f;
        #pragma unroll
        for (int j = 0; j < CC; j++) acc += sadj[i*CC + j] * v[j];
        out[(size_t)i*TD + n] = acc;
    }
}

// fp32 GEMM for GCN; TOH also writes half to g_xh (padded 128-stride)
template<int RELU, int HASB, int TOH>
__global__ void __launch_bounds__(256)
k_gemm(const float* __restrict__ A, const float* __restrict__ B,
       const float* __restrict__ bias, float* __restrict__ C, int M, int N, int K){
    __shared__ __align__(16) float As[16][64];
    __shared__ __align__(16) float Bs[16][64];
    int tid = threadIdx.x;
    int tx = tid & 15, ty = tid >> 4;
    int m0 = blockIdx.y * 64, n0 = blockIdx.x * 64;
    float acc[4][4] = {};
    int nk = (K + 15) >> 4;
    for (int kt = 0; kt < nk; kt++){
        int k0 = kt * 16;
        {
            int r = tid >> 2; int kc = (tid & 3) * 4;
            int grow = m0 + r;
            #pragma unroll
            for (int i = 0; i < 4; i++){
                int kk = k0 + kc + i;
                As[kc + i][r] = (grow < M && kk < K) ? A[(size_t)grow*K + kk] : 0.f;
            }
        }
        {
            int kr = tid >> 4; int nc = (tid & 15) * 4;
            int gk = k0 + kr;
            #pragma unroll
            for (int i = 0; i < 4; i++){
                int gn = n0 + nc + i;
                Bs[kr][nc + i] = (gk < K && gn < N) ? B[(size_t)gk*N + gn] : 0.f;
            }
        }
        __syncthreads();
        #pragma unroll
        for (int kc = 0; kc < 16; kc++){
            float4 a4 = *(const float4*)&As[kc][ty*4];
            float4 b4 = *(const float4*)&Bs[kc][tx*4];
            float av[4] = {a4.x, a4.y, a4.z, a4.w};
            float bv[4] = {b4.x, b4.y, b4.z, b4.w};
            #pragma unroll
            for (int j = 0; j < 4; j++)
                #pragma unroll
                for (int i = 0; i < 4; i++)
                    acc[j][i] += av[j] * bv[i];
        }
        __syncthreads();
    }
    #pragma unroll
    for (int j = 0; j < 4; j++){
        int row = m0 + ty*4 + j;
        if (row >= M) continue;
        #pragma unroll
        for (int i = 0; i < 4; i++){
            int col = n0 + tx*4 + i;
            if (col >= N) continue;
            float v = acc[j][i];
            if (HASB) v += bias[col];
            if (RELU) v = fmaxf(v, 0.f);
            C[(size_t)row*N + col] = v;
            if (TOH) g_xh[(size_t)row*DP + col] = __float2half(v);
        }
    }
}

// ---------------- prediction head ----------------
__global__ void k_stepM(const float* __restrict__ l1, const float* __restrict__ l1b,
                        const float* __restrict__ l2, const float* __restrict__ l2b){
    int idx = blockIdx.x * blockDim.x + threadIdx.x;
    if (idx < DD*DD){
        int e = idx / DD, d = idx % DD;
        float acc = 0.f;
        for (int r = 0; r < LHID; r++)
            acc += l1[e*LHID + r] * l2[r*DD + d];
        g_M2[idx] = acc;
    } else if (idx < DD*DD + DD){
        int d = idx - DD*DD;
        float acc = l2b[d];
        for (int r = 0; r < LHID; r++)
            acc += l1b[r] * l2[r*DD + d];
        g_cvec[d] = acc;
    }
}

#define HEAD_SMEM ((DD*DD + DD + CC*DD) * (int)sizeof(float))
__global__ void __launch_bounds__(1024)
k_head(const float* __restrict__ x, float* __restrict__ out){
    extern __shared__ float hs[];
    float* sM2 = hs;                 // [100][100]
    float* scv = sM2 + DD*DD;        // [100]
    float* scr = scv + DD;           // [32][100]
    int tid = threadIdx.x;
    for (int q = tid; q < DD*DD; q += 1024) sM2[q] = g_M2[q];
    if (tid < DD) scv[tid] = g_cvec[tid];
    for (int q = tid; q < CC*DD; q += 1024){
        int c = q / DD, d = q % DD;
        scr[q] = x[((size_t)c*TT + TT - 1)*DD + d];
    }
    __syncthreads();
    for (int k = 0; k < NPREDK; k++){
        float rv[4];
        int cnt = 0;
        for (int q = tid; q < CC*DD; q += 1024){
            int c = q / DD, d = q % DD;
            float acc = scv[d];
            const float* cr = scr + c*DD;
            #pragma unroll 4
            for (int e = 0; e < DD; e++)
                acc += cr[e] * sM2[e*DD + d];
            rv[cnt++] = acc;
        }
        __syncthreads();
        cnt = 0;
        for (int q = tid; q < CC*DD; q += 1024){
            int c = q / DD, d = q % DD;
            scr[q] = rv[cnt];
            out[((size_t)c*NPREDK + k)*DD + d] = rv[cnt];
            cnt++;
        }
        __syncthreads();
    }
}

// ---------------- host orchestration ----------------
static float* symF(const void* s){ void* p = nullptr; cudaGetSymbolAddress(&p, s); return (float*)p; }
static __half* symH(const void* s){ void* p = nullptr; cudaGetSymbolAddress(&p, s); return (__half*)p; }

extern "C" void kernel_launch(void* const* d_in, const int* in_sizes, int n_in,
                              void* d_out, int out_size){
    const float* X      = (const float*)d_in[0];
    const float* A      = (const float*)d_in[1];
    const float* gcn_w1 = (const float*)d_in[2];
    const float* gcn_b1 = (const float*)d_in[3];
    const float* gcn_w2 = (const float*)d_in[4];
    const float* gcn_b2 = (const float*)d_in[5];
    const float* enc_wq = (const float*)d_in[6];
    const float* enc_wk = (const float*)d_in[7];
    const float* enc_wv = (const float*)d_in[8];
    const float* enc_wm = (const float*)d_in[9];
    const float* enc_f1w= (const float*)d_in[10];
    const float* enc_f1b= (const float*)d_in[11];
    const float* enc_f2w= (const float*)d_in[12];
    const float* enc_f2b= (const float*)d_in[13];
    const float* ln1g   = (const float*)d_in[14];
    const float* ln1b   = (const float*)d_in[15];
    const float* ln2g   = (const float*)d_in[16];
    const float* ln2b   = (const float*)d_in[17];
    const float* lin1_w = (const float*)d_in[18];
    const float* lin1_b = (const float*)d_in[19];
    const float* lin2_w = (const float*)d_in[20];
    const float* lin2_b = (const float*)d_in[21];
    float* out = (float*)d_out;

    float*  p_h1   = symF(g_h1);
    float*  p_hid  = symF(g_hid);
    float*  p_hid2 = symF(g_hid2);
    float*  p_x    = symF(g_x);
    float*  p_y    = symF(g_y);
    __half* p_xh   = symH(g_xh);
    __half* p_qkv  = symH(g_qkvh);
    __half* p_att  = symH(g_atth);
    __half* p_ffn  = symH(g_ffnh);
    __half* p_wqkv = symH(g_wqkv);
    __half* p_wm   = symH(g_wm);
    __half* p_f1   = symH(g_f1);
    __half* p_f2   = symH(g_f2);

    cudaFuncSetAttribute(k_fattn, cudaFuncAttributeMaxDynamicSharedMemorySize, FA_SMEM);
    cudaFuncSetAttribute(k_head,  cudaFuncAttributeMaxDynamicSharedMemorySize, HEAD_SMEM);

    // GCN (fp32); final gemm also emits fp16 padded xh
    k_adj<<<1, 32>>>(A);
    k_agg<<<(TT*DD + 255)/256, 256>>>(X, p_h1, TT*DD);
    k_gemm<1,1,0><<<dim3(1, CT/64), 256>>>(p_h1, gcn_w1, gcn_b1, p_hid, CT, HIDG, DD);
    k_agg<<<(TT*HIDG + 255)/256, 256>>>(p_hid, p_hid2, TT*HIDG);
    k_gemm<0,1,1><<<dim3(2, CT/64), 256>>>(p_hid2, gcn_w2, gcn_b2, p_x, CT, DD, HIDG);

    // pack weights fp16 (all layers); fold head affine (multi-CTA)
    k_pack_qkv<<<(NLAYER*DP*QKVP + 255)/256, 256>>>(enc_wq, enc_wk, enc_wv);
    k_pack_wm <<<(NLAYER*ATTP*DP + 255)/256, 256>>>(enc_wm);
    k_pack_f1 <<<(NLAYER*DP*FFND + 255)/256, 256>>>(enc_f1w);
    k_pack_f2 <<<(NLAYER*FFND*DP + 255)/256, 256>>>(enc_f2w);
    k_stepM<<<(DD*DD + DD + 255)/256, 256>>>(lin1_w, lin1_b, lin2_w, lin2_b);

    for (int l = 0; l < NLAYER; l++){
        // QKV: [CT,128] @ [128,1920] -> fp16 (special full-K kernel)
        k_qkv<<<dim3(QKVP/QBN, CT/QBM), 256>>>(p_xh, p_wqkv + (size_t)l*DP*QKVP, p_qkv);

        // fused attention
        k_fattn<<<dim3(TT/FA_BQ, NB), 256, FA_SMEM>>>(p_qkv, p_att);

        // proj: y = x + att @ wm  (fp32 out)
        hgemm<3><<<dim3(2, CT/BM), 256>>>(
            p_att, p_wm + (size_t)l*ATTP*DP, p_y, nullptr, nullptr, p_x, DD,
            CT, DD, ATTP, ATTP, DP, DD);

        k_lnh<<<CT/8, 256>>>(p_y, ln1g + l*DD, ln1b + l*DD, p_xh);

        // ffn1: relu(xh @ f1 + b1) -> fp16
        hgemm<4><<<dim3(1, CT/BM), 256>>>(
            p_xh, p_f1 + (size_t)l*DP*FFND, nullptr, p_ffn, enc_f1b + l*FFND, nullptr, 0,
            CT, FFND, DP, DP, FFND, FFND);

        // ffn2: x = y + ffn @ f2 + b2 (fp32 out)
        hgemm<5><<<dim3(2, CT/BM), 256>>>(
            p_ffn, p_f2 + (size_t)l*FFND*DP, p_x, nullptr, enc_f2b + l*DD, p_y, DD,
            CT, DD, FFND, FFND, DP, DD);

        k_lnh<<<CT/8, 256>>>(p_x, ln2g + l*DD, ln2b + l*DD, p_xh);
    }

    // head: iterate 10 steps (fold already done in k_stepM)
    k_head<<<1, 1024, HEAD_SMEM>>>(p_x, out);
}

// round 15
// speedup vs baseline: 1.5492x; 1.0020x over previous
#include <cuda_runtime.h>
#include <cuda_fp16.h>
#include <math.h>

#define CC 32
#define TT 768
#define DD 100
#define HH 5
#define HIDG 60
#define FFND 64
#define NPREDK 10
#define LHID 200
#define NLAYER 3
#define CT (CC*TT)          // 24576
#define DP 128              // padded feature/head dim
#define QKVP (15*DP)        // 1920
#define ATTP (HH*DP)        // 640
#define NB (CC*HH)          // 160

// ---------------- device scratch ----------------
__device__ float g_h1[CT*DD];
__device__ float g_hid[CT*HIDG];
__device__ float g_hid2[CT*HIDG];
__device__ float g_x[CT*DD];
__device__ float g_y[CT*DD];
__device__ float g_M2[DD*DD];
__device__ float g_cvec[DD];

__device__ __half g_xh[CT*DP];
__device__ __half g_qkvh[(size_t)CT*QKVP];
__device__ __half g_atth[(size_t)CT*ATTP];   // pad cols stay zero (.bss)
__device__ __half g_ffnh[CT*FFND];
__device__ __half g_wqkv[NLAYER*DP*QKVP];
__device__ __half g_wm[NLAYER*ATTP*DP];
__device__ __half g_f1[NLAYER*DP*FFND];
__device__ __half g_f2[NLAYER*FFND*DP];

// ---------------- small helpers ----------------
__device__ __forceinline__ unsigned sptr(const void* p){
    return (unsigned)__cvta_generic_to_shared(p);
}
__device__ __forceinline__ void cpa16(unsigned dst, const void* src, int bytes){
    asm volatile("cp.async.cg.shared.global [%0], [%1], 16, %2;\n"
                 :: "r"(dst), "l"(src), "r"(bytes));
}
__device__ __forceinline__ void cp_commit(){ asm volatile("cp.async.commit_group;\n" ::: "memory"); }
__device__ __forceinline__ void cp_wait0(){ asm volatile("cp.async.wait_group 0;\n" ::: "memory"); }

__device__ __forceinline__ void ldsm4(unsigned& r0,unsigned& r1,unsigned& r2,unsigned& r3, unsigned a){
    asm volatile("ldmatrix.sync.aligned.m8n8.x4.shared.b16 {%0,%1,%2,%3}, [%4];\n"
        : "=r"(r0),"=r"(r1),"=r"(r2),"=r"(r3) : "r"(a));
}
__device__ __forceinline__ void ldsm4t(unsigned& r0,unsigned& r1,unsigned& r2,unsigned& r3, unsigned a){
    asm volatile("ldmatrix.sync.aligned.m8n8.x4.trans.shared.b16 {%0,%1,%2,%3}, [%4];\n"
        : "=r"(r0),"=r"(r1),"=r"(r2),"=r"(r3) : "r"(a));
}
__device__ __forceinline__ void mma16816(float* c, const unsigned* a, const unsigned* b){
    asm volatile("mma.sync.aligned.m16n8k16.row.col.f32.f16.f16.f32 "
        "{%0,%1,%2,%3}, {%4,%5,%6,%7}, {%8,%9}, {%0,%1,%2,%3};\n"
        : "+f"(c[0]),"+f"(c[1]),"+f"(c[2]),"+f"(c[3])
        : "r"(a[0]),"r"(a[1]),"r"(a[2]),"r"(a[3]), "r"(b[0]),"r"(b[1]));
}

// ---------------- fused flash attention (R10-proven) ----------------
#define FA_BQ 128
#define FA_BK 64
#define FA_DS 136
#define FA_SMEM ((FA_BQ + 4*FA_BK) * FA_DS * 2)

__global__ void __launch_bounds__(256, 1)
k_fattn(const __half* __restrict__ qkv, __half* __restrict__ att){
    extern __shared__ __align__(16) __half sm[];
    __half* Qs = sm;                       // [128][136]
    __half* Ks = Qs + FA_BQ*FA_DS;         // [2][64][136]
    __half* Vs = Ks + 2*FA_BK*FA_DS;       // [2][64][136]

    int tid = threadIdx.x, lane = tid & 31, w = tid >> 5;
    int qt = blockIdx.x;
    int z = blockIdx.y;
    int c = z / HH, h = z % HH;
    const __half* Qg = qkv + (size_t)c*TT*QKVP + h*DP;
    const __half* Kg = Qg + HH*DP;
    const __half* Vg = Qg + 2*HH*DP;

    #pragma unroll
    for (int i = 0; i < 8; i++){
        int idx = tid + i*256;
        int r = idx >> 4, cc2 = (idx & 15) * 8;
        cpa16(sptr(&Qs[r*FA_DS + cc2]), Qg + (size_t)(qt*FA_BQ + r)*QKVP + cc2, 16);
    }
    cp_commit();

    auto prefKV = [&](int kt, int buf){
        const __half* kb = Kg + (size_t)kt*FA_BK*QKVP;
        const __half* vb = Vg + (size_t)kt*FA_BK*QKVP;
        #pragma unroll
        for (int i = 0; i < 4; i++){
            int idx = tid + i*256;
            int r = idx >> 4, cc2 = (idx & 15) * 8;
            cpa16(sptr(&Ks[(buf*FA_BK + r)*FA_DS + cc2]), kb + (size_t)r*QKVP + cc2, 16);
        }
        #pragma unroll
        for (int i = 0; i < 4; i++){
            int idx = tid + i*256;
            int r = idx >> 4, cc2 = (idx & 15) * 8;
            cpa16(sptr(&Vs[(buf*FA_BK + r)*FA_DS + cc2]), vb + (size_t)r*QKVP + cc2, 16);
        }
    };
    prefKV(0, 0);
    cp_commit();
    cp_wait0();
    __syncthreads();

    unsigned qa[7][4];
    #pragma unroll
    for (int kk = 0; kk < 7; kk++){
        unsigned ad = sptr(&Qs[(w*16 + (lane & 15))*FA_DS + kk*16 + (lane >> 4)*8]);
        ldsm4(qa[kk][0], qa[kk][1], qa[kk][2], qa[kk][3], ad);
    }

    float o[14][4];
    #pragma unroll
    for (int i = 0; i < 14; i++){ o[i][0]=0.f; o[i][1]=0.f; o[i][2]=0.f; o[i][3]=0.f; }
    float rs0 = 0.f, rs1 = 0.f;

    for (int kt = 0; kt < TT/FA_BK; kt++){
        int buf = kt & 1;
        if (kt){
            cp_wait0();
            __syncthreads();
        }
        if (kt + 1 < TT/FA_BK) prefKV(kt + 1, buf ^ 1);
        cp_commit();

        float s[8][4];
        #pragma unroll
        for (int i = 0; i < 8; i++){ s[i][0]=0.f; s[i][1]=0.f; s[i][2]=0.f; s[i][3]=0.f; }
        #pragma unroll
        for (int ks = 0; ks < 7; ks++){
            unsigned kbf[8][2];
            #pragma unroll
            for (int np = 0; np < 4; np++){
                unsigned ad = sptr(&Ks[(buf*FA_BK + np*16 + (lane & 7) + ((lane >> 4) << 3))*FA_DS
                                        + ks*16 + ((lane >> 3) & 1)*8]);
                ldsm4(kbf[np*2][0], kbf[np*2][1], kbf[np*2+1][0], kbf[np*2+1][1], ad);
            }
            #pragma unroll
            for (int nt = 0; nt < 8; nt++)
                mma16816(s[nt], qa[ks], kbf[nt]);
        }

        // interleaved exp->pack per PV k-step (rowsum order preserved)
        #pragma unroll
        for (int ks = 0; ks < 4; ks++){
            unsigned paks[4];
            #pragma unroll
            for (int j = 0; j < 2; j++){
                int nt = 2*ks + j;
                __half2 h01 = __floats2half2_rn(__expf(s[nt][0]*0.1f), __expf(s[nt][1]*0.1f));
                __half2 h23 = __floats2half2_rn(__expf(s[nt][2]*0.1f), __expf(s[nt][3]*0.1f));
                paks[2*j]     = *(unsigned*)&h01;
                paks[2*j + 1] = *(unsigned*)&h23;
                float2 f01 = __half22float2(h01); rs0 += f01.x + f01.y;
                float2 f23 = __half22float2(h23); rs1 += f23.x + f23.y;
            }
            #pragma unroll
            for (int nt16 = 0; nt16 < 7; nt16++){
                unsigned b0[2], b1[2];
                unsigned ad = sptr(&Vs[(buf*FA_BK + ks*16 + (lane & 15))*FA_DS
                                        + nt16*16 + (lane >> 4)*8]);
                ldsm4t(b0[0], b0[1], b1[0], b1[1], ad);
                mma16816(o[nt16*2],     paks, b0);
                mma16816(o[nt16*2 + 1], paks, b1);
            }
        }
        __syncthreads();
    }

    rs0 += __shfl_xor_sync(0xffffffffu, rs0, 1);
    rs0 += __shfl_xor_sync(0xffffffffu, rs0, 2);
    rs1 += __shfl_xor_sync(0xffffffffu, rs1, 1);
    rs1 += __shfl_xor_sync(0xffffffffu, rs1, 2);
    float inv0 = 1.f / rs0, inv1 = 1.f / rs1;

    int row0 = qt*FA_BQ + w*16 + (lane >> 2);
    __half* o0 = att + ((size_t)c*TT + row0)*ATTP + h*DP;
    __half* o1 = o0 + 8*ATTP;
    #pragma unroll
    for (int nt = 0; nt < 13; nt++){
        int col = nt*8 + (lane & 3)*2;
        if (col <= 98){
            *(__half2*)(o0 + col) = __floats2half2_rn(o[nt][0]*inv0, o[nt][1]*inv0);
            *(__half2*)(o1 + col) = __floats2half2_rn(o[nt][2]*inv1, o[nt][3]*inv1);
        }
    }
}

// ---------------- QKV special GEMM: K=128 fully smem-resident, no pipeline ----------------
#define QBM 128
#define QBN 64
__global__ void __launch_bounds__(256)
k_qkv(const __half* __restrict__ A, const __half* __restrict__ B, __half* __restrict__ C){
    __shared__ __align__(16) __half As[QBM][DP+8];   // 128 x 136
    __shared__ __align__(16) __half Bs[DP][QBN+8];   // 128 x 72
    int tid = threadIdx.x;
    int m0 = blockIdx.y * QBM, n0 = blockIdx.x * QBN;
    int warp = tid >> 5, lane = tid & 31;
    int wm0 = (warp >> 1) * 32, wn0 = (warp & 1) * 32;

    #pragma unroll
    for (int i = 0; i < 8; i++){
        int idx = tid + i*256;
        int r = idx >> 4, cc = (idx & 15) * 8;
        cpa16(sptr(&As[r][cc]), A + (size_t)(m0 + r)*DP + cc, 16);
    }
    #pragma unroll
    for (int i = 0; i < 4; i++){
        int idx = tid + i*256;
        int r = idx >> 3, cc = (idx & 7) * 8;
        cpa16(sptr(&Bs[r][cc]), B + (size_t)r*QKVP + n0 + cc, 16);
    }
    cp_commit(); cp_wait0(); __syncthreads();

    float c[2][4][4];
    #pragma unroll
    for (int a=0;a<2;a++) for (int b=0;b<4;b++) for (int d=0;d<4;d++) c[a][b][d]=0.f;

    #pragma unroll
    for (int ks = 0; ks < 8; ks++){
        unsigned a[2][4], b[4][2];
        #pragma unroll
        for (int mt = 0; mt < 2; mt++){
            unsigned ad = sptr(&As[wm0 + mt*16 + (lane & 15)][ks*16 + (lane >> 4)*8]);
            ldsm4(a[mt][0], a[mt][1], a[mt][2], a[mt][3], ad);
        }
        #pragma unroll
        for (int np = 0; np < 2; np++){
            unsigned ad = sptr(&Bs[ks*16 + (lane & 15)][wn0 + np*16 + (lane >> 4)*8]);
            ldsm4t(b[np*2][0], b[np*2][1], b[np*2+1][0], b[np*2+1][1], ad);
        }
        #pragma unroll
        for (int mt = 0; mt < 2; mt++)
            #pragma unroll
            for (int nt = 0; nt < 4; nt++)
                mma16816(c[mt][nt], a[mt], b[nt]);
    }

    #pragma unroll
    for (int mt = 0; mt < 2; mt++){
        #pragma unroll
        for (int i = 0; i < 2; i++){
            int row = m0 + wm0 + mt*16 + (lane >> 2) + i*8;
            #pragma unroll
            for (int nt = 0; nt < 4; nt++){
                int col = n0 + wn0 + nt*8 + (lane & 3)*2;
                *(__half2*)(C + (size_t)row*QKVP + col) =
                    __floats2half2_rn(c[mt][nt][i*2+0], c[mt][nt][i*2+1]);
            }
        }
    }
}

// ---------------- fp16 tensor-core GEMM (generic, R5-proven) ----------------
// EPI: 3 f32 acc+res; 4 half(relu(acc+bias)); 5 f32 acc+bias+res
#define BM 128
#define BN 64
#define BKK 32

template<int EPI>
__global__ void __launch_bounds__(256)
hgemm(const __half* __restrict__ A, const __half* __restrict__ B,
      float* __restrict__ outF, __half* __restrict__ outH,
      const float* __restrict__ bias, const float* __restrict__ res, int ldr,
      int M, int N, int K, int lda, int ldb, int ldc)
{
    __shared__ __align__(16) __half As[2][BM][BKK+8];
    __shared__ __align__(16) __half Bs[2][BKK][BN+8];

    int tid = threadIdx.x;
    int m0 = blockIdx.y * BM, n0 = blockIdx.x * BN;
    int warp = tid >> 5, lane = tid & 31;
    int wm0 = (warp >> 1) * 32, wn0 = (warp & 1) * 32;

    float c[2][4][4];
    #pragma unroll
    for (int a=0;a<2;a++) for (int b=0;b<4;b++) for (int d=0;d<4;d++) c[a][b][d]=0.f;

    auto prefA = [&](int kt, int buf){
        int k0 = kt*BKK;
        #pragma unroll
        for (int i=0;i<2;i++){
            int q = tid + i*256;
            int r = q >> 2, cc = (q & 3) * 8;
            cpa16(sptr(&As[buf][r][cc]), A + (size_t)(m0+r)*lda + k0 + cc, 16);
        }
    };
    auto prefB = [&](int kt, int buf){
        int k0 = kt*BKK;
        int r = tid >> 3, cc = (tid & 7) * 8;
        int nrem = N - (n0 + cc);
        int bytes = nrem >= 8 ? 16 : (nrem > 0 ? nrem*2 : 0);
        const __half* src = bytes ? (B + (size_t)(k0+r)*ldb + n0 + cc) : B;
        cpa16(sptr(&Bs[buf][r][cc]), src, bytes);
    };

    int nk = K / BKK;
    prefA(0,0); prefB(0,0); cp_commit();

    for (int kt = 0; kt < nk; kt++){
        int buf = kt & 1;
        cp_wait0();
        __syncthreads();
        if (kt+1 < nk){ prefA(kt+1, buf^1); prefB(kt+1, buf^1); }
        cp_commit();

        #pragma unroll
        for (int ks = 0; ks < 2; ks++){
            unsigned a[2][4], b[4][2];
            #pragma unroll
            for (int mt = 0; mt < 2; mt++){
                unsigned ad = sptr(&As[buf][wm0 + mt*16 + (lane & 15)][ks*16 + (lane >> 4)*8]);
                ldsm4(a[mt][0], a[mt][1], a[mt][2], a[mt][3], ad);
            }
            #pragma unroll
            for (int np = 0; np < 2; np++){
                unsigned ad = sptr(&Bs[buf][ks*16 + (lane & 15)][wn0 + np*16 + (lane >> 4)*8]);
                ldsm4t(b[np*2][0], b[np*2][1], b[np*2+1][0], b[np*2+1][1], ad);
            }
            #pragma unroll
            for (int mt = 0; mt < 2; mt++)
                #pragma unroll
                for (int nt = 0; nt < 4; nt++)
                    mma16816(c[mt][nt], a[mt], b[nt]);
        }
        __syncthreads();
    }

    #pragma unroll
    for (int mt = 0; mt < 2; mt++){
        #pragma unroll
        for (int i = 0; i < 2; i++){
            int row = m0 + wm0 + mt*16 + (lane >> 2) + i*8;
            #pragma unroll
            for (int nt = 0; nt < 4; nt++){
                int col = n0 + wn0 + nt*8 + (lane & 3)*2;
                if (col >= N) continue;
                float v0 = c[mt][nt][i*2+0];
                float v1 = c[mt][nt][i*2+1];
                size_t off = (size_t)row*ldc + col;
                if (EPI == 3){
                    outF[off]   = v0 + res[(size_t)row*ldr + col];
                    outF[off+1] = v1 + res[(size_t)row*ldr + col + 1];
                } else if (EPI == 4){
                    *(__half2*)(outH + off) = __floats2half2_rn(fmaxf(v0 + bias[col], 0.f),
                                                                fmaxf(v1 + bias[col+1], 0.f));
                } else if (EPI == 5){
                    outF[off]   = v0 + bias[col]   + res[(size_t)row*ldr + col];
                    outF[off+1] = v1 + bias[col+1] + res[(size_t)row*ldr + col + 1];
                }
            }
        }
    }
}

// ---------------- weight packing ----------------
__global__ void k_pack_qkv(const float* __restrict__ wq, const float* __restrict__ wk,
                           const float* __restrict__ wv){
    int idx = blockIdx.x*256 + threadIdx.x;
    if (idx >= NLAYER*DP*QKVP) return;
    int l = idx / (DP*QKVP);
    int r = idx % (DP*QKVP);
    int k = r / QKVP, n = r % QKVP;
    int slot = n / DP, d = n % DP;
    int type = slot / HH, h = slot % HH;
    float v = 0.f;
    if (k < DD && d < DD){
        const float* w = type == 0 ? wq : (type == 1 ? wk : wv);
        v = w[(((size_t)l*HH + h)*DD + k)*DD + d];
    }
    g_wqkv[idx] = __float2half(v);
}

__global__ void k_pack_wm(const float* __restrict__ wm){
    int idx = blockIdx.x*256 + threadIdx.x;
    if (idx >= NLAYER*ATTP*DP) return;
    int l = idx / (ATTP*DP);
    int r = idx % (ATTP*DP);
    int k = r / DP, n = r % DP;
    int h = k / DP, dk = k % DP;
    float v = 0.f;
    if (dk < DD && n < DD)
        v = wm[((size_t)l*(HH*DD) + h*DD + dk)*DD + n];
    g_wm[idx] = __float2half(v);
}

__global__ void k_pack_f1(const float* __restrict__ f1){
    int idx = blockIdx.x*256 + threadIdx.x;
    if (idx >= NLAYER*DP*FFND) return;
    int l = idx / (DP*FFND);
    int r = idx % (DP*FFND);
    int k = r / FFND, n = r % FFND;
    g_f1[idx] = __float2half(k < DD ? f1[((size_t)l*DD + k)*FFND + n] : 0.f);
}

__global__ void k_pack_f2(const float* __restrict__ f2){
    int idx = blockIdx.x*256 + threadIdx.x;
    if (idx >= NLAYER*FFND*DP) return;
    int l = idx / (FFND*DP);
    int r = idx % (FFND*DP);
    int k = r / DP, n = r % DP;
    g_f2[idx] = __float2half(n < DD ? f2[((size_t)l*FFND + k)*DD + n] : 0.f);
}

// ---------------- layernorm (fp32 in-place) + fp16 padded output ----------------
__global__ void k_lnh(float* __restrict__ x, const float* __restrict__ g,
                      const float* __restrict__ b, __half* __restrict__ xh){
    int warp = threadIdx.x >> 5;
    int lane = threadIdx.x & 31;
    int row = blockIdx.x*8 + warp;
    if (row >= CT) return;
    float* xr = x + (size_t)row*DD;
    float v0 = xr[lane], v1 = xr[lane+32], v2 = xr[lane+64];
    float v3 = (lane + 96 < DD) ? xr[lane+96] : 0.f;
    float s = v0 + v1 + v2 + v3;
    #pragma unroll
    for (int o = 16; o; o >>= 1) s += __shfl_xor_sync(0xffffffffu, s, o);
    float mean = s * (1.f/DD);
    float d0 = v0-mean, d1 = v1-mean, d2 = v2-mean;
    float d3 = (lane + 96 < DD) ? (v3 - mean) : 0.f;
    float vs = d0*d0 + d1*d1 + d2*d2 + d3*d3;
    #pragma unroll
    for (int o = 16; o; o >>= 1) vs += __shfl_xor_sync(0xffffffffu, vs, o);
    float inv = rsqrtf(vs * (1.f/DD) + 1e-5f);
    __half* hr = xh + (size_t)row*DP;
    float w;
    w = d0*inv*g[lane]    + b[lane];    xr[lane]    = w; hr[lane]    = __float2half(w);
    w = d1*inv*g[lane+32] + b[lane+32]; xr[lane+32] = w; hr[lane+32] = __float2half(w);
    w = d2*inv*g[lane+64] + b[lane+64]; xr[lane+64] = w; hr[lane+64] = __float2half(w);
    if (lane + 96 < DD){
        w = d3*inv*g[lane+96] + b[lane+96]; xr[lane+96] = w; hr[lane+96] = __float2half(w);
    } else {
        hr[96 + lane] = __half(0.f);
    }
}

// ---------------- GCN ----------------
// adjacency normalization folded in: threads 0..31 compute row i with the same
// sequential j-loop as the old k_adj -> bit-identical sadj
__global__ void k_agg(const float* __restrict__ A, const float* __restrict__ in,
                      float* __restrict__ out, int TD){
    __shared__ float sadj[CC*CC];
    int tid = threadIdx.x;
    if (tid < CC){
        int i = tid;
        float s = 0.f;
        for (int j = 0; j < CC; j++) s += A[i*CC + j] + (i == j ? 1.f : 0.f);
        float inv = 1.f / s;
        for (int j = 0; j < CC; j++)
            sadj[i*CC + j] = (A[i*CC + j] + (i == j ? 1.f : 0.f)) * inv;
    }
    __syncthreads();
    int n = blockIdx.x*256 + tid;
    if (n >= TD) return;
    float v[CC];
    #pragma unroll
    for (int j = 0; j < CC; j++) v[j] = in[(size_t)j*TD + n];
    #pragma unroll
    for (int i = 0; i < CC; i++){
        float acc = 0.f;
        #pragma unroll
        for (int j = 0; j < CC; j++) acc += sadj[i*CC + j] * v[j];
        out[(size_t)i*TD + n] = acc;
    }
}

// fp32 GEMM for GCN; TOH also writes half to g_xh (padded 128-stride)
template<int RELU, int HASB, int TOH>
__global__ void __launch_bounds__(256)
k_gemm(const float* __restrict__ A, const float* __restrict__ B,
       const float* __restrict__ bias, float* __restrict__ C, int M, int N, int K){
    __shared__ __align__(16) float As[16][64];
    __shared__ __align__(16) float Bs[16][64];
    int tid = threadIdx.x;
    int tx = tid & 15, ty = tid >> 4;
    int m0 = blockIdx.y * 64, n0 = blockIdx.x * 64;
    float acc[4][4] = {};
    int nk = (K + 15) >> 4;
    for (int kt = 0; kt < nk; kt++){
        int k0 = kt * 16;
        {
            int r = tid >> 2; int kc = (tid & 3) * 4;
            int grow = m0 + r;
            #pragma unroll
            for (int i = 0; i < 4; i++){
                int kk = k0 + kc + i;
                As[kc + i][r] = (grow < M && kk < K) ? A[(size_t)grow*K + kk] : 0.f;
            }
        }
        {
            int kr = tid >> 4; int nc = (tid & 15) * 4;
            int gk = k0 + kr;
            #pragma unroll
            for (int i = 0; i < 4; i++){
                int gn = n0 + nc + i;
                Bs[kr][nc + i] = (gk < K && gn < N) ? B[(size_t)gk*N + gn] : 0.f;
            }
        }
        __syncthreads();
        #pragma unroll
        for (int kc = 0; kc < 16; kc++){
            float4 a4 = *(const float4*)&As[kc][ty*4];
            float4 b4 = *(const float4*)&Bs[kc][tx*4];
            float av[4] = {a4.x, a4.y, a4.z, a4.w};
            float bv[4] = {b4.x, b4.y, b4.z, b4.w};
            #pragma unroll
            for (int j = 0; j < 4; j++)
                #pragma unroll
                for (int i = 0; i < 4; i++)
                    acc[j][i] += av[j] * bv[i];
        }
        __syncthreads();
    }
    #pragma unroll
    for (int j = 0; j < 4; j++){
        int row = m0 + ty*4 + j;
        if (row >= M) continue;
        #pragma unroll
        for (int i = 0; i < 4; i++){
            int col = n0 + tx*4 + i;
            if (col >= N) continue;
            float v = acc[j][i];
            if (HASB) v += bias[col];
            if (RELU) v = fmaxf(v, 0.f);
            C[(size_t)row*N + col] = v;
            if (TOH) g_xh[(size_t)row*DP + col] = __float2half(v);
        }
    }
}

// ---------------- prediction head ----------------
__global__ void k_stepM(const float* __restrict__ l1, const float* __restrict__ l1b,
                        const float* __restrict__ l2, const float* __restrict__ l2b){
    int idx = blockIdx.x * blockDim.x + threadIdx.x;
    if (idx < DD*DD){
        int e = idx / DD, d = idx % DD;
        float acc = 0.f;
        for (int r = 0; r < LHID; r++)
            acc += l1[e*LHID + r] * l2[r*DD + d];
        g_M2[idx] = acc;
    } else if (idx < DD*DD + DD){
        int d = idx - DD*DD;
        float acc = l2b[d];
        for (int r = 0; r < LHID; r++)
            acc += l1b[r] * l2[r*DD + d];
        g_cvec[d] = acc;
    }
}

#define HEAD_SMEM ((DD*DD + DD + CC*DD) * (int)sizeof(float))
__global__ void __launch_bounds__(1024)
k_head(const float* __restrict__ x, float* __restrict__ out){
    extern __shared__ float hs[];
    float* sM2 = hs;
    float* scv = sM2 + DD*DD;
    float* scr = scv + DD;
    int tid = threadIdx.x;
    for (int q = tid; q < DD*DD; q += 1024) sM2[q] = g_M2[q];
    if (tid < DD) scv[tid] = g_cvec[tid];
    for (int q = tid; q < CC*DD; q += 1024){
        int c = q / DD, d = q % DD;
        scr[q] = x[((size_t)c*TT + TT - 1)*DD + d];
    }
    __syncthreads();
    for (int k = 0; k < NPREDK; k++){
        float rv[4];
        int cnt = 0;
        for (int q = tid; q < CC*DD; q += 1024){
            int c = q / DD, d = q % DD;
            float acc = scv[d];
            const float* cr = scr + c*DD;
            #pragma unroll 4
            for (int e = 0; e < DD; e++)
                acc += cr[e] * sM2[e*DD + d];
            rv[cnt++] = acc;
        }
        __syncthreads();
        cnt = 0;
        for (int q = tid; q < CC*DD; q += 1024){
            int c = q / DD, d = q % DD;
            scr[q] = rv[cnt];
            out[((size_t)c*NPREDK + k)*DD + d] = rv[cnt];
            cnt++;
        }
        __syncthreads();
    }
}

// ---------------- host orchestration ----------------
static float* symF(const void* s){ void* p = nullptr; cudaGetSymbolAddress(&p, s); return (float*)p; }
static __half* symH(const void* s){ void* p = nullptr; cudaGetSymbolAddress(&p, s); return (__half*)p; }

extern "C" void kernel_launch(void* const* d_in, const int* in_sizes, int n_in,
                              void* d_out, int out_size){
    const float* X      = (const float*)d_in[0];
    const float* A      = (const float*)d_in[1];
    const float* gcn_w1 = (const float*)d_in[2];
    const float* gcn_b1 = (const float*)d_in[3];
    const float* gcn_w2 = (const float*)d_in[4];
    const float* gcn_b2 = (const float*)d_in[5];
    const float* enc_wq = (const float*)d_in[6];
    const float* enc_wk = (const float*)d_in[7];
    const float* enc_wv = (const float*)d_in[8];
    const float* enc_wm = (const float*)d_in[9];
    const float* enc_f1w= (const float*)d_in[10];
    const float* enc_f1b= (const float*)d_in[11];
    const float* enc_f2w= (const float*)d_in[12];
    const float* enc_f2b= (const float*)d_in[13];
    const float* ln1g   = (const float*)d_in[14];
    const float* ln1b   = (const float*)d_in[15];
    const float* ln2g   = (const float*)d_in[16];
    const float* ln2b   = (const float*)d_in[17];
    const float* lin1_w = (const float*)d_in[18];
    const float* lin1_b = (const float*)d_in[19];
    const float* lin2_w = (const float*)d_in[20];
    const float* lin2_b = (const float*)d_in[21];
    float* out = (float*)d_out;

    float*  p_h1   = symF(g_h1);
    float*  p_hid  = symF(g_hid);
    float*  p_hid2 = symF(g_hid2);
    float*  p_x    = symF(g_x);
    float*  p_y    = symF(g_y);
    __half* p_xh   = symH(g_xh);
    __half* p_qkv  = symH(g_qkvh);
    __half* p_att  = symH(g_atth);
    __half* p_ffn  = symH(g_ffnh);
    __half* p_wqkv = symH(g_wqkv);
    __half* p_wm   = symH(g_wm);
    __half* p_f1   = symH(g_f1);
    __half* p_f2   = symH(g_f2);

    cudaFuncSetAttribute(k_fattn, cudaFuncAttributeMaxDynamicSharedMemorySize, FA_SMEM);
    cudaFuncSetAttribute(k_head,  cudaFuncAttributeMaxDynamicSharedMemorySize, HEAD_SMEM);

    // GCN (fp32); adj normalization folded into k_agg; final gemm emits fp16 xh
    k_agg<<<(TT*DD + 255)/256, 256>>>(A, X, p_h1, TT*DD);
    k_gemm<1,1,0><<<dim3(1, CT/64), 256>>>(p_h1, gcn_w1, gcn_b1, p_hid, CT, HIDG, DD);
    k_agg<<<(TT*HIDG + 255)/256, 256>>>(A, p_hid, p_hid2, TT*HIDG);
    k_gemm<0,1,1><<<dim3(2, CT/64), 256>>>(p_hid2, gcn_w2, gcn_b2, p_x, CT, DD, HIDG);

    // pack weights fp16 (all layers); fold head affine (multi-CTA)
    k_pack_qkv<<<(NLAYER*DP*QKVP + 255)/256, 256>>>(enc_wq, enc_wk, enc_wv);
    k_pack_wm <<<(NLAYER*ATTP*DP + 255)/256, 256>>>(enc_wm);
    k_pack_f1 <<<(NLAYER*DP*FFND + 255)/256, 256>>>(enc_f1w);
    k_pack_f2 <<<(NLAYER*FFND*DP + 255)/256, 256>>>(enc_f2w);
    k_stepM<<<(DD*DD + DD + 255)/256, 256>>>(lin1_w, lin1_b, lin2_w, lin2_b);

    for (int l = 0; l < NLAYER; l++){
        // QKV: [CT,128] @ [128,1920] -> fp16 (special full-K kernel)
        k_qkv<<<dim3(QKVP/QBN, CT/QBM), 256>>>(p_xh, p_wqkv + (size_t)l*DP*QKVP, p_qkv);

        // fused attention
        k_fattn<<<dim3(TT/FA_BQ, NB), 256, FA_SMEM>>>(p_qkv, p_att);

        // proj: y = x + att @ wm  (fp32 out)
        hgemm<3><<<dim3(2, CT/BM), 256>>>(
            p_att, p_wm + (size_t)l*ATTP*DP, p_y, nullptr, nullptr, p_x, DD,
            CT, DD, ATTP, ATTP, DP, DD);

        k_lnh<<<CT/8, 256>>>(p_y, ln1g + l*DD, ln1b + l*DD, p_xh);

        // ffn1: relu(xh @ f1 + b1) -> fp16
        hgemm<4><<<dim3(1, CT/BM), 256>>>(
            p_xh, p_f1 + (size_t)l*DP*FFND, nullptr, p_ffn, enc_f1b + l*FFND, nullptr, 0,
            CT, FFND, DP, DP, FFND, FFND);

        // ffn2: x = y + ffn @ f2 + b2 (fp32 out)
        hgemm<5><<<dim3(2, CT/BM), 256>>>(
            p_ffn, p_f2 + (size_t)l*FFND*DP, p_x, nullptr, enc_f2b + l*DD, p_y, DD,
            CT, DD, FFND, FFND, DP, DD);

        k_lnh<<<CT/8, 256>>>(p_x, ln2g + l*DD, ln2b + l*DD, p_xh);
    }

    // head: iterate 10 steps (fold already done in k_stepM)
    k_head<<<1, 1024, HEAD_SMEM>>>(p_x, out);
}

// round 16
// speedup vs baseline: 1.5849x; 1.0230x over previous
#include <cuda_runtime.h>
#include <cuda_fp16.h>
#include <math.h>

#define CC 32
#define TT 768
#define DD 100
#define HH 5
#define HIDG 60
#define FFND 64
#define NPREDK 10
#define LHID 200
#define NLAYER 3
#define CT (CC*TT)          // 24576
#define DP 128              // padded feature/head dim
#define QKVP (15*DP)        // 1920
#define ATTP (HH*DP)        // 640
#define NB (CC*HH)          // 160

// ---------------- device scratch ----------------
__device__ float g_u[CT*DD];
__device__ float g_x[CT*DD];
__device__ float g_y[CT*DD];
__device__ float g_M2[DD*DD];
__device__ float g_cvec[DD];

__device__ __half g_h1h[CT*DP];      // agg(X) fp16, pads 100..127 stay zero (.bss)
__device__ __half g_th[CT*64];       // relu GCN hidden, pads 60..63 stay zero
__device__ __half g_xh[CT*DP];
__device__ __half g_qkvh[(size_t)CT*QKVP];
__device__ __half g_atth[(size_t)CT*ATTP];   // pad cols stay zero (.bss)
__device__ __half g_ffnh[CT*FFND];
__device__ __half g_wqkv[NLAYER*DP*QKVP];
__device__ __half g_wm[NLAYER*ATTP*DP];
__device__ __half g_f1[NLAYER*DP*FFND];
__device__ __half g_f2[NLAYER*FFND*DP];
__device__ __half g_w1h[DP*64];      // gcn_w1 padded [128][64]
__device__ __half g_w2h[64*104];     // gcn_w2 padded [64][104]

// ---------------- small helpers ----------------
__device__ __forceinline__ unsigned sptr(const void* p){
    return (unsigned)__cvta_generic_to_shared(p);
}
__device__ __forceinline__ void cpa16(unsigned dst, const void* src, int bytes){
    asm volatile("cp.async.cg.shared.global [%0], [%1], 16, %2;\n"
                 :: "r"(dst), "l"(src), "r"(bytes));
}
__device__ __forceinline__ void cp_commit(){ asm volatile("cp.async.commit_group;\n" ::: "memory"); }
__device__ __forceinline__ void cp_wait0(){ asm volatile("cp.async.wait_group 0;\n" ::: "memory"); }

__device__ __forceinline__ void ldsm4(unsigned& r0,unsigned& r1,unsigned& r2,unsigned& r3, unsigned a){
    asm volatile("ldmatrix.sync.aligned.m8n8.x4.shared.b16 {%0,%1,%2,%3}, [%4];\n"
        : "=r"(r0),"=r"(r1),"=r"(r2),"=r"(r3) : "r"(a));
}
__device__ __forceinline__ void ldsm4t(unsigned& r0,unsigned& r1,unsigned& r2,unsigned& r3, unsigned a){
    asm volatile("ldmatrix.sync.aligned.m8n8.x4.trans.shared.b16 {%0,%1,%2,%3}, [%4];\n"
        : "=r"(r0),"=r"(r1),"=r"(r2),"=r"(r3) : "r"(a));
}
__device__ __forceinline__ void mma16816(float* c, const unsigned* a, const unsigned* b){
    asm volatile("mma.sync.aligned.m16n8k16.row.col.f32.f16.f16.f32 "
        "{%0,%1,%2,%3}, {%4,%5,%6,%7}, {%8,%9}, {%0,%1,%2,%3};\n"
        : "+f"(c[0]),"+f"(c[1]),"+f"(c[2]),"+f"(c[3])
        : "r"(a[0]),"r"(a[1]),"r"(a[2]),"r"(a[3]), "r"(b[0]),"r"(b[1]));
}

// ---------------- fused flash attention (R10-proven) ----------------
#define FA_BQ 128
#define FA_BK 64
#define FA_DS 136
#define FA_SMEM ((FA_BQ + 4*FA_BK) * FA_DS * 2)

__global__ void __launch_bounds__(256, 1)
k_fattn(const __half* __restrict__ qkv, __half* __restrict__ att){
    extern __shared__ __align__(16) __half sm[];
    __half* Qs = sm;                       // [128][136]
    __half* Ks = Qs + FA_BQ*FA_DS;         // [2][64][136]
    __half* Vs = Ks + 2*FA_BK*FA_DS;       // [2][64][136]

    int tid = threadIdx.x, lane = tid & 31, w = tid >> 5;
    int qt = blockIdx.x;
    int z = blockIdx.y;
    int c = z / HH, h = z % HH;
    const __half* Qg = qkv + (size_t)c*TT*QKVP + h*DP;
    const __half* Kg = Qg + HH*DP;
    const __half* Vg = Qg + 2*HH*DP;

    #pragma unroll
    for (int i = 0; i < 8; i++){
        int idx = tid + i*256;
        int r = idx >> 4, cc2 = (idx & 15) * 8;
        cpa16(sptr(&Qs[r*FA_DS + cc2]), Qg + (size_t)(qt*FA_BQ + r)*QKVP + cc2, 16);
    }
    cp_commit();

    auto prefKV = [&](int kt, int buf){
        const __half* kb = Kg + (size_t)kt*FA_BK*QKVP;
        const __half* vb = Vg + (size_t)kt*FA_BK*QKVP;
        #pragma unroll
        for (int i = 0; i < 4; i++){
            int idx = tid + i*256;
            int r = idx >> 4, cc2 = (idx & 15) * 8;
            cpa16(sptr(&Ks[(buf*FA_BK + r)*FA_DS + cc2]), kb + (size_t)r*QKVP + cc2, 16);
        }
        #pragma unroll
        for (int i = 0; i < 4; i++){
            int idx = tid + i*256;
            int r = idx >> 4, cc2 = (idx & 15) * 8;
            cpa16(sptr(&Vs[(buf*FA_BK + r)*FA_DS + cc2]), vb + (size_t)r*QKVP + cc2, 16);
        }
    };
    prefKV(0, 0);
    cp_commit();
    cp_wait0();
    __syncthreads();

    unsigned qa[7][4];
    #pragma unroll
    for (int kk = 0; kk < 7; kk++){
        unsigned ad = sptr(&Qs[(w*16 + (lane & 15))*FA_DS + kk*16 + (lane >> 4)*8]);
        ldsm4(qa[kk][0], qa[kk][1], qa[kk][2], qa[kk][3], ad);
    }

    float o[14][4];
    #pragma unroll
    for (int i = 0; i < 14; i++){ o[i][0]=0.f; o[i][1]=0.f; o[i][2]=0.f; o[i][3]=0.f; }
    float rs0 = 0.f, rs1 = 0.f;

    for (int kt = 0; kt < TT/FA_BK; kt++){
        int buf = kt & 1;
        if (kt){
            cp_wait0();
            __syncthreads();
        }
        if (kt + 1 < TT/FA_BK) prefKV(kt + 1, buf ^ 1);
        cp_commit();

        float s[8][4];
        #pragma unroll
        for (int i = 0; i < 8; i++){ s[i][0]=0.f; s[i][1]=0.f; s[i][2]=0.f; s[i][3]=0.f; }
        #pragma unroll
        for (int ks = 0; ks < 7; ks++){
            unsigned kbf[8][2];
            #pragma unroll
            for (int np = 0; np < 4; np++){
                unsigned ad = sptr(&Ks[(buf*FA_BK + np*16 + (lane & 7) + ((lane >> 4) << 3))*FA_DS
                                        + ks*16 + ((lane >> 3) & 1)*8]);
                ldsm4(kbf[np*2][0], kbf[np*2][1], kbf[np*2+1][0], kbf[np*2+1][1], ad);
            }
            #pragma unroll
            for (int nt = 0; nt < 8; nt++)
                mma16816(s[nt], qa[ks], kbf[nt]);
        }

        // interleaved exp->pack per PV k-step (rowsum order preserved)
        #pragma unroll
        for (int ks = 0; ks < 4; ks++){
            unsigned paks[4];
            #pragma unroll
            for (int j = 0; j < 2; j++){
                int nt = 2*ks + j;
                __half2 h01 = __floats2half2_rn(__expf(s[nt][0]*0.1f), __expf(s[nt][1]*0.1f));
                __half2 h23 = __floats2half2_rn(__expf(s[nt][2]*0.1f), __expf(s[nt][3]*0.1f));
                paks[2*j]     = *(unsigned*)&h01;
                paks[2*j + 1] = *(unsigned*)&h23;
                float2 f01 = __half22float2(h01); rs0 += f01.x + f01.y;
                float2 f23 = __half22float2(h23); rs1 += f23.x + f23.y;
            }
            #pragma unroll
            for (int nt16 = 0; nt16 < 7; nt16++){
                unsigned b0[2], b1[2];
                unsigned ad = sptr(&Vs[(buf*FA_BK + ks*16 + (lane & 15))*FA_DS
                                        + nt16*16 + (lane >> 4)*8]);
                ldsm4t(b0[0], b0[1], b1[0], b1[1], ad);
                mma16816(o[nt16*2],     paks, b0);
                mma16816(o[nt16*2 + 1], paks, b1);
            }
        }
        __syncthreads();
    }

    rs0 += __shfl_xor_sync(0xffffffffu, rs0, 1);
    rs0 += __shfl_xor_sync(0xffffffffu, rs0, 2);
    rs1 += __shfl_xor_sync(0xffffffffu, rs1, 1);
    rs1 += __shfl_xor_sync(0xffffffffu, rs1, 2);
    float inv0 = 1.f / rs0, inv1 = 1.f / rs1;

    int row0 = qt*FA_BQ + w*16 + (lane >> 2);
    __half* o0 = att + ((size_t)c*TT + row0)*ATTP + h*DP;
    __half* o1 = o0 + 8*ATTP;
    #pragma unroll
    for (int nt = 0; nt < 13; nt++){
        int col = nt*8 + (lane & 3)*2;
        if (col <= 98){
            *(__half2*)(o0 + col) = __floats2half2_rn(o[nt][0]*inv0, o[nt][1]*inv0);
            *(__half2*)(o1 + col) = __floats2half2_rn(o[nt][2]*inv1, o[nt][3]*inv1);
        }
    }
}

// ---------------- QKV special GEMM: K=128 fully smem-resident, no pipeline ----------------
#define QBM 128
#define QBN 64
__global__ void __launch_bounds__(256)
k_qkv(const __half* __restrict__ A, const __half* __restrict__ B, __half* __restrict__ C){
    __shared__ __align__(16) __half As[QBM][DP+8];   // 128 x 136
    __shared__ __align__(16) __half Bs[DP][QBN+8];   // 128 x 72
    int tid = threadIdx.x;
    int m0 = blockIdx.y * QBM, n0 = blockIdx.x * QBN;
    int warp = tid >> 5, lane = tid & 31;
    int wm0 = (warp >> 1) * 32, wn0 = (warp & 1) * 32;

    #pragma unroll
    for (int i = 0; i < 8; i++){
        int idx = tid + i*256;
        int r = idx >> 4, cc = (idx & 15) * 8;
        cpa16(sptr(&As[r][cc]), A + (size_t)(m0 + r)*DP + cc, 16);
    }
    #pragma unroll
    for (int i = 0; i < 4; i++){
        int idx = tid + i*256;
        int r = idx >> 3, cc = (idx & 7) * 8;
        cpa16(sptr(&Bs[r][cc]), B + (size_t)r*QKVP + n0 + cc, 16);
    }
    cp_commit(); cp_wait0(); __syncthreads();

    float c[2][4][4];
    #pragma unroll
    for (int a=0;a<2;a++) for (int b=0;b<4;b++) for (int d=0;d<4;d++) c[a][b][d]=0.f;

    #pragma unroll
    for (int ks = 0; ks < 8; ks++){
        unsigned a[2][4], b[4][2];
        #pragma unroll
        for (int mt = 0; mt < 2; mt++){
            unsigned ad = sptr(&As[wm0 + mt*16 + (lane & 15)][ks*16 + (lane >> 4)*8]);
            ldsm4(a[mt][0], a[mt][1], a[mt][2], a[mt][3], ad);
        }
        #pragma unroll
        for (int np = 0; np < 2; np++){
            unsigned ad = sptr(&Bs[ks*16 + (lane & 15)][wn0 + np*16 + (lane >> 4)*8]);
            ldsm4t(b[np*2][0], b[np*2][1], b[np*2+1][0], b[np*2+1][1], ad);
        }
        #pragma unroll
        for (int mt = 0; mt < 2; mt++)
            #pragma unroll
            for (int nt = 0; nt < 4; nt++)
                mma16816(c[mt][nt], a[mt], b[nt]);
    }

    #pragma unroll
    for (int mt = 0; mt < 2; mt++){
        #pragma unroll
        for (int i = 0; i < 2; i++){
            int row = m0 + wm0 + mt*16 + (lane >> 2) + i*8;
            #pragma unroll
            for (int nt = 0; nt < 4; nt++){
                int col = n0 + wn0 + nt*8 + (lane & 3)*2;
                *(__half2*)(C + (size_t)row*QKVP + col) =
                    __floats2half2_rn(c[mt][nt][i*2+0], c[mt][nt][i*2+1]);
            }
        }
    }
}

// ---------------- fp16 tensor-core GEMM (generic) ----------------
// EPI: 3 f32 acc+res; 4 half(relu(acc+bias)); 5 f32 acc+bias+res; 6 f32 acc+bias
#define BM 128
#define BN 64
#define BKK 32

template<int EPI>
__global__ void __launch_bounds__(256)
hgemm(const __half* __restrict__ A, const __half* __restrict__ B,
      float* __restrict__ outF, __half* __restrict__ outH,
      const float* __restrict__ bias, const float* __restrict__ res, int ldr,
      int M, int N, int K, int lda, int ldb, int ldc)
{
    __shared__ __align__(16) __half As[2][BM][BKK+8];
    __shared__ __align__(16) __half Bs[2][BKK][BN+8];

    int tid = threadIdx.x;
    int m0 = blockIdx.y * BM, n0 = blockIdx.x * BN;
    int warp = tid >> 5, lane = tid & 31;
    int wm0 = (warp >> 1) * 32, wn0 = (warp & 1) * 32;

    float c[2][4][4];
    #pragma unroll
    for (int a=0;a<2;a++) for (int b=0;b<4;b++) for (int d=0;d<4;d++) c[a][b][d]=0.f;

    auto prefA = [&](int kt, int buf){
        int k0 = kt*BKK;
        #pragma unroll
        for (int i=0;i<2;i++){
            int q = tid + i*256;
            int r = q >> 2, cc = (q & 3) * 8;
            cpa16(sptr(&As[buf][r][cc]), A + (size_t)(m0+r)*lda + k0 + cc, 16);
        }
    };
    auto prefB = [&](int kt, int buf){
        int k0 = kt*BKK;
        int r = tid >> 3, cc = (tid & 7) * 8;
        int nrem = N - (n0 + cc);
        int bytes = nrem >= 8 ? 16 : (nrem > 0 ? nrem*2 : 0);
        const __half* src = bytes ? (B + (size_t)(k0+r)*ldb + n0 + cc) : B;
        cpa16(sptr(&Bs[buf][r][cc]), src, bytes);
    };

    int nk = K / BKK;
    prefA(0,0); prefB(0,0); cp_commit();

    for (int kt = 0; kt < nk; kt++){
        int buf = kt & 1;
        cp_wait0();
        __syncthreads();
        if (kt+1 < nk){ prefA(kt+1, buf^1); prefB(kt+1, buf^1); }
        cp_commit();

        #pragma unroll
        for (int ks = 0; ks < 2; ks++){
            unsigned a[2][4], b[4][2];
            #pragma unroll
            for (int mt = 0; mt < 2; mt++){
                unsigned ad = sptr(&As[buf][wm0 + mt*16 + (lane & 15)][ks*16 + (lane >> 4)*8]);
                ldsm4(a[mt][0], a[mt][1], a[mt][2], a[mt][3], ad);
            }
            #pragma unroll
            for (int np = 0; np < 2; np++){
                unsigned ad = sptr(&Bs[buf][ks*16 + (lane & 15)][wn0 + np*16 + (lane >> 4)*8]);
                ldsm4t(b[np*2][0], b[np*2][1], b[np*2+1][0], b[np*2+1][1], ad);
            }
            #pragma unroll
            for (int mt = 0; mt < 2; mt++)
                #pragma unroll
                for (int nt = 0; nt < 4; nt++)
                    mma16816(c[mt][nt], a[mt], b[nt]);
        }
        __syncthreads();
    }

    #pragma unroll
    for (int mt = 0; mt < 2; mt++){
        #pragma unroll
        for (int i = 0; i < 2; i++){
            int row = m0 + wm0 + mt*16 + (lane >> 2) + i*8;
            #pragma unroll
            for (int nt = 0; nt < 4; nt++){
                int col = n0 + wn0 + nt*8 + (lane & 3)*2;
                if (col >= N) continue;
                float v0 = c[mt][nt][i*2+0];
                float v1 = c[mt][nt][i*2+1];
                size_t off = (size_t)row*ldc + col;
                if (EPI == 3){
                    outF[off]   = v0 + res[(size_t)row*ldr + col];
                    outF[off+1] = v1 + res[(size_t)row*ldr + col + 1];
                } else if (EPI == 4){
                    *(__half2*)(outH + off) = __floats2half2_rn(fmaxf(v0 + bias[col], 0.f),
                                                                fmaxf(v1 + bias[col+1], 0.f));
                } else if (EPI == 5){
                    outF[off]   = v0 + bias[col]   + res[(size_t)row*ldr + col];
                    outF[off+1] = v1 + bias[col+1] + res[(size_t)row*ldr + col + 1];
                } else if (EPI == 6){
                    outF[off]   = v0 + bias[col];
                    outF[off+1] = v1 + bias[col+1];
                }
            }
        }
    }
}

// ---------------- weight packing ----------------
__global__ void k_pack_qkv(const float* __restrict__ wq, const float* __restrict__ wk,
                           const float* __restrict__ wv){
    int idx = blockIdx.x*256 + threadIdx.x;
    if (idx >= NLAYER*DP*QKVP) return;
    int l = idx / (DP*QKVP);
    int r = idx % (DP*QKVP);
    int k = r / QKVP, n = r % QKVP;
    int slot = n / DP, d = n % DP;
    int type = slot / HH, h = slot % HH;
    float v = 0.f;
    if (k < DD && d < DD){
        const float* w = type == 0 ? wq : (type == 1 ? wk : wv);
        v = w[(((size_t)l*HH + h)*DD + k)*DD + d];
    }
    g_wqkv[idx] = __float2half(v);
}

__global__ void k_pack_wm(const float* __restrict__ wm){
    int idx = blockIdx.x*256 + threadIdx.x;
    if (idx >= NLAYER*ATTP*DP) return;
    int l = idx / (ATTP*DP);
    int r = idx % (ATTP*DP);
    int k = r / DP, n = r % DP;
    int h = k / DP, dk = k % DP;
    float v = 0.f;
    if (dk < DD && n < DD)
        v = wm[((size_t)l*(HH*DD) + h*DD + dk)*DD + n];
    g_wm[idx] = __float2half(v);
}

__global__ void k_pack_f1(const float* __restrict__ f1){
    int idx = blockIdx.x*256 + threadIdx.x;
    if (idx >= NLAYER*DP*FFND) return;
    int l = idx / (DP*FFND);
    int r = idx % (DP*FFND);
    int k = r / FFND, n = r % FFND;
    g_f1[idx] = __float2half(k < DD ? f1[((size_t)l*DD + k)*FFND + n] : 0.f);
}

__global__ void k_pack_f2(const float* __restrict__ f2){
    int idx = blockIdx.x*256 + threadIdx.x;
    if (idx >= NLAYER*FFND*DP) return;
    int l = idx / (FFND*DP);
    int r = idx % (FFND*DP);
    int k = r / DP, n = r % DP;
    g_f2[idx] = __float2half(n < DD ? f2[((size_t)l*FFND + k)*DD + n] : 0.f);
}

// GCN weight packs: w1 -> [128][64], w2 -> [64][104] (zero-padded)
__global__ void k_pack_w1(const float* __restrict__ w1){
    int idx = blockIdx.x*256 + threadIdx.x;
    if (idx >= DP*64) return;
    int k = idx / 64, n = idx % 64;
    g_w1h[idx] = __float2half((k < DD && n < HIDG) ? w1[k*HIDG + n] : 0.f);
}
__global__ void k_pack_w2(const float* __restrict__ w2){
    int idx = blockIdx.x*256 + threadIdx.x;
    if (idx >= 64*104) return;
    int k = idx / 104, n = idx % 104;
    g_w2h[idx] = __float2half((k < HIDG && n < DD) ? w2[k*DD + n] : 0.f);
}

// ---------------- layernorm (fp32 in-place) + fp16 padded output ----------------
__global__ void k_lnh(float* __restrict__ x, const float* __restrict__ g,
                      const float* __restrict__ b, __half* __restrict__ xh){
    int warp = threadIdx.x >> 5;
    int lane = threadIdx.x & 31;
    int row = blockIdx.x*8 + warp;
    if (row >= CT) return;
    float* xr = x + (size_t)row*DD;
    float v0 = xr[lane], v1 = xr[lane+32], v2 = xr[lane+64];
    float v3 = (lane + 96 < DD) ? xr[lane+96] : 0.f;
    float s = v0 + v1 + v2 + v3;
    #pragma unroll
    for (int o = 16; o; o >>= 1) s += __shfl_xor_sync(0xffffffffu, s, o);
    float mean = s * (1.f/DD);
    float d0 = v0-mean, d1 = v1-mean, d2 = v2-mean;
    float d3 = (lane + 96 < DD) ? (v3 - mean) : 0.f;
    float vs = d0*d0 + d1*d1 + d2*d2 + d3*d3;
    #pragma unroll
    for (int o = 16; o; o >>= 1) vs += __shfl_xor_sync(0xffffffffu, vs, o);
    float inv = rsqrtf(vs * (1.f/DD) + 1e-5f);
    __half* hr = xh + (size_t)row*DP;
    float w;
    w = d0*inv*g[lane]    + b[lane];    xr[lane]    = w; hr[lane]    = __float2half(w);
    w = d1*inv*g[lane+32] + b[lane+32]; xr[lane+32] = w; hr[lane+32] = __float2half(w);
    w = d2*inv*g[lane+64] + b[lane+64]; xr[lane+64] = w; hr[lane+64] = __float2half(w);
    if (lane + 96 < DD){
        w = d3*inv*g[lane+96] + b[lane+96]; xr[lane+96] = w; hr[lane+96] = __float2half(w);
    } else {
        hr[96 + lane] = __half(0.f);
    }
}

// ---------------- GCN aggregation ----------------
// adjacency normalization folded in (sequential j-loop, bit-identical sadj).
// MODE 0: write fp16 padded [row][DP] to outh   (h1 for gemm1)
// MODE 1: write fp32 out + fp16 padded g_xh     (final GCN output)
template<int MODE>
__global__ void k_agg(const float* __restrict__ A, const float* __restrict__ in,
                      float* __restrict__ out, __half* __restrict__ outh, int TD){
    __shared__ float sadj[CC*CC];
    int tid = threadIdx.x;
    if (tid < CC){
        int i = tid;
        float s = 0.f;
        for (int j = 0; j < CC; j++) s += A[i*CC + j] + (i == j ? 1.f : 0.f);
        float inv = 1.f / s;
        for (int j = 0; j < CC; j++)
            sadj[i*CC + j] = (A[i*CC + j] + (i == j ? 1.f : 0.f)) * inv;
    }
    __syncthreads();
    int n = blockIdx.x*256 + tid;
    if (n >= TD) return;
    int t = n / DD, d = n % DD;
    float v[CC];
    #pragma unroll
    for (int j = 0; j < CC; j++) v[j] = in[(size_t)j*TD + n];
    #pragma unroll
    for (int i = 0; i < CC; i++){
        float acc = 0.f;
        #pragma unroll
        for (int j = 0; j < CC; j++) acc += sadj[i*CC + j] * v[j];
        if (MODE == 0){
            outh[((size_t)i*TT + t)*DP + d] = __float2half(acc);
        } else {
            out[(size_t)i*TD + n] = acc;
            g_xh[((size_t)i*TT + t)*DP + d] = __float2half(acc);
        }
    }
}

// ---------------- prediction head ----------------
__global__ void k_stepM(const float* __restrict__ l1, const float* __restrict__ l1b,
                        const float* __restrict__ l2, const float* __restrict__ l2b){
    int idx = blockIdx.x * blockDim.x + threadIdx.x;
    if (idx < DD*DD){
        int e = idx / DD, d = idx % DD;
        float acc = 0.f;
        for (int r = 0; r < LHID; r++)
            acc += l1[e*LHID + r] * l2[r*DD + d];
        g_M2[idx] = acc;
    } else if (idx < DD*DD + DD){
        int d = idx - DD*DD;
        float acc = l2b[d];
        for (int r = 0; r < LHID; r++)
            acc += l1b[r] * l2[r*DD + d];
        g_cvec[d] = acc;
    }
}

#define HEAD_SMEM ((DD*DD + DD + CC*DD) * (int)sizeof(float))
__global__ void __launch_bounds__(1024)
k_head(const float* __restrict__ x, float* __restrict__ out){
    extern __shared__ float hs[];
    float* sM2 = hs;
    float* scv = sM2 + DD*DD;
    float* scr = scv + DD;
    int tid = threadIdx.x;
    for (int q = tid; q < DD*DD; q += 1024) sM2[q] = g_M2[q];
    if (tid < DD) scv[tid] = g_cvec[tid];
    for (int q = tid; q < CC*DD; q += 1024){
        int c = q / DD, d = q % DD;
        scr[q] = x[((size_t)c*TT + TT - 1)*DD + d];
    }
    __syncthreads();
    for (int k = 0; k < NPREDK; k++){
        float rv[4];
        int cnt = 0;
        for (int q = tid; q < CC*DD; q += 1024){
            int c = q / DD, d = q % DD;
            float acc = scv[d];
            const float* cr = scr + c*DD;
            #pragma unroll 4
            for (int e = 0; e < DD; e++)
                acc += cr[e] * sM2[e*DD + d];
            rv[cnt++] = acc;
        }
        __syncthreads();
        cnt = 0;
        for (int q = tid; q < CC*DD; q += 1024){
            int c = q / DD, d = q % DD;
            scr[q] = rv[cnt];
            out[((size_t)c*NPREDK + k)*DD + d] = rv[cnt];
            cnt++;
        }
        __syncthreads();
    }
}

// ---------------- host orchestration ----------------
static float* symF(const void* s){ void* p = nullptr; cudaGetSymbolAddress(&p, s); return (float*)p; }
static __half* symH(const void* s){ void* p = nullptr; cudaGetSymbolAddress(&p, s); return (__half*)p; }

extern "C" void kernel_launch(void* const* d_in, const int* in_sizes, int n_in,
                              void* d_out, int out_size){
    const float* X      = (const float*)d_in[0];
    const float* A      = (const float*)d_in[1];
    const float* gcn_w1 = (const float*)d_in[2];
    const float* gcn_b1 = (const float*)d_in[3];
    const float* gcn_w2 = (const float*)d_in[4];
    const float* gcn_b2 = (const float*)d_in[5];
    const float* enc_wq = (const float*)d_in[6];
    const float* enc_wk = (const float*)d_in[7];
    const float* enc_wv = (const float*)d_in[8];
    const float* enc_wm = (const float*)d_in[9];
    const float* enc_f1w= (const float*)d_in[10];
    const float* enc_f1b= (const float*)d_in[11];
    const float* enc_f2w= (const float*)d_in[12];
    const float* enc_f2b= (const float*)d_in[13];
    const float* ln1g   = (const float*)d_in[14];
    const float* ln1b   = (const float*)d_in[15];
    const float* ln2g   = (const float*)d_in[16];
    const float* ln2b   = (const float*)d_in[17];
    const float* lin1_w = (const float*)d_in[18];
    const float* lin1_b = (const float*)d_in[19];
    const float* lin2_w = (const float*)d_in[20];
    const float* lin2_b = (const float*)d_in[21];
    float* out = (float*)d_out;

    float*  p_u    = symF(g_u);
    float*  p_x    = symF(g_x);
    float*  p_y    = symF(g_y);
    __half* p_h1h  = symH(g_h1h);
    __half* p_th   = symH(g_th);
    __half* p_xh   = symH(g_xh);
    __half* p_qkv  = symH(g_qkvh);
    __half* p_att  = symH(g_atth);
    __half* p_ffn  = symH(g_ffnh);
    __half* p_wqkv = symH(g_wqkv);
    __half* p_wm   = symH(g_wm);
    __half* p_f1   = symH(g_f1);
    __half* p_f2   = symH(g_f2);
    __half* p_w1h  = symH(g_w1h);
    __half* p_w2h  = symH(g_w2h);

    cudaFuncSetAttribute(k_fattn, cudaFuncAttributeMaxDynamicSharedMemorySize, FA_SMEM);
    cudaFuncSetAttribute(k_head,  cudaFuncAttributeMaxDynamicSharedMemorySize, HEAD_SMEM);

    // GCN weight packs first (needed by gemm1/gemm2)
    k_pack_w1<<<(DP*64 + 255)/256, 256>>>(gcn_w1);
    k_pack_w2<<<(64*104 + 255)/256, 256>>>(gcn_w2);

    // GCN: h1 = agg(X) [fp16]; t = relu(h1 W1 + b1) [fp16];
    //      u = t W2 + b2 [fp32]; x = agg(u) [fp32 + fp16 xh]  (agg/W2 commute)
    k_agg<0><<<(TT*DD + 255)/256, 256>>>(A, X, nullptr, p_h1h, TT*DD);
    hgemm<4><<<dim3(1, CT/BM), 256>>>(
        p_h1h, p_w1h, nullptr, p_th, gcn_b1, nullptr, 0,
        CT, HIDG, DP, DP, 64, 64);
    hgemm<6><<<dim3(2, CT/BM), 256>>>(
        p_th, p_w2h, p_u, nullptr, gcn_b2, nullptr, 0,
        CT, DD, 64, 64, 104, DD);
    k_agg<1><<<(TT*DD + 255)/256, 256>>>(A, p_u, p_x, nullptr, TT*DD);

    // pack encoder weights fp16 (all layers); fold head affine (multi-CTA)
    k_pack_qkv<<<(NLAYER*DP*QKVP + 255)/256, 256>>>(enc_wq, enc_wk, enc_wv);
    k_pack_wm <<<(NLAYER*ATTP*DP + 255)/256, 256>>>(enc_wm);
    k_pack_f1 <<<(NLAYER*DP*FFND + 255)/256, 256>>>(enc_f1w);
    k_pack_f2 <<<(NLAYER*FFND*DP + 255)/256, 256>>>(enc_f2w);
    k_stepM<<<(DD*DD + DD + 255)/256, 256>>>(lin1_w, lin1_b, lin2_w, lin2_b);

    for (int l = 0; l < NLAYER; l++){
        // QKV: [CT,128] @ [128,1920] -> fp16 (special full-K kernel)
        k_qkv<<<dim3(QKVP/QBN, CT/QBM), 256>>>(p_xh, p_wqkv + (size_t)l*DP*QKVP, p_qkv);

        // fused attention
        k_fattn<<<dim3(TT/FA_BQ, NB), 256, FA_SMEM>>>(p_qkv, p_att);

        // proj: y = x + att @ wm  (fp32 out)
        hgemm<3><<<dim3(2, CT/BM), 256>>>(
            p_att, p_wm + (size_t)l*ATTP*DP, p_y, nullptr, nullptr, p_x, DD,
            CT, DD, ATTP, ATTP, DP, DD);

        k_lnh<<<CT/8, 256>>>(p_y, ln1g + l*DD, ln1b + l*DD, p_xh);

        // ffn1: relu(xh @ f1 + b1) -> fp16
        hgemm<4><<<dim3(1, CT/BM), 256>>>(
            p_xh, p_f1 + (size_t)l*DP*FFND, nullptr, p_ffn, enc_f1b + l*FFND, nullptr, 0,
            CT, FFND, DP, DP, FFND, FFND);

        // ffn2: x = y + ffn @ f2 + b2 (fp32 out)
        hgemm<5><<<dim3(2, CT/BM), 256>>>(
            p_ffn, p_f2 + (size_t)l*FFND*DP, p_x, nullptr, enc_f2b + l*DD, p_y, DD,
            CT, DD, FFND, FFND, DP, DD);

        k_lnh<<<CT/8, 256>>>(p_x, ln2g + l*DD, ln2b + l*DD, p_xh);
    }

    // head: iterate 10 steps (fold already done in k_stepM)
    k_head<<<1, 1024, HEAD_SMEM>>>(p_x, out);
}

// round 17
// speedup vs baseline: 1.6310x; 1.0291x over previous
#include <cuda_runtime.h>
#include <cuda_fp16.h>
#include <math.h>

#define CC 32
#define TT 768
#define DD 100
#define HH 5
#define HIDG 60
#define FFND 64
#define NPREDK 10
#define LHID 200
#define NLAYER 3
#define CT (CC*TT)          // 24576
#define DP 128              // padded feature/head dim
#define QKVP (15*DP)        // 1920
#define ATTP (HH*DP)        // 640
#define NB (CC*HH)          // 160

// ---------------- device scratch ----------------
__device__ float g_u[CT*DD];
__device__ float g_x[CT*DD];
__device__ float g_y[CT*DD];
__device__ float g_M2[DD*DD];
__device__ float g_cvec[DD];

__device__ __half g_h1h[CT*DP];      // agg(X) fp16, pads 100..127 stay zero (.bss)
__device__ __half g_th[CT*64];       // relu GCN hidden, pads 60..63 stay zero
__device__ __half g_xh[CT*DP];
__device__ __half g_qkvh[(size_t)CT*QKVP];
__device__ __half g_atth[(size_t)CT*ATTP];   // pad cols stay zero (.bss)
__device__ __half g_wqkv[NLAYER*DP*QKVP];
__device__ __half g_wm[NLAYER*ATTP*DP];
__device__ __half g_f1[NLAYER*DP*FFND];
__device__ __half g_f2[NLAYER*FFND*DP];
__device__ __half g_w1h[DP*64];      // gcn_w1 padded [128][64]
__device__ __half g_w2h[64*104];     // gcn_w2 padded [64][104]

// ---------------- small helpers ----------------
__device__ __forceinline__ unsigned sptr(const void* p){
    return (unsigned)__cvta_generic_to_shared(p);
}
__device__ __forceinline__ void cpa16(unsigned dst, const void* src, int bytes){
    asm volatile("cp.async.cg.shared.global [%0], [%1], 16, %2;\n"
                 :: "r"(dst), "l"(src), "r"(bytes));
}
__device__ __forceinline__ void cp_commit(){ asm volatile("cp.async.commit_group;\n" ::: "memory"); }
__device__ __forceinline__ void cp_wait0(){ asm volatile("cp.async.wait_group 0;\n" ::: "memory"); }

__device__ __forceinline__ void ldsm4(unsigned& r0,unsigned& r1,unsigned& r2,unsigned& r3, unsigned a){
    asm volatile("ldmatrix.sync.aligned.m8n8.x4.shared.b16 {%0,%1,%2,%3}, [%4];\n"
        : "=r"(r0),"=r"(r1),"=r"(r2),"=r"(r3) : "r"(a));
}
__device__ __forceinline__ void ldsm4t(unsigned& r0,unsigned& r1,unsigned& r2,unsigned& r3, unsigned a){
    asm volatile("ldmatrix.sync.aligned.m8n8.x4.trans.shared.b16 {%0,%1,%2,%3}, [%4];\n"
        : "=r"(r0),"=r"(r1),"=r"(r2),"=r"(r3) : "r"(a));
}
__device__ __forceinline__ void mma16816(float* c, const unsigned* a, const unsigned* b){
    asm volatile("mma.sync.aligned.m16n8k16.row.col.f32.f16.f16.f32 "
        "{%0,%1,%2,%3}, {%4,%5,%6,%7}, {%8,%9}, {%0,%1,%2,%3};\n"
        : "+f"(c[0]),"+f"(c[1]),"+f"(c[2]),"+f"(c[3])
        : "r"(a[0]),"r"(a[1]),"r"(a[2]),"r"(a[3]), "r"(b[0]),"r"(b[1]));
}

// ---------------- fused flash attention (R10-proven) ----------------
#define FA_BQ 128
#define FA_BK 64
#define FA_DS 136
#define FA_SMEM ((FA_BQ + 4*FA_BK) * FA_DS * 2)

__global__ void __launch_bounds__(256, 1)
k_fattn(const __half* __restrict__ qkv, __half* __restrict__ att){
    extern __shared__ __align__(16) __half sm[];
    __half* Qs = sm;                       // [128][136]
    __half* Ks = Qs + FA_BQ*FA_DS;         // [2][64][136]
    __half* Vs = Ks + 2*FA_BK*FA_DS;       // [2][64][136]

    int tid = threadIdx.x, lane = tid & 31, w = tid >> 5;
    int qt = blockIdx.x;
    int z = blockIdx.y;
    int c = z / HH, h = z % HH;
    const __half* Qg = qkv + (size_t)c*TT*QKVP + h*DP;
    const __half* Kg = Qg + HH*DP;
    const __half* Vg = Qg + 2*HH*DP;

    #pragma unroll
    for (int i = 0; i < 8; i++){
        int idx = tid + i*256;
        int r = idx >> 4, cc2 = (idx & 15) * 8;
        cpa16(sptr(&Qs[r*FA_DS + cc2]), Qg + (size_t)(qt*FA_BQ + r)*QKVP + cc2, 16);
    }
    cp_commit();

    auto prefKV = [&](int kt, int buf){
        const __half* kb = Kg + (size_t)kt*FA_BK*QKVP;
        const __half* vb = Vg + (size_t)kt*FA_BK*QKVP;
        #pragma unroll
        for (int i = 0; i < 4; i++){
            int idx = tid + i*256;
            int r = idx >> 4, cc2 = (idx & 15) * 8;
            cpa16(sptr(&Ks[(buf*FA_BK + r)*FA_DS + cc2]), kb + (size_t)r*QKVP + cc2, 16);
        }
        #pragma unroll
        for (int i = 0; i < 4; i++){
            int idx = tid + i*256;
            int r = idx >> 4, cc2 = (idx & 15) * 8;
            cpa16(sptr(&Vs[(buf*FA_BK + r)*FA_DS + cc2]), vb + (size_t)r*QKVP + cc2, 16);
        }
    };
    prefKV(0, 0);
    cp_commit();
    cp_wait0();
    __syncthreads();

    unsigned qa[7][4];
    #pragma unroll
    for (int kk = 0; kk < 7; kk++){
        unsigned ad = sptr(&Qs[(w*16 + (lane & 15))*FA_DS + kk*16 + (lane >> 4)*8]);
        ldsm4(qa[kk][0], qa[kk][1], qa[kk][2], qa[kk][3], ad);
    }

    float o[14][4];
    #pragma unroll
    for (int i = 0; i < 14; i++){ o[i][0]=0.f; o[i][1]=0.f; o[i][2]=0.f; o[i][3]=0.f; }
    float rs0 = 0.f, rs1 = 0.f;

    for (int kt = 0; kt < TT/FA_BK; kt++){
        int buf = kt & 1;
        if (kt){
            cp_wait0();
            __syncthreads();
        }
        if (kt + 1 < TT/FA_BK) prefKV(kt + 1, buf ^ 1);
        cp_commit();

        float s[8][4];
        #pragma unroll
        for (int i = 0; i < 8; i++){ s[i][0]=0.f; s[i][1]=0.f; s[i][2]=0.f; s[i][3]=0.f; }
        #pragma unroll
        for (int ks = 0; ks < 7; ks++){
            unsigned kbf[8][2];
            #pragma unroll
            for (int np = 0; np < 4; np++){
                unsigned ad = sptr(&Ks[(buf*FA_BK + np*16 + (lane & 7) + ((lane >> 4) << 3))*FA_DS
                                        + ks*16 + ((lane >> 3) & 1)*8]);
                ldsm4(kbf[np*2][0], kbf[np*2][1], kbf[np*2+1][0], kbf[np*2+1][1], ad);
            }
            #pragma unroll
            for (int nt = 0; nt < 8; nt++)
                mma16816(s[nt], qa[ks], kbf[nt]);
        }

        // interleaved exp->pack per PV k-step (rowsum order preserved)
        #pragma unroll
        for (int ks = 0; ks < 4; ks++){
            unsigned paks[4];
            #pragma unroll
            for (int j = 0; j < 2; j++){
                int nt = 2*ks + j;
                __half2 h01 = __floats2half2_rn(__expf(s[nt][0]*0.1f), __expf(s[nt][1]*0.1f));
                __half2 h23 = __floats2half2_rn(__expf(s[nt][2]*0.1f), __expf(s[nt][3]*0.1f));
                paks[2*j]     = *(unsigned*)&h01;
                paks[2*j + 1] = *(unsigned*)&h23;
                float2 f01 = __half22float2(h01); rs0 += f01.x + f01.y;
                float2 f23 = __half22float2(h23); rs1 += f23.x + f23.y;
            }
            #pragma unroll
            for (int nt16 = 0; nt16 < 7; nt16++){
                unsigned b0[2], b1[2];
                unsigned ad = sptr(&Vs[(buf*FA_BK + ks*16 + (lane & 15))*FA_DS
                                        + nt16*16 + (lane >> 4)*8]);
                ldsm4t(b0[0], b0[1], b1[0], b1[1], ad);
                mma16816(o[nt16*2],     paks, b0);
                mma16816(o[nt16*2 + 1], paks, b1);
            }
        }
        __syncthreads();
    }

    rs0 += __shfl_xor_sync(0xffffffffu, rs0, 1);
    rs0 += __shfl_xor_sync(0xffffffffu, rs0, 2);
    rs1 += __shfl_xor_sync(0xffffffffu, rs1, 1);
    rs1 += __shfl_xor_sync(0xffffffffu, rs1, 2);
    float inv0 = 1.f / rs0, inv1 = 1.f / rs1;

    int row0 = qt*FA_BQ + w*16 + (lane >> 2);
    __half* o0 = att + ((size_t)c*TT + row0)*ATTP + h*DP;
    __half* o1 = o0 + 8*ATTP;
    #pragma unroll
    for (int nt = 0; nt < 13; nt++){
        int col = nt*8 + (lane & 3)*2;
        if (col <= 98){
            *(__half2*)(o0 + col) = __floats2half2_rn(o[nt][0]*inv0, o[nt][1]*inv0);
            *(__half2*)(o1 + col) = __floats2half2_rn(o[nt][2]*inv1, o[nt][3]*inv1);
        }
    }
}

// ---------------- QKV special GEMM: K=128 fully smem-resident ----------------
#define QBM 128
#define QBN 64
__global__ void __launch_bounds__(256)
k_qkv(const __half* __restrict__ A, const __half* __restrict__ B, __half* __restrict__ C){
    __shared__ __align__(16) __half As[QBM][DP+8];   // 128 x 136
    __shared__ __align__(16) __half Bs[DP][QBN+8];   // 128 x 72
    int tid = threadIdx.x;
    int m0 = blockIdx.y * QBM, n0 = blockIdx.x * QBN;
    int warp = tid >> 5, lane = tid & 31;
    int wm0 = (warp >> 1) * 32, wn0 = (warp & 1) * 32;

    #pragma unroll
    for (int i = 0; i < 8; i++){
        int idx = tid + i*256;
        int r = idx >> 4, cc = (idx & 15) * 8;
        cpa16(sptr(&As[r][cc]), A + (size_t)(m0 + r)*DP + cc, 16);
    }
    #pragma unroll
    for (int i = 0; i < 4; i++){
        int idx = tid + i*256;
        int r = idx >> 3, cc = (idx & 7) * 8;
        cpa16(sptr(&Bs[r][cc]), B + (size_t)r*QKVP + n0 + cc, 16);
    }
    cp_commit(); cp_wait0(); __syncthreads();

    float c[2][4][4];
    #pragma unroll
    for (int a=0;a<2;a++) for (int b=0;b<4;b++) for (int d=0;d<4;d++) c[a][b][d]=0.f;

    #pragma unroll
    for (int ks = 0; ks < 8; ks++){
        unsigned a[2][4], b[4][2];
        #pragma unroll
        for (int mt = 0; mt < 2; mt++){
            unsigned ad = sptr(&As[wm0 + mt*16 + (lane & 15)][ks*16 + (lane >> 4)*8]);
            ldsm4(a[mt][0], a[mt][1], a[mt][2], a[mt][3], ad);
        }
        #pragma unroll
        for (int np = 0; np < 2; np++){
            unsigned ad = sptr(&Bs[ks*16 + (lane & 15)][wn0 + np*16 + (lane >> 4)*8]);
            ldsm4t(b[np*2][0], b[np*2][1], b[np*2+1][0], b[np*2+1][1], ad);
        }
        #pragma unroll
        for (int mt = 0; mt < 2; mt++)
            #pragma unroll
            for (int nt = 0; nt < 4; nt++)
                mma16816(c[mt][nt], a[mt], b[nt]);
    }

    #pragma unroll
    for (int mt = 0; mt < 2; mt++){
        #pragma unroll
        for (int i = 0; i < 2; i++){
            int row = m0 + wm0 + mt*16 + (lane >> 2) + i*8;
            #pragma unroll
            for (int nt = 0; nt < 4; nt++){
                int col = n0 + wn0 + nt*8 + (lane & 3)*2;
                *(__half2*)(C + (size_t)row*QKVP + col) =
                    __floats2half2_rn(c[mt][nt][i*2+0], c[mt][nt][i*2+1]);
            }
        }
    }
}

// ---------------- fused FFN: x = LN2(y + relu(xh@f1+b1)@f2 + b2) ----------------
// One CTA per 128 rows; warp-per-16-rows; t stays in registers (C->A frag trick)
#define FFN_SMEM ((128*136 + 128*72 + 64*112) * 2)

__global__ void __launch_bounds__(256)
k_ffn(const __half* __restrict__ xh, const float* __restrict__ y,
      const __half* __restrict__ f1, const __half* __restrict__ f2,
      const float* __restrict__ b1, const float* __restrict__ b2,
      const float* __restrict__ lg, const float* __restrict__ lb,
      float* __restrict__ xout, __half* __restrict__ xhout){
    extern __shared__ __align__(16) __half fs[];
    __half* Xs  = fs;                 // [128][136]
    __half* F1s = Xs + 128*136;       // [128][72]
    __half* F2s = F1s + 128*72;       // [64][112]
    int tid = threadIdx.x, lane = tid & 31, w = tid >> 5;
    int m0 = blockIdx.x * 128;

    #pragma unroll
    for (int i = 0; i < 8; i++){
        int idx = tid + i*256;                 // 2048 chunks
        int r = idx >> 4, cc = (idx & 15) * 8;
        cpa16(sptr(&Xs[r*136 + cc]), xh + (size_t)(m0 + r)*DP + cc, 16);
    }
    #pragma unroll
    for (int i = 0; i < 4; i++){
        int idx = tid + i*256;                 // 1024 chunks
        int r = idx >> 3, cc = (idx & 7) * 8;
        cpa16(sptr(&F1s[r*72 + cc]), f1 + (size_t)r*FFND + cc, 16);
    }
    #pragma unroll
    for (int i = 0; i < 4; i++){
        int idx = tid + i*256;                 // 896 chunks
        if (idx < 896){
            int r = idx / 14, cc = (idx % 14) * 8;
            cpa16(sptr(&F2s[r*112 + cc]), f2 + (size_t)r*DP + cc, 16);
        }
    }
    cp_commit(); cp_wait0(); __syncthreads();

    // ffn1: t = relu(x @ f1 + b1), warp rows w*16..w*16+15, cols 0..63
    float ct[8][4];
    #pragma unroll
    for (int i = 0; i < 8; i++){ ct[i][0]=0.f; ct[i][1]=0.f; ct[i][2]=0.f; ct[i][3]=0.f; }
    #pragma unroll
    for (int g = 0; g < 8; g++){
        unsigned a[4];
        ldsm4(a[0], a[1], a[2], a[3],
              sptr(&Xs[(w*16 + (lane & 15))*136 + g*16 + (lane >> 4)*8]));
        #pragma unroll
        for (int n16 = 0; n16 < 4; n16++){
            unsigned b0[2], b1r[2];
            ldsm4t(b0[0], b0[1], b1r[0], b1r[1],
                   sptr(&F1s[(g*16 + (lane & 15))*72 + n16*16 + (lane >> 4)*8]));
            mma16816(ct[n16*2],     a, b0);
            mma16816(ct[n16*2 + 1], a, b1r);
        }
    }

    // relu + bias, pack C-frags -> A-frags (k_fattn pa mapping)
    unsigned ta[4][4];
    #pragma unroll
    for (int nt = 0; nt < 8; nt++){
        int col = nt*8 + (lane & 3)*2;
        __half2 h01 = __floats2half2_rn(fmaxf(ct[nt][0] + b1[col], 0.f),
                                        fmaxf(ct[nt][1] + b1[col+1], 0.f));
        __half2 h23 = __floats2half2_rn(fmaxf(ct[nt][2] + b1[col], 0.f),
                                        fmaxf(ct[nt][3] + b1[col+1], 0.f));
        int g = nt >> 1, odd = (nt & 1) << 1;
        ta[g][odd]     = *(unsigned*)&h01;
        ta[g][odd + 1] = *(unsigned*)&h23;
    }

    // ffn2: u = t @ f2
    float cf[14][4];
    #pragma unroll
    for (int i = 0; i < 14; i++){ cf[i][0]=0.f; cf[i][1]=0.f; cf[i][2]=0.f; cf[i][3]=0.f; }
    #pragma unroll
    for (int g = 0; g < 4; g++){
        #pragma unroll
        for (int n16 = 0; n16 < 7; n16++){
            unsigned b0[2], b1r[2];
            ldsm4t(b0[0], b0[1], b1r[0], b1r[1],
                   sptr(&F2s[(g*16 + (lane & 15))*112 + n16*16 + (lane >> 4)*8]));
            mma16816(cf[n16*2],     ta[g], b0);
            mma16816(cf[n16*2 + 1], ta[g], b1r);
        }
    }

    // epilogue: v = (u + b2) + y ; then LN over each row (4-lane shfl groups)
    int r0 = m0 + w*16 + (lane >> 2);
    int r1 = r0 + 8;
    float s0 = 0.f, s1 = 0.f;
    #pragma unroll
    for (int nt = 0; nt < 14; nt++){
        int col = nt*8 + (lane & 3)*2;
        if (col <= 98){
            float2 y0 = *(const float2*)(y + (size_t)r0*DD + col);
            float2 y1 = *(const float2*)(y + (size_t)r1*DD + col);
            cf[nt][0] = (cf[nt][0] + b2[col])   + y0.x;
            cf[nt][1] = (cf[nt][1] + b2[col+1]) + y0.y;
            cf[nt][2] = (cf[nt][2] + b2[col])   + y1.x;
            cf[nt][3] = (cf[nt][3] + b2[col+1]) + y1.y;
            s0 += cf[nt][0] + cf[nt][1];
            s1 += cf[nt][2] + cf[nt][3];
        }
    }
    s0 += __shfl_xor_sync(0xffffffffu, s0, 1);
    s0 += __shfl_xor_sync(0xffffffffu, s0, 2);
    s1 += __shfl_xor_sync(0xffffffffu, s1, 1);
    s1 += __shfl_xor_sync(0xffffffffu, s1, 2);
    float mean0 = s0 * (1.f/DD), mean1 = s1 * (1.f/DD);
    float vs0 = 0.f, vs1 = 0.f;
    #pragma unroll
    for (int nt = 0; nt < 14; nt++){
        int col = nt*8 + (lane & 3)*2;
        if (col <= 98){
            float d0 = cf[nt][0]-mean0, d1 = cf[nt][1]-mean0;
            float d2 = cf[nt][2]-mean1, d3 = cf[nt][3]-mean1;
            vs0 += d0*d0 + d1*d1;
            vs1 += d2*d2 + d3*d3;
        }
    }
    vs0 += __shfl_xor_sync(0xffffffffu, vs0, 1);
    vs0 += __shfl_xor_sync(0xffffffffu, vs0, 2);
    vs1 += __shfl_xor_sync(0xffffffffu, vs1, 1);
    vs1 += __shfl_xor_sync(0xffffffffu, vs1, 2);
    float inv0 = rsqrtf(vs0 * (1.f/DD) + 1e-5f);
    float inv1 = rsqrtf(vs1 * (1.f/DD) + 1e-5f);

    #pragma unroll
    for (int nt = 0; nt < 14; nt++){
        int col = nt*8 + (lane & 3)*2;
        if (col <= 98){
            float g0 = lg[col], g1 = lg[col+1];
            float q0 = lb[col], q1 = lb[col+1];
            float n00 = (cf[nt][0]-mean0)*inv0*g0 + q0;
            float n01 = (cf[nt][1]-mean0)*inv0*g1 + q1;
            float n10 = (cf[nt][2]-mean1)*inv1*g0 + q0;
            float n11 = (cf[nt][3]-mean1)*inv1*g1 + q1;
            *(float2*)(xout + (size_t)r0*DD + col) = make_float2(n00, n01);
            *(float2*)(xout + (size_t)r1*DD + col) = make_float2(n10, n11);
            *(__half2*)(xhout + (size_t)r0*DP + col) = __floats2half2_rn(n00, n01);
            *(__half2*)(xhout + (size_t)r1*DP + col) = __floats2half2_rn(n10, n11);
        }
    }
}

// ---------------- fp16 tensor-core GEMM (generic) ----------------
// EPI: 3 f32 acc+res; 4 half(relu(acc+bias)); 6 f32 acc+bias
#define BM 128
#define BN 64
#define BKK 32

template<int EPI>
__global__ void __launch_bounds__(256)
hgemm(const __half* __restrict__ A, const __half* __restrict__ B,
      float* __restrict__ outF, __half* __restrict__ outH,
      const float* __restrict__ bias, const float* __restrict__ res, int ldr,
      int M, int N, int K, int lda, int ldb, int ldc)
{
    __shared__ __align__(16) __half As[2][BM][BKK+8];
    __shared__ __align__(16) __half Bs[2][BKK][BN+8];

    int tid = threadIdx.x;
    int m0 = blockIdx.y * BM, n0 = blockIdx.x * BN;
    int warp = tid >> 5, lane = tid & 31;
    int wm0 = (warp >> 1) * 32, wn0 = (warp & 1) * 32;

    float c[2][4][4];
    #pragma unroll
    for (int a=0;a<2;a++) for (int b=0;b<4;b++) for (int d=0;d<4;d++) c[a][b][d]=0.f;

    auto prefA = [&](int kt, int buf){
        int k0 = kt*BKK;
        #pragma unroll
        for (int i=0;i<2;i++){
            int q = tid + i*256;
            int r = q >> 2, cc = (q & 3) * 8;
            cpa16(sptr(&As[buf][r][cc]), A + (size_t)(m0+r)*lda + k0 + cc, 16);
        }
    };
    auto prefB = [&](int kt, int buf){
        int k0 = kt*BKK;
        int r = tid >> 3, cc = (tid & 7) * 8;
        int nrem = N - (n0 + cc);
        int bytes = nrem >= 8 ? 16 : (nrem > 0 ? nrem*2 : 0);
        const __half* src = bytes ? (B + (size_t)(k0+r)*ldb + n0 + cc) : B;
        cpa16(sptr(&Bs[buf][r][cc]), src, bytes);
    };

    int nk = K / BKK;
    prefA(0,0); prefB(0,0); cp_commit();

    for (int kt = 0; kt < nk; kt++){
        int buf = kt & 1;
        cp_wait0();
        __syncthreads();
        if (kt+1 < nk){ prefA(kt+1, buf^1); prefB(kt+1, buf^1); }
        cp_commit();

        #pragma unroll
        for (int ks = 0; ks < 2; ks++){
            unsigned a[2][4], b[4][2];
            #pragma unroll
            for (int mt = 0; mt < 2; mt++){
                unsigned ad = sptr(&As[buf][wm0 + mt*16 + (lane & 15)][ks*16 + (lane >> 4)*8]);
                ldsm4(a[mt][0], a[mt][1], a[mt][2], a[mt][3], ad);
            }
            #pragma unroll
            for (int np = 0; np < 2; np++){
                unsigned ad = sptr(&Bs[buf][ks*16 + (lane & 15)][wn0 + np*16 + (lane >> 4)*8]);
                ldsm4t(b[np*2][0], b[np*2][1], b[np*2+1][0], b[np*2+1][1], ad);
            }
            #pragma unroll
            for (int mt = 0; mt < 2; mt++)
                #pragma unroll
                for (int nt = 0; nt < 4; nt++)
                    mma16816(c[mt][nt], a[mt], b[nt]);
        }
        __syncthreads();
    }

    #pragma unroll
    for (int mt = 0; mt < 2; mt++){
        #pragma unroll
        for (int i = 0; i < 2; i++){
            int row = m0 + wm0 + mt*16 + (lane >> 2) + i*8;
            #pragma unroll
            for (int nt = 0; nt < 4; nt++){
                int col = n0 + wn0 + nt*8 + (lane & 3)*2;
                if (col >= N) continue;
                float v0 = c[mt][nt][i*2+0];
                float v1 = c[mt][nt][i*2+1];
                size_t off = (size_t)row*ldc + col;
                if (EPI == 3){
                    outF[off]   = v0 + res[(size_t)row*ldr + col];
                    outF[off+1] = v1 + res[(size_t)row*ldr + col + 1];
                } else if (EPI == 4){
                    *(__half2*)(outH + off) = __floats2half2_rn(fmaxf(v0 + bias[col], 0.f),
                                                                fmaxf(v1 + bias[col+1], 0.f));
                } else if (EPI == 6){
                    outF[off]   = v0 + bias[col];
                    outF[off+1] = v1 + bias[col+1];
                }
            }
        }
    }
}

// ---------------- weight packing ----------------
__global__ void k_pack_qkv(const float* __restrict__ wq, const float* __restrict__ wk,
                           const float* __restrict__ wv){
    int idx = blockIdx.x*256 + threadIdx.x;
    if (idx >= NLAYER*DP*QKVP) return;
    int l = idx / (DP*QKVP);
    int r = idx % (DP*QKVP);
    int k = r / QKVP, n = r % QKVP;
    int slot = n / DP, d = n % DP;
    int type = slot / HH, h = slot % HH;
    float v = 0.f;
    if (k < DD && d < DD){
        const float* w = type == 0 ? wq : (type == 1 ? wk : wv);
        v = w[(((size_t)l*HH + h)*DD + k)*DD + d];
    }
    g_wqkv[idx] = __float2half(v);
}

__global__ void k_pack_wm(const float* __restrict__ wm){
    int idx = blockIdx.x*256 + threadIdx.x;
    if (idx >= NLAYER*ATTP*DP) return;
    int l = idx / (ATTP*DP);
    int r = idx % (ATTP*DP);
    int k = r / DP, n = r % DP;
    int h = k / DP, dk = k % DP;
    float v = 0.f;
    if (dk < DD && n < DD)
        v = wm[((size_t)l*(HH*DD) + h*DD + dk)*DD + n];
    g_wm[idx] = __float2half(v);
}

__global__ void k_pack_f1(const float* __restrict__ f1){
    int idx = blockIdx.x*256 + threadIdx.x;
    if (idx >= NLAYER*DP*FFND) return;
    int l = idx / (DP*FFND);
    int r = idx % (DP*FFND);
    int k = r / FFND, n = r % FFND;
    g_f1[idx] = __float2half(k < DD ? f1[((size_t)l*DD + k)*FFND + n] : 0.f);
}

__global__ void k_pack_f2(const float* __restrict__ f2){
    int idx = blockIdx.x*256 + threadIdx.x;
    if (idx >= NLAYER*FFND*DP) return;
    int l = idx / (FFND*DP);
    int r = idx % (FFND*DP);
    int k = r / DP, n = r % DP;
    g_f2[idx] = __float2half(n < DD ? f2[((size_t)l*FFND + k)*DD + n] : 0.f);
}

// GCN weight packs: w1 -> [128][64], w2 -> [64][104] (zero-padded)
__global__ void k_pack_w1(const float* __restrict__ w1){
    int idx = blockIdx.x*256 + threadIdx.x;
    if (idx >= DP*64) return;
    int k = idx / 64, n = idx % 64;
    g_w1h[idx] = __float2half((k < DD && n < HIDG) ? w1[k*HIDG + n] : 0.f);
}
__global__ void k_pack_w2(const float* __restrict__ w2){
    int idx = blockIdx.x*256 + threadIdx.x;
    if (idx >= 64*104) return;
    int k = idx / 104, n = idx % 104;
    g_w2h[idx] = __float2half((k < HIDG && n < DD) ? w2[k*DD + n] : 0.f);
}

// ---------------- layernorm (fp32 in-place) + fp16 padded output ----------------
__global__ void k_lnh(float* __restrict__ x, const float* __restrict__ g,
                      const float* __restrict__ b, __half* __restrict__ xh){
    int warp = threadIdx.x >> 5;
    int lane = threadIdx.x & 31;
    int row = blockIdx.x*8 + warp;
    if (row >= CT) return;
    float* xr = x + (size_t)row*DD;
    float v0 = xr[lane], v1 = xr[lane+32], v2 = xr[lane+64];
    float v3 = (lane + 96 < DD) ? xr[lane+96] : 0.f;
    float s = v0 + v1 + v2 + v3;
    #pragma unroll
    for (int o = 16; o; o >>= 1) s += __shfl_xor_sync(0xffffffffu, s, o);
    float mean = s * (1.f/DD);
    float d0 = v0-mean, d1 = v1-mean, d2 = v2-mean;
    float d3 = (lane + 96 < DD) ? (v3 - mean) : 0.f;
    float vs = d0*d0 + d1*d1 + d2*d2 + d3*d3;
    #pragma unroll
    for (int o = 16; o; o >>= 1) vs += __shfl_xor_sync(0xffffffffu, vs, o);
    float inv = rsqrtf(vs * (1.f/DD) + 1e-5f);
    __half* hr = xh + (size_t)row*DP;
    float w;
    w = d0*inv*g[lane]    + b[lane];    xr[lane]    = w; hr[lane]    = __float2half(w);
    w = d1*inv*g[lane+32] + b[lane+32]; xr[lane+32] = w; hr[lane+32] = __float2half(w);
    w = d2*inv*g[lane+64] + b[lane+64]; xr[lane+64] = w; hr[lane+64] = __float2half(w);
    if (lane + 96 < DD){
        w = d3*inv*g[lane+96] + b[lane+96]; xr[lane+96] = w; hr[lane+96] = __float2half(w);
    } else {
        hr[96 + lane] = __half(0.f);
    }
}

// ---------------- GCN aggregation ----------------
template<int MODE>
__global__ void k_agg(const float* __restrict__ A, const float* __restrict__ in,
                      float* __restrict__ out, __half* __restrict__ outh, int TD){
    __shared__ float sadj[CC*CC];
    int tid = threadIdx.x;
    if (tid < CC){
        int i = tid;
        float s = 0.f;
        for (int j = 0; j < CC; j++) s += A[i*CC + j] + (i == j ? 1.f : 0.f);
        float inv = 1.f / s;
        for (int j = 0; j < CC; j++)
            sadj[i*CC + j] = (A[i*CC + j] + (i == j ? 1.f : 0.f)) * inv;
    }
    __syncthreads();
    int n = blockIdx.x*256 + tid;
    if (n >= TD) return;
    int t = n / DD, d = n % DD;
    float v[CC];
    #pragma unroll
    for (int j = 0; j < CC; j++) v[j] = in[(size_t)j*TD + n];
    #pragma unroll
    for (int i = 0; i < CC; i++){
        float acc = 0.f;
        #pragma unroll
        for (int j = 0; j < CC; j++) acc += sadj[i*CC + j] * v[j];
        if (MODE == 0){
            outh[((size_t)i*TT + t)*DP + d] = __float2half(acc);
        } else {
            out[(size_t)i*TD + n] = acc;
            g_xh[((size_t)i*TT + t)*DP + d] = __float2half(acc);
        }
    }
}

// ---------------- prediction head ----------------
__global__ void k_stepM(const float* __restrict__ l1, const float* __restrict__ l1b,
                        const float* __restrict__ l2, const float* __restrict__ l2b){
    int idx = blockIdx.x * blockDim.x + threadIdx.x;
    if (idx < DD*DD){
        int e = idx / DD, d = idx % DD;
        float acc = 0.f;
        for (int r = 0; r < LHID; r++)
            acc += l1[e*LHID + r] * l2[r*DD + d];
        g_M2[idx] = acc;
    } else if (idx < DD*DD + DD){
        int d = idx - DD*DD;
        float acc = l2b[d];
        for (int r = 0; r < LHID; r++)
            acc += l1b[r] * l2[r*DD + d];
        g_cvec[d] = acc;
    }
}

#define HEAD_SMEM ((DD*DD + DD + CC*DD) * (int)sizeof(float))
__global__ void __launch_bounds__(1024)
k_head(const float* __restrict__ x, float* __restrict__ out){
    extern __shared__ float hs[];
    float* sM2 = hs;
    float* scv = sM2 + DD*DD;
    float* scr = scv + DD;
    int tid = threadIdx.x;
    for (int q = tid; q < DD*DD; q += 1024) sM2[q] = g_M2[q];
    if (tid < DD) scv[tid] = g_cvec[tid];
    for (int q = tid; q < CC*DD; q += 1024){
        int c = q / DD, d = q % DD;
        scr[q] = x[((size_t)c*TT + TT - 1)*DD + d];
    }
    __syncthreads();
    for (int k = 0; k < NPREDK; k++){
        float rv[4];
        int cnt = 0;
        for (int q = tid; q < CC*DD; q += 1024){
            int c = q / DD, d = q % DD;
            float acc = scv[d];
            const float* cr = scr + c*DD;
            #pragma unroll 4
            for (int e = 0; e < DD; e++)
                acc += cr[e] * sM2[e*DD + d];
            rv[cnt++] = acc;
        }
        __syncthreads();
        cnt = 0;
        for (int q = tid; q < CC*DD; q += 1024){
            int c = q / DD, d = q % DD;
            scr[q] = rv[cnt];
            out[((size_t)c*NPREDK + k)*DD + d] = rv[cnt];
            cnt++;
        }
        __syncthreads();
    }
}

// ---------------- host orchestration ----------------
static float* symF(const void* s){ void* p = nullptr; cudaGetSymbolAddress(&p, s); return (float*)p; }
static __half* symH(const void* s){ void* p = nullptr; cudaGetSymbolAddress(&p, s); return (__half*)p; }

extern "C" void kernel_launch(void* const* d_in, const int* in_sizes, int n_in,
                              void* d_out, int out_size){
    const float* X      = (const float*)d_in[0];
    const float* A      = (const float*)d_in[1];
    const float* gcn_w1 = (const float*)d_in[2];
    const float* gcn_b1 = (const float*)d_in[3];
    const float* gcn_w2 = (const float*)d_in[4];
    const float* gcn_b2 = (const float*)d_in[5];
    const float* enc_wq = (const float*)d_in[6];
    const float* enc_wk = (const float*)d_in[7];
    const float* enc_wv = (const float*)d_in[8];
    const float* enc_wm = (const float*)d_in[9];
    const float* enc_f1w= (const float*)d_in[10];
    const float* enc_f1b= (const float*)d_in[11];
    const float* enc_f2w= (const float*)d_in[12];
    const float* enc_f2b= (const float*)d_in[13];
    const float* ln1g   = (const float*)d_in[14];
    const float* ln1b   = (const float*)d_in[15];
    const float* ln2g   = (const float*)d_in[16];
    const float* ln2b   = (const float*)d_in[17];
    const float* lin1_w = (const float*)d_in[18];
    const float* lin1_b = (const float*)d_in[19];
    const float* lin2_w = (const float*)d_in[20];
    const float* lin2_b = (const float*)d_in[21];
    float* out = (float*)d_out;

    float*  p_u    = symF(g_u);
    float*  p_x    = symF(g_x);
    float*  p_y    = symF(g_y);
    __half* p_h1h  = symH(g_h1h);
    __half* p_th   = symH(g_th);
    __half* p_xh   = symH(g_xh);
    __half* p_qkv  = symH(g_qkvh);
    __half* p_att  = symH(g_atth);
    __half* p_wqkv = symH(g_wqkv);
    __half* p_wm   = symH(g_wm);
    __half* p_f1   = symH(g_f1);
    __half* p_f2   = symH(g_f2);
    __half* p_w1h  = symH(g_w1h);
    __half* p_w2h  = symH(g_w2h);

    cudaFuncSetAttribute(k_fattn, cudaFuncAttributeMaxDynamicSharedMemorySize, FA_SMEM);
    cudaFuncSetAttribute(k_head,  cudaFuncAttributeMaxDynamicSharedMemorySize, HEAD_SMEM);
    cudaFuncSetAttribute(k_ffn,   cudaFuncAttributeMaxDynamicSharedMemorySize, FFN_SMEM);

    // GCN weight packs first
    k_pack_w1<<<(DP*64 + 255)/256, 256>>>(gcn_w1);
    k_pack_w2<<<(64*104 + 255)/256, 256>>>(gcn_w2);

    // GCN: h1 = agg(X); t = relu(h1 W1 + b1); u = t W2 + b2; x = agg(u) (commute)
    k_agg<0><<<(TT*DD + 255)/256, 256>>>(A, X, nullptr, p_h1h, TT*DD);
    hgemm<4><<<dim3(1, CT/BM), 256>>>(
        p_h1h, p_w1h, nullptr, p_th, gcn_b1, nullptr, 0,
        CT, HIDG, DP, DP, 64, 64);
    hgemm<6><<<dim3(2, CT/BM), 256>>>(
        p_th, p_w2h, p_u, nullptr, gcn_b2, nullptr, 0,
        CT, DD, 64, 64, 104, DD);
    k_agg<1><<<(TT*DD + 255)/256, 256>>>(A, p_u, p_x, nullptr, TT*DD);

    // pack encoder weights; fold head affine
    k_pack_qkv<<<(NLAYER*DP*QKVP + 255)/256, 256>>>(enc_wq, enc_wk, enc_wv);
    k_pack_wm <<<(NLAYER*ATTP*DP + 255)/256, 256>>>(enc_wm);
    k_pack_f1 <<<(NLAYER*DP*FFND + 255)/256, 256>>>(enc_f1w);
    k_pack_f2 <<<(NLAYER*FFND*DP + 255)/256, 256>>>(enc_f2w);
    k_stepM<<<(DD*DD + DD + 255)/256, 256>>>(lin1_w, lin1_b, lin2_w, lin2_b);

    for (int l = 0; l < NLAYER; l++){
        // QKV
        k_qkv<<<dim3(QKVP/QBN, CT/QBM), 256>>>(p_xh, p_wqkv + (size_t)l*DP*QKVP, p_qkv);

        // fused attention
        k_fattn<<<dim3(TT/FA_BQ, NB), 256, FA_SMEM>>>(p_qkv, p_att);

        // proj: y = x + att @ wm
        hgemm<3><<<dim3(2, CT/BM), 256>>>(
            p_att, p_wm + (size_t)l*ATTP*DP, p_y, nullptr, nullptr, p_x, DD,
            CT, DD, ATTP, ATTP, DP, DD);

        // ln1: y <- LN(y) in place, xh = fp16(padded)
        k_lnh<<<CT/8, 256>>>(p_y, ln1g + l*DD, ln1b + l*DD, p_xh);

        // fused ffn1 + ffn2 + ln2 -> x, xh
        k_ffn<<<CT/128, 256, FFN_SMEM>>>(
            p_xh, p_y,
            p_f1 + (size_t)l*DP*FFND, p_f2 + (size_t)l*FFND*DP,
            enc_f1b + l*FFND, enc_f2b + l*DD,
            ln2g + l*DD, ln2b + l*DD,
            p_x, p_xh);
    }

    // head
    k_head<<<1, 1024, HEAD_SMEM>>>(p_x, out);
}